// round 10
// baseline (speedup 1.0000x reference)
#include <cuda_runtime.h>
#include <cuda_bf16.h>
#include <cuda_fp16.h>
#include <math.h>
#include <stdint.h>

// Problem constants
#define B_   64
#define T_   256
#define E_   300
#define H_   256
#define G4H  1024      // 4*H
#define INTER_ 128
#define NL   17
#define TL   19        // NUM_LABELS + 2
#define START_L 17
#define END_L   18
#define LOW_POT (-10000.0f)

// ---------------- scratch (device globals; no allocations allowed) ----------
__device__ float g_xproj[(size_t)2 * T_ * G4H * B_];   // [dir][t][n(1024)][b]
__device__ float g_h[(size_t)2 * T_ * H_ * B_];        // [dir][t][k][b]
__device__ float g_inter[(size_t)T_ * INTER_ * B_];    // [t][n(128)][b]
__device__ float g_unary[(size_t)B_ * T_ * TL];        // [b][t][l]
__device__ int   g_flags[4 * T_ * 16];                 // per-(grp,step,producer) flags

// W_hh in f16 mma-fragment order: [dir][hc(16)][q(4)][kt(16)][lane(32)][reg(4)]
__device__ uint32_t g_wfrag16_hi[2 * 16 * 4 * 16 * 32 * 4];
__device__ uint32_t g_wfrag16_lo[2 * 16 * 4 * 16 * 32 * 4];
// h in f16 mma B-fragment order: [grp(4)][par(2)][kt(16)][nt(4)][lane(32)][reg(2)]
// producer hc owns contiguous 256-u32 chunk (kt == hc)
__device__ uint32_t g_hfrag16_hi[4 * 2 * 16 * 4 * 32 * 2];
__device__ uint32_t g_hfrag16_lo[4 * 2 * 16 * 4 * 32 * 2];

// ---------------- helpers ----------------------------------------------------
__device__ __forceinline__ uint32_t f2tf32(float x) {
    uint32_t r;
    asm("cvt.rna.tf32.f32 %0, %1;" : "=r"(r) : "f"(x));
    return r;
}
__device__ __forceinline__ void split_tf32(float x, uint32_t& hi, uint32_t& lo) {
    hi = f2tf32(x);
    lo = f2tf32(x - __uint_as_float(hi));
}
__device__ __forceinline__ void mma_tf32(float* d, const uint32_t* a, uint32_t b0, uint32_t b1) {
    asm volatile(
        "mma.sync.aligned.m16n8k8.row.col.f32.tf32.tf32.f32 "
        "{%0,%1,%2,%3}, {%4,%5,%6,%7}, {%8,%9}, {%0,%1,%2,%3};"
        : "+f"(d[0]), "+f"(d[1]), "+f"(d[2]), "+f"(d[3])
        : "r"(a[0]), "r"(a[1]), "r"(a[2]), "r"(a[3]), "r"(b0), "r"(b1));
}
__device__ __forceinline__ void mma_f16(float* d, const uint32_t* a, uint32_t b0, uint32_t b1) {
    asm volatile(
        "mma.sync.aligned.m16n8k16.row.col.f32.f16.f16.f32 "
        "{%0,%1,%2,%3}, {%4,%5,%6,%7}, {%8,%9}, {%0,%1,%2,%3};"
        : "+f"(d[0]), "+f"(d[1]), "+f"(d[2]), "+f"(d[3])
        : "r"(a[0]), "r"(a[1]), "r"(a[2]), "r"(a[3]), "r"(b0), "r"(b1));
}
__device__ __forceinline__ void split_pack_f16(float x0, float x1, uint32_t& hi, uint32_t& lo) {
    __half h0 = __float2half_rn(x0);
    __half h1 = __float2half_rn(x1);
    __half l0 = __float2half_rn(x0 - __half2float(h0));
    __half l1 = __float2half_rn(x1 - __half2float(h1));
    hi = (uint32_t)__half_as_ushort(h0) | ((uint32_t)__half_as_ushort(h1) << 16);
    lo = (uint32_t)__half_as_ushort(l0) | ((uint32_t)__half_as_ushort(l1) << 16);
}
__device__ __forceinline__ void split_f16_u16(float x, uint16_t& hi, uint16_t& lo) {
    __half h = __float2half_rn(x);
    __half l = __float2half_rn(x - __half2float(h));
    hi = __half_as_ushort(h);
    lo = __half_as_ushort(l);
}

// fast activations (~1e-7 rel err, clamped)
__device__ __forceinline__ float sigf(float x) {
    x = fmaxf(fminf(x, 30.f), -30.f);
    return __fdividef(1.f, 1.f + __expf(-x));
}
__device__ __forceinline__ float tanhf_fast(float x) {
    x = fmaxf(fminf(x, 15.f), -15.f);
    float e = __expf(2.f * x);
    return __fdividef(e - 1.f, e + 1.f);
}

// ---------------- flag zeroing (graph-replay determinism) -------------------
__global__ void zero_bar_kernel() {
    int i = blockIdx.x * 256 + threadIdx.x;
    if (i < 4 * T_ * 16) g_flags[i] = 0;
}

// ---------------- W_hh f16 fragment prep ------------------------------------
__global__ void prep_whh_kernel(const float* __restrict__ Whf,
                                const float* __restrict__ Whb) {
    int idx = blockIdx.x * 256 + threadIdx.x;
    if (idx >= 2 * 16 * 4 * 16 * 32 * 4) return;
    int reg  = idx & 3;
    int lane = (idx >> 2) & 31;
    int kt   = (idx >> 7) & 15;
    int q    = (idx >> 11) & 3;
    int hc   = (idx >> 13) & 15;
    int dir  = (idx >> 17) & 1;
    const float* W = dir ? Whb : Whf;
    int i  = (lane >> 2) + 8 * (reg & 1);
    int g  = q * 256 + hc * 16 + i;
    int k0 = kt * 16 + (lane & 3) * 2 + 8 * (reg >> 1);
    float v0 = W[(size_t)g * H_ + k0];
    float v1 = W[(size_t)g * H_ + k0 + 1];
    uint32_t hi, lo;
    split_pack_f16(v0, v1, hi, lo);
    g_wfrag16_hi[idx] = hi;
    g_wfrag16_lo[idx] = lo;
}

// =============================================================================
// xproj GEMM (fp16x3, m16n8k16), 2 timesteps per block: tile 128(n) x 128(cols)
// cols: 0..63 -> (t0, b), 64..127 -> (t0+1, b). grid (8 ntiles, 128 tpairs, 2 dir).
// Warp grid 4(m-groups) x 2(n-groups aligned with timesteps).
// =============================================================================
#define XP_PAD 20
#define XP_A_SZ (128 * XP_PAD)            // 2560
#define XP_B_SZ (128 * XP_PAD)            // 2560
#define XP_AH(b) ((b) * XP_A_SZ)
#define XP_AL(b) (2 * XP_A_SZ + (b) * XP_A_SZ)
#define XP_BH(b) (4 * XP_A_SZ + (b) * XP_B_SZ)
#define XP_BL(b) (4 * XP_A_SZ + 2 * XP_B_SZ + (b) * XP_B_SZ)
#define XP_TOK   (4 * XP_A_SZ + 4 * XP_B_SZ)
#define XP_SMEM_BYTES ((4 * XP_A_SZ + 4 * XP_B_SZ + 128) * 4)   // 82432

__global__ void __launch_bounds__(256, 1)
xproj_kernel(const int* __restrict__ x,
             const float* __restrict__ emb,
             const float* __restrict__ Wf, const float* __restrict__ bf,
             const float* __restrict__ Wb, const float* __restrict__ bb) {
    extern __shared__ uint32_t sm[];
    const int tid  = threadIdx.x;
    const int n0   = blockIdx.x * 128;
    const int t0   = blockIdx.y * 2;
    const int dir  = blockIdx.z;
    const float* W    = dir ? Wb : Wf;
    const float* bias = dir ? bb : bf;

    int* tok = (int*)(sm + XP_TOK);
    if (tid < 128) tok[tid] = x[(tid & 63) * T_ + t0 + (tid >> 6)];
    __syncthreads();

    const int rowA = tid & 127;          // A row within tile
    const int kqA  = tid >> 7;           // 0..1 (16 k each)
    const int colB = tid & 127;          // B col (token column)
    const int kqB  = tid >> 7;           // 0..1 (16 k each)
    const float* Arow = W + (size_t)(n0 + rowA) * E_;
    const float* Brow = emb + (size_t)tok[colB] * E_;

    const int wid  = tid >> 5;
    const int lane = tid & 31;
    const int r    = lane >> 2;          // 0..7
    const int cidx = lane & 3;           // 0..3
    const int mg   = wid & 3;            // m-group: mtiles 2mg, 2mg+1
    const int ng   = wid >> 2;           // n-group: cols ng*64..+63 (timestep ng)

    float acc[2][8][4];
#pragma unroll
    for (int m = 0; m < 2; m++)
#pragma unroll
        for (int j = 0; j < 8; j++)
#pragma unroll
            for (int c = 0; c < 4; c++) acc[m][j][c] = 0.f;

    float4 av[4];
    float4 bv[4];

    // --- prologue: load + store chunk 0 into buffer 0
#pragma unroll
    for (int j = 0; j < 4; j++) {
        int gk4 = kqA * 4 + j;
        av[j] = (gk4 < 75) ? *(const float4*)(Arow + gk4 * 4) : make_float4(0, 0, 0, 0);
    }
#pragma unroll
    for (int j = 0; j < 4; j++) {
        int gk4 = kqB * 4 + j;
        bv[j] = (gk4 < 75) ? *(const float4*)(Brow + gk4 * 4) : make_float4(0, 0, 0, 0);
    }
#pragma unroll
    for (int j = 0; j < 4; j++) {
        int k2b = kqA * 8 + j * 2;
        uint32_t h0, l0, h1, l1;
        split_pack_f16(av[j].x, av[j].y, h0, l0);
        split_pack_f16(av[j].z, av[j].w, h1, l1);
        sm[XP_AH(0) + rowA * XP_PAD + k2b]     = h0;
        sm[XP_AH(0) + rowA * XP_PAD + k2b + 1] = h1;
        sm[XP_AL(0) + rowA * XP_PAD + k2b]     = l0;
        sm[XP_AL(0) + rowA * XP_PAD + k2b + 1] = l1;
    }
#pragma unroll
    for (int j = 0; j < 4; j++) {
        int k2b = kqB * 8 + j * 2;
        uint32_t h0, l0, h1, l1;
        split_pack_f16(bv[j].x, bv[j].y, h0, l0);
        split_pack_f16(bv[j].z, bv[j].w, h1, l1);
        sm[XP_BH(0) + colB * XP_PAD + k2b]     = h0;
        sm[XP_BH(0) + colB * XP_PAD + k2b + 1] = h1;
        sm[XP_BL(0) + colB * XP_PAD + k2b]     = l0;
        sm[XP_BL(0) + colB * XP_PAD + k2b + 1] = l1;
    }
    __syncthreads();

    for (int kc = 0; kc < 10; kc++) {
        const int buf = kc & 1;
        if (kc < 9) {
#pragma unroll
            for (int j = 0; j < 4; j++) {
                int gk4 = (kc + 1) * 8 + kqA * 4 + j;
                av[j] = (gk4 < 75) ? *(const float4*)(Arow + gk4 * 4) : make_float4(0, 0, 0, 0);
            }
#pragma unroll
            for (int j = 0; j < 4; j++) {
                int gk4 = (kc + 1) * 8 + kqB * 4 + j;
                bv[j] = (gk4 < 75) ? *(const float4*)(Brow + gk4 * 4) : make_float4(0, 0, 0, 0);
            }
        }
        const uint32_t* AHp = sm + XP_AH(buf);
        const uint32_t* ALp = sm + XP_AL(buf);
        const uint32_t* BHp = sm + XP_BH(buf);
        const uint32_t* BLp = sm + XP_BL(buf);
#pragma unroll
        for (int s2 = 0; s2 < 2; s2++) {
            const int k2b = s2 * 8 + cidx;
            uint32_t ah[2][4], al[2][4];
#pragma unroll
            for (int m = 0; m < 2; m++) {
                const int row0 = (2 * mg + m) * 16 + r;
                ah[m][0] = AHp[row0 * XP_PAD + k2b];
                ah[m][1] = AHp[(row0 + 8) * XP_PAD + k2b];
                ah[m][2] = AHp[row0 * XP_PAD + k2b + 4];
                ah[m][3] = AHp[(row0 + 8) * XP_PAD + k2b + 4];
                al[m][0] = ALp[row0 * XP_PAD + k2b];
                al[m][1] = ALp[(row0 + 8) * XP_PAD + k2b];
                al[m][2] = ALp[row0 * XP_PAD + k2b + 4];
                al[m][3] = ALp[(row0 + 8) * XP_PAD + k2b + 4];
            }
#pragma unroll
            for (int j = 0; j < 8; j++) {
                const int col = ng * 64 + j * 8 + r;
                uint32_t bh0 = BHp[col * XP_PAD + k2b];
                uint32_t bh1 = BHp[col * XP_PAD + k2b + 4];
                uint32_t bl0 = BLp[col * XP_PAD + k2b];
                uint32_t bl1 = BLp[col * XP_PAD + k2b + 4];
#pragma unroll
                for (int m = 0; m < 2; m++) {
                    mma_f16(acc[m][j], ah[m], bh0, bh1);
                    mma_f16(acc[m][j], al[m], bh0, bh1);
                    mma_f16(acc[m][j], ah[m], bl0, bl1);
                }
            }
        }
        if (kc < 9) {
            const int nb = (kc + 1) & 1;
#pragma unroll
            for (int j = 0; j < 4; j++) {
                int k2b = kqA * 8 + j * 2;
                uint32_t h0, l0, h1, l1;
                split_pack_f16(av[j].x, av[j].y, h0, l0);
                split_pack_f16(av[j].z, av[j].w, h1, l1);
                sm[XP_AH(nb) + rowA * XP_PAD + k2b]     = h0;
                sm[XP_AH(nb) + rowA * XP_PAD + k2b + 1] = h1;
                sm[XP_AL(nb) + rowA * XP_PAD + k2b]     = l0;
                sm[XP_AL(nb) + rowA * XP_PAD + k2b + 1] = l1;
            }
#pragma unroll
            for (int j = 0; j < 4; j++) {
                int k2b = kqB * 8 + j * 2;
                uint32_t h0, l0, h1, l1;
                split_pack_f16(bv[j].x, bv[j].y, h0, l0);
                split_pack_f16(bv[j].z, bv[j].w, h1, l1);
                sm[XP_BH(nb) + colB * XP_PAD + k2b]     = h0;
                sm[XP_BH(nb) + colB * XP_PAD + k2b + 1] = h1;
                sm[XP_BL(nb) + colB * XP_PAD + k2b]     = l0;
                sm[XP_BL(nb) + colB * XP_PAD + k2b + 1] = l1;
            }
        }
        __syncthreads();
    }

    // epilogue: +bias, write [dir][t0+ng][n][b]
    const int t = t0 + ng;
    float* outb = g_xproj + ((size_t)(dir * T_ + t)) * (G4H * B_);
#pragma unroll
    for (int m = 0; m < 2; m++) {
        const int gr0 = n0 + (2 * mg + m) * 16 + r;
        const int gr1 = gr0 + 8;
        const float bv0 = bias[gr0];
        const float bv1 = bias[gr1];
#pragma unroll
        for (int j = 0; j < 8; j++) {
            const int bcol = j * 8 + 2 * cidx;
            float2 o0 = make_float2(acc[m][j][0] + bv0, acc[m][j][1] + bv0);
            float2 o1 = make_float2(acc[m][j][2] + bv1, acc[m][j][3] + bv1);
            *(float2*)(outb + (size_t)gr0 * B_ + bcol) = o0;
            *(float2*)(outb + (size_t)gr1 * B_ + bcol) = o1;
        }
    }
}

// =============================================================================
// LSTM recurrence (3xFP16 mma), persistent blocks, per-warp producer-granular
// wait+copy (warp w polls producers 2w/2w+1 and copies their 1KB chunks).
// 64 blocks = dir(2) x bg(2, 32 batches) x hc(16, 16 hidden units).
// =============================================================================
#define L_AHI 0
#define L_ALO 8192
#define L_BHI 16384
#define L_BLO 20480
#define L_GEX 24576
#define L_SMEM_BYTES ((24576 + 4 * 16 * 33) * 4)   // 106752

__global__ void __launch_bounds__(256, 1) lstm_kernel() {
    extern __shared__ uint32_t s[];
    uint32_t* Ahi = s + L_AHI;
    uint32_t* Alo = s + L_ALO;
    uint32_t* Bhi = s + L_BHI;
    uint32_t* Blo = s + L_BLO;
    float*    gex = (float*)(s + L_GEX);

    const int tid = threadIdx.x;
    const int bx  = blockIdx.x;
    const int dir = bx >> 5;
    const int bg  = (bx >> 4) & 1;
    const int hc  = bx & 15;
    const int grp = dir * 2 + bg;

    // ---- load this block's f16 A fragments (weights) into smem
    {
        const uint4* srcH = (const uint4*)(g_wfrag16_hi + ((size_t)(dir * 16 + hc)) * 8192);
        const uint4* srcL = (const uint4*)(g_wfrag16_lo + ((size_t)(dir * 16 + hc)) * 8192);
        uint4* dH = (uint4*)Ahi;
        uint4* dL = (uint4*)Alo;
#pragma unroll
        for (int j = 0; j < 8; j++) {
            dH[tid + j * 256] = srcH[tid + j * 256];
            dL[tid + j * 256] = srcL[tid + j * 256];
        }
    }

    const int w    = tid >> 5;
    const int lane = tid & 31;
    const int q    = w & 3;
    const int nt0  = (w >> 2) * 2;

    const int ci = (2 * tid) >> 5;     // 0..15
    const int cb = (2 * tid) & 31;     // even
    float cst0 = 0.f, cst1 = 0.f;

    // h fragment store coords (producer side), k = hc*16+ci
    const int kin   = ci;
    const int s_reg = kin >> 3;
    const int s_tig = (kin >> 1) & 3;
    const int s_half = kin & 1;

    __syncthreads();

    for (int st = 0; st < T_; st++) {
        const int t = dir ? (T_ - 1 - st) : st;

        // prefetch xproj gate pre-activations
        float2 xpv[4];
        {
            const float* xb = g_xproj + ((size_t)(dir * T_ + t)) * (G4H * B_)
                              + (size_t)(hc * 16 + ci) * B_ + bg * 32 + cb;
#pragma unroll
            for (int qq = 0; qq < 4; qq++)
                xpv[qq] = *(const float2*)(xb + (size_t)qq * (H_ * B_));
        }

        float ga[4][2];
#pragma unroll
        for (int qq = 0; qq < 4; qq++) { ga[qq][0] = xpv[qq].x; ga[qq][1] = xpv[qq].y; }

        if (st > 0) {
            // per-warp: poll producers 2w, 2w+1 of step st-1, copy their chunks
            const int fbase = (grp * T_ + st - 1) << 4;
            const size_t hb = ((size_t)grp * 2 + ((st - 1) & 1)) * 4096;
#pragma unroll
            for (int e = 0; e < 2; e++) {
                const int p = w * 2 + e;
                const int* fp = g_flags + fbase + p;
                int v;
                for (;;) {
                    asm volatile("ld.acquire.gpu.global.b32 %0, [%1];"
                                 : "=r"(v) : "l"(fp) : "memory");
                    if (v) break;
                    __nanosleep(30);
                }
                const uint4* sH = (const uint4*)(g_hfrag16_hi + hb + p * 256);
                const uint4* sL = (const uint4*)(g_hfrag16_lo + hb + p * 256);
                uint4* dH = (uint4*)(Bhi + p * 256);
                uint4* dL = (uint4*)(Blo + p * 256);
#pragma unroll
                for (int j = 0; j < 2; j++) {
                    dH[lane + j * 32] = __ldcg(sH + lane + j * 32);
                    dL[lane + j * 32] = __ldcg(sL + lane + j * 32);
                }
            }
            __syncthreads();

            float acc[2][4];
#pragma unroll
            for (int e = 0; e < 2; e++)
#pragma unroll
                for (int j = 0; j < 4; j++) acc[e][j] = 0.f;

            const uint32_t* Aq_hi = Ahi + q * 2048;
            const uint32_t* Aq_lo = Alo + q * 2048;
#pragma unroll 8
            for (int kt = 0; kt < 16; kt++) {
                uint4 ahv = *(const uint4*)(Aq_hi + (kt * 32 + lane) * 4);
                uint4 alv = *(const uint4*)(Aq_lo + (kt * 32 + lane) * 4);
                const uint32_t* ah = (const uint32_t*)&ahv;
                const uint32_t* al = (const uint32_t*)&alv;
#pragma unroll
                for (int e = 0; e < 2; e++) {
                    const int nt = nt0 + e;
                    uint2 bh = *(const uint2*)(Bhi + ((kt * 4 + nt) * 32 + lane) * 2);
                    uint2 bl = *(const uint2*)(Blo + ((kt * 4 + nt) * 32 + lane) * 2);
                    mma_f16(acc[e], ah, bh.x, bh.y);
                    mma_f16(acc[e], al, bh.x, bh.y);
                    mma_f16(acc[e], ah, bl.x, bl.y);
                }
            }
            {
                const int i_lo = lane >> 2;
                const int colb = (lane & 3) * 2;
#pragma unroll
                for (int e = 0; e < 2; e++) {
                    const int col = (nt0 + e) * 8 + colb;
                    gex[(q * 16 + i_lo) * 33 + col]     = acc[e][0];
                    gex[(q * 16 + i_lo) * 33 + col + 1] = acc[e][1];
                    gex[(q * 16 + i_lo + 8) * 33 + col]     = acc[e][2];
                    gex[(q * 16 + i_lo + 8) * 33 + col + 1] = acc[e][3];
                }
            }
            __syncthreads();

#pragma unroll
            for (int qq = 0; qq < 4; qq++) {
                ga[qq][0] += gex[(qq * 16 + ci) * 33 + cb];
                ga[qq][1] += gex[(qq * 16 + ci) * 33 + cb + 1];
            }
        }

        float h0, h1;
        {
            float ig = sigf(ga[0][0]);
            float fg = sigf(ga[1][0]);
            float gg = tanhf_fast(ga[2][0]);
            float og = sigf(ga[3][0]);
            cst0 = fg * cst0 + ig * gg;
            h0 = og * tanhf_fast(cst0);
        }
        {
            float ig = sigf(ga[0][1]);
            float fg = sigf(ga[1][1]);
            float gg = tanhf_fast(ga[2][1]);
            float og = sigf(ga[3][1]);
            cst1 = fg * cst1 + ig * gg;
            h1 = og * tanhf_fast(cst1);
        }

        // write h (fp32 for fc1) and f16 hi/lo fragment halves (parity st&1)
        {
            const int k = hc * 16 + ci;
            *(float2*)(g_h + (((size_t)(dir * T_ + t)) * H_ + k) * B_ + bg * 32 + cb)
                = make_float2(h0, h1);

            const size_t hb = ((size_t)grp * 2 + (st & 1)) * 4096;
            uint16_t* HHi = (uint16_t*)g_hfrag16_hi;
            uint16_t* HLo = (uint16_t*)g_hfrag16_lo;
            uint16_t fhi, flo;
            // cell 0: n = cb
            {
                const int nt = cb >> 3;
                const int laneb = (cb & 7) * 4 + s_tig;
                const size_t word = hb + (((size_t)hc * 4 + nt) * 32 + laneb) * 2 + s_reg;
                split_f16_u16(h0, fhi, flo);
                HHi[word * 2 + s_half] = fhi;
                HLo[word * 2 + s_half] = flo;
            }
            // cell 1: n = cb+1
            {
                const int b1 = cb + 1;
                const int nt = b1 >> 3;
                const int laneb = (b1 & 7) * 4 + s_tig;
                const size_t word = hb + (((size_t)hc * 4 + nt) * 32 + laneb) * 2 + s_reg;
                split_f16_u16(h1, fhi, flo);
                HHi[word * 2 + s_half] = fhi;
                HLo[word * 2 + s_half] = flo;
            }
        }
        __syncthreads();
        if (tid == 0) {
            __threadfence();
            int* fp = g_flags + ((grp * T_ + st) << 4) + hc;
            asm volatile("st.release.gpu.global.b32 [%0], %1;" :: "l"(fp), "r"(1) : "memory");
        }
    }
}

// =============================================================================
// fc1 (3xTF32) — proven; unchanged
// =============================================================================
#define XA_PAD 136
#define XB_PAD 72
#define XA_SZ  (32 * XA_PAD)
#define XB_SZ  (32 * XB_PAD)
#define X_AH(buf) ((buf) * XA_SZ)
#define X_AL(buf) (2 * XA_SZ + (buf) * XA_SZ)
#define X_BH(buf) (4 * XA_SZ + (buf) * XB_SZ)
#define X_BL(buf) (4 * XA_SZ + 2 * XB_SZ + (buf) * XB_SZ)
#define X_SMEM_BYTES ((4 * XA_SZ + 4 * XB_SZ + 64) * 4)

__global__ void __launch_bounds__(256, 2)
fc1_kernel(const float* __restrict__ W, const float* __restrict__ bias) {
    extern __shared__ uint32_t sm[];
    const int tid = threadIdx.x;
    const int t   = blockIdx.x;

    const int rowA = tid & 127;
    const int kqA  = tid >> 7;
    const float* Arow = W + (size_t)rowA * 512;

    const int wid  = tid >> 5;
    const int lane = tid & 31;
    const int r    = lane >> 2;
    const int cidx = lane & 3;

    float acc[8][4];
#pragma unroll
    for (int i = 0; i < 8; i++)
#pragma unroll
        for (int j = 0; j < 4; j++) acc[i][j] = 0.f;

    float4 av[4];
    float4 bv[2];

#pragma unroll
    for (int j = 0; j < 4; j++) {
        int gk4 = kqA + 2 * j;
        av[j] = *(const float4*)(Arow + gk4 * 4);
    }
#pragma unroll
    for (int j = 0; j < 2; j++) {
        int f4id = tid + j * 256;
        int kl = f4id >> 4, b4 = f4id & 15;
        int kgl = kl;
        int d = kgl >> 8, kh = kgl & 255;
        bv[j] = *(const float4*)(g_h + ((size_t)(d * T_ + t) * 256 + kh) * 64 + b4 * 4);
    }
#pragma unroll
    for (int j = 0; j < 4; j++) {
        int kl = (kqA + 2 * j) * 4;
        const float* v = (const float*)&av[j];
#pragma unroll
        for (int c = 0; c < 4; c++) {
            uint32_t hi, lo; split_tf32(v[c], hi, lo);
            sm[X_AH(0) + (kl + c) * XA_PAD + rowA] = hi;
            sm[X_AL(0) + (kl + c) * XA_PAD + rowA] = lo;
        }
    }
#pragma unroll
    for (int j = 0; j < 2; j++) {
        int f4id = tid + j * 256;
        int kl = f4id >> 4, b4 = f4id & 15;
        const float* v = (const float*)&bv[j];
#pragma unroll
        for (int c = 0; c < 4; c++) {
            uint32_t hi, lo; split_tf32(v[c], hi, lo);
            sm[X_BH(0) + kl * XB_PAD + b4 * 4 + c] = hi;
            sm[X_BL(0) + kl * XB_PAD + b4 * 4 + c] = lo;
        }
    }
    __syncthreads();

    for (int kc = 0; kc < 16; kc++) {
        const int buf = kc & 1;
        if (kc < 15) {
#pragma unroll
            for (int j = 0; j < 4; j++) {
                int gk4 = (kc + 1) * 8 + kqA + 2 * j;
                av[j] = *(const float4*)(Arow + gk4 * 4);
            }
#pragma unroll
            for (int j = 0; j < 2; j++) {
                int f4id = tid + j * 256;
                int kl = f4id >> 4, b4 = f4id & 15;
                int kgl = (kc + 1) * 32 + kl;
                int d = kgl >> 8, kh = kgl & 255;
                bv[j] = *(const float4*)(g_h + ((size_t)(d * T_ + t) * 256 + kh) * 64 + b4 * 4);
            }
        }
        const uint32_t* AH = sm + X_AH(buf);
        const uint32_t* AL = sm + X_AL(buf);
        const uint32_t* BH = sm + X_BH(buf);
        const uint32_t* BL = sm + X_BL(buf);
        const int row0 = wid * 16 + r;
#pragma unroll
        for (int kk = 0; kk < 4; kk++) {
            const int base = kk * 8 + cidx;
            uint32_t ah[4], al[4];
            ah[0] = AH[base * XA_PAD + row0];
            ah[1] = AH[base * XA_PAD + row0 + 8];
            ah[2] = AH[(base + 4) * XA_PAD + row0];
            ah[3] = AH[(base + 4) * XA_PAD + row0 + 8];
            al[0] = AL[base * XA_PAD + row0];
            al[1] = AL[base * XA_PAD + row0 + 8];
            al[2] = AL[(base + 4) * XA_PAD + row0];
            al[3] = AL[(base + 4) * XA_PAD + row0 + 8];
#pragma unroll
            for (int nt = 0; nt < 8; nt++) {
                const int col = nt * 8 + r;
                uint32_t bh0 = BH[base * XB_PAD + col];
                uint32_t bh1 = BH[(base + 4) * XB_PAD + col];
                uint32_t bl0 = BL[base * XB_PAD + col];
                uint32_t bl1 = BL[(base + 4) * XB_PAD + col];
                mma_tf32(acc[nt], ah, bh0, bh1);
                mma_tf32(acc[nt], al, bh0, bh1);
                mma_tf32(acc[nt], ah, bl0, bl1);
            }
        }
        if (kc < 15) {
            const int nb = (kc + 1) & 1;
#pragma unroll
            for (int j = 0; j < 4; j++) {
                int kl = (kqA + 2 * j) * 4;
                const float* v = (const float*)&av[j];
#pragma unroll
                for (int c = 0; c < 4; c++) {
                    uint32_t hi, lo; split_tf32(v[c], hi, lo);
                    sm[X_AH(nb) + (kl + c) * XA_PAD + rowA] = hi;
                    sm[X_AL(nb) + (kl + c) * XA_PAD + rowA] = lo;
                }
            }
#pragma unroll
            for (int j = 0; j < 2; j++) {
                int f4id = tid + j * 256;
                int kl = f4id >> 4, b4 = f4id & 15;
                const float* v = (const float*)&bv[j];
#pragma unroll
                for (int c = 0; c < 4; c++) {
                    uint32_t hi, lo; split_tf32(v[c], hi, lo);
                    sm[X_BH(nb) + kl * XB_PAD + b4 * 4 + c] = hi;
                    sm[X_BL(nb) + kl * XB_PAD + b4 * 4 + c] = lo;
                }
            }
        }
        __syncthreads();
    }

    const int gr0 = wid * 16 + r;
    const int gr1 = gr0 + 8;
    const float bv0 = bias[gr0];
    const float bv1 = bias[gr1];
    float* outb = g_inter + (size_t)t * INTER_ * B_;
#pragma unroll
    for (int nt = 0; nt < 8; nt++) {
        const int col = nt * 8 + 2 * cidx;
        float2 o0 = make_float2(fmaxf(acc[nt][0] + bv0, 0.f), fmaxf(acc[nt][1] + bv0, 0.f));
        float2 o1 = make_float2(fmaxf(acc[nt][2] + bv1, 0.f), fmaxf(acc[nt][3] + bv1, 0.f));
        *(float2*)(outb + (size_t)gr0 * B_ + col) = o0;
        *(float2*)(outb + (size_t)gr1 * B_ + col) = o1;
    }
}

// ---------------- cls: unary[b][t][l] = cls_W[l,:]·inter[t][:,b] + cls_b[l] --
__global__ void cls_kernel(const float* __restrict__ clsW, const float* __restrict__ clsb) {
    __shared__ float sI[INTER_ * B_];
    __shared__ float sW[NL * INTER_];
    const int t = blockIdx.x;
    const int tid = threadIdx.x;
    const float4* src = (const float4*)(g_inter + (size_t)t * INTER_ * B_);
    float4* dst = (float4*)sI;
#pragma unroll
    for (int i = 0; i < 8; i++) dst[tid + i * 256] = src[tid + i * 256];
    for (int i = tid; i < NL * INTER_; i += 256) sW[i] = clsW[i];
    __syncthreads();

    const int b  = tid & 63;
    const int lg = tid >> 6;
    for (int l = lg; l < NL; l += 4) {
        float acc = clsb[l];
        const float* wr = sW + l * INTER_;
#pragma unroll 8
        for (int n = 0; n < INTER_; n++) acc += wr[n] * sI[n * B_ + b];
        g_unary[((size_t)b * T_ + t) * TL + l] = acc;
    }
    if (tid < 128) {
        int bb = tid & 63;
        int l  = NL + (tid >> 6);
        g_unary[((size_t)bb * T_ + t) * TL + l] = LOW_POT;
    }
}

// ---------------- Viterbi + backtrace (one block per batch element) ---------
__global__ void viterbi_kernel(const float* __restrict__ trans, float* __restrict__ out,
                               int score_off, int label_off) {
    __shared__ float tr[TL * TL];
    __shared__ float s0[TL], s1[TL];
    __shared__ unsigned char bp[T_][TL];
    const int b = blockIdx.x;
    const int tid = threadIdx.x;

    for (int i = tid; i < TL * TL; i += 32) tr[i] = trans[i];
    if (tid < TL) s0[tid] = (tid == START_L) ? 0.f : LOW_POT;
    __syncthreads();

    const float* ub = g_unary + (size_t)b * T_ * TL;
    float* sc = s0;
    float* sn = s1;
    for (int t = 0; t < T_; t++) {
        if (tid < TL) {
            float best = sc[0] + tr[tid * TL + 0];
            int bpi = 0;
#pragma unroll
            for (int p = 1; p < TL; p++) {
                float v = sc[p] + tr[tid * TL + p];
                if (v > best) { best = v; bpi = p; }
            }
            sn[tid] = best + ub[t * TL + tid];
            bp[t][tid] = (unsigned char)bpi;
        }
        __syncthreads();
        float* tmp = sc; sc = sn; sn = tmp;
    }
    if (tid == 0) {
        float best = sc[0] + tr[END_L * TL + 0];
        int li = 0;
        for (int l = 1; l < TL; l++) {
            float v = sc[l] + tr[END_L * TL + l];
            if (v > best) { best = v; li = l; }
        }
        if (score_off >= 0) out[score_off + b] = best;
        if (label_off >= 0) {
            int cur = li;
            for (int t = T_ - 1; t >= 0; t--) {
                out[label_off + (size_t)b * T_ + t] = (float)cur;
                cur = bp[t][cur];
            }
        }
    }
}

// ---------------- launch -----------------------------------------------------
extern "C" void kernel_launch(void* const* d_in, const int* in_sizes, int n_in,
                              void* d_out, int out_size) {
    const int*   x       = (const int*)d_in[0];
    const float* emb     = (const float*)d_in[1];
    const float* W_ih_f  = (const float*)d_in[2];
    const float* W_hh_f  = (const float*)d_in[3];
    const float* b_f     = (const float*)d_in[4];
    const float* W_ih_b  = (const float*)d_in[5];
    const float* W_hh_b  = (const float*)d_in[6];
    const float* b_b     = (const float*)d_in[7];
    const float* fc1_W   = (const float*)d_in[8];
    const float* fc1_b   = (const float*)d_in[9];
    const float* cls_W   = (const float*)d_in[10];
    const float* cls_b   = (const float*)d_in[11];
    const float* trans   = (const float*)d_in[12];
    float* out = (float*)d_out;

    int score_off = 0, label_off = B_;
    if (out_size == B_ * T_)      { score_off = -1; label_off = 0; }
    else if (out_size == B_)      { label_off = -1; }

    cudaFuncSetAttribute(lstm_kernel, cudaFuncAttributeMaxDynamicSharedMemorySize, L_SMEM_BYTES);
    cudaFuncSetAttribute(xproj_kernel, cudaFuncAttributeMaxDynamicSharedMemorySize, XP_SMEM_BYTES);
    cudaFuncSetAttribute(fc1_kernel, cudaFuncAttributeMaxDynamicSharedMemorySize, X_SMEM_BYTES);

    zero_bar_kernel<<<64, 256>>>();
    prep_whh_kernel<<<1024, 256>>>(W_hh_f, W_hh_b);
    xproj_kernel<<<dim3(8, 128, 2), 256, XP_SMEM_BYTES>>>(x, emb, W_ih_f, b_f, W_ih_b, b_b);
    lstm_kernel<<<64, 256, L_SMEM_BYTES>>>();
    fc1_kernel<<<T_, 256, X_SMEM_BYTES>>>(fc1_W, fc1_b);
    cls_kernel<<<T_, 256>>>(cls_W, cls_b);
    viterbi_kernel<<<B_, 32>>>(trans, out, score_off, label_off);
}

// round 11
// speedup vs baseline: 1.0926x; 1.0926x over previous
#include <cuda_runtime.h>
#include <cuda_bf16.h>
#include <cuda_fp16.h>
#include <math.h>
#include <stdint.h>

// Problem constants
#define B_   64
#define T_   256
#define E_   300
#define H_   256
#define G4H  1024      // 4*H
#define INTER_ 128
#define NL   17
#define TL   19        // NUM_LABELS + 2
#define START_L 17
#define END_L   18
#define LOW_POT (-10000.0f)

// ---------------- scratch (device globals; no allocations allowed) ----------
__device__ float g_xproj[(size_t)2 * T_ * G4H * B_];   // [dir][t][n(1024)][b]
__device__ float g_h[(size_t)2 * T_ * H_ * B_];        // [dir][t][k][b]
__device__ float g_unary[(size_t)B_ * T_ * TL];        // [b][t][l]
__device__ int   g_flags[4 * T_ * 16];                 // per-(grp,step,producer) flags

// W_hh in f16 mma-fragment order: [dir][hc(16)][q(4)][kt(16)][lane(32)][reg(4)]
__device__ uint32_t g_wfrag16_hi[2 * 16 * 4 * 16 * 32 * 4];
__device__ uint32_t g_wfrag16_lo[2 * 16 * 4 * 16 * 32 * 4];
// h in f16 mma B-fragment order: [grp(4)][par(2)][kt(16)][nt(4)][lane(32)][reg(2)]
// producer hc owns contiguous 256-u32 chunk (kt == hc)
__device__ uint32_t g_hfrag16_hi[4 * 2 * 16 * 4 * 32 * 2];
__device__ uint32_t g_hfrag16_lo[4 * 2 * 16 * 4 * 32 * 2];

// ---------------- helpers ----------------------------------------------------
__device__ __forceinline__ uint32_t f2tf32(float x) {
    uint32_t r;
    asm("cvt.rna.tf32.f32 %0, %1;" : "=r"(r) : "f"(x));
    return r;
}
__device__ __forceinline__ void split_tf32(float x, uint32_t& hi, uint32_t& lo) {
    hi = f2tf32(x);
    lo = f2tf32(x - __uint_as_float(hi));
}
__device__ __forceinline__ void mma_tf32(float* d, const uint32_t* a, uint32_t b0, uint32_t b1) {
    asm volatile(
        "mma.sync.aligned.m16n8k8.row.col.f32.tf32.tf32.f32 "
        "{%0,%1,%2,%3}, {%4,%5,%6,%7}, {%8,%9}, {%0,%1,%2,%3};"
        : "+f"(d[0]), "+f"(d[1]), "+f"(d[2]), "+f"(d[3])
        : "r"(a[0]), "r"(a[1]), "r"(a[2]), "r"(a[3]), "r"(b0), "r"(b1));
}
__device__ __forceinline__ void mma_f16(float* d, const uint32_t* a, uint32_t b0, uint32_t b1) {
    asm volatile(
        "mma.sync.aligned.m16n8k16.row.col.f32.f16.f16.f32 "
        "{%0,%1,%2,%3}, {%4,%5,%6,%7}, {%8,%9}, {%0,%1,%2,%3};"
        : "+f"(d[0]), "+f"(d[1]), "+f"(d[2]), "+f"(d[3])
        : "r"(a[0]), "r"(a[1]), "r"(a[2]), "r"(a[3]), "r"(b0), "r"(b1));
}
__device__ __forceinline__ void split_pack_f16(float x0, float x1, uint32_t& hi, uint32_t& lo) {
    __half h0 = __float2half_rn(x0);
    __half h1 = __float2half_rn(x1);
    __half l0 = __float2half_rn(x0 - __half2float(h0));
    __half l1 = __float2half_rn(x1 - __half2float(h1));
    hi = (uint32_t)__half_as_ushort(h0) | ((uint32_t)__half_as_ushort(h1) << 16);
    lo = (uint32_t)__half_as_ushort(l0) | ((uint32_t)__half_as_ushort(l1) << 16);
}
__device__ __forceinline__ void split_f16_u16(float x, uint16_t& hi, uint16_t& lo) {
    __half h = __float2half_rn(x);
    __half l = __float2half_rn(x - __half2float(h));
    hi = __half_as_ushort(h);
    lo = __half_as_ushort(l);
}

// fast activations (~1e-7 rel err, clamped)
__device__ __forceinline__ float sigf(float x) {
    x = fmaxf(fminf(x, 30.f), -30.f);
    return __fdividef(1.f, 1.f + __expf(-x));
}
__device__ __forceinline__ float tanhf_fast(float x) {
    x = fmaxf(fminf(x, 15.f), -15.f);
    float e = __expf(2.f * x);
    return __fdividef(e - 1.f, e + 1.f);
}

// ---------------- flag zeroing (graph-replay determinism) -------------------
__global__ void zero_bar_kernel() {
    int i = blockIdx.x * 256 + threadIdx.x;
    if (i < 4 * T_ * 16) g_flags[i] = 0;
}

// ---------------- W_hh f16 fragment prep ------------------------------------
__global__ void prep_whh_kernel(const float* __restrict__ Whf,
                                const float* __restrict__ Whb) {
    int idx = blockIdx.x * 256 + threadIdx.x;
    if (idx >= 2 * 16 * 4 * 16 * 32 * 4) return;
    int reg  = idx & 3;
    int lane = (idx >> 2) & 31;
    int kt   = (idx >> 7) & 15;
    int q    = (idx >> 11) & 3;
    int hc   = (idx >> 13) & 15;
    int dir  = (idx >> 17) & 1;
    const float* W = dir ? Whb : Whf;
    int i  = (lane >> 2) + 8 * (reg & 1);
    int g  = q * 256 + hc * 16 + i;
    int k0 = kt * 16 + (lane & 3) * 2 + 8 * (reg >> 1);
    float v0 = W[(size_t)g * H_ + k0];
    float v1 = W[(size_t)g * H_ + k0 + 1];
    uint32_t hi, lo;
    split_pack_f16(v0, v1, hi, lo);
    g_wfrag16_hi[idx] = hi;
    g_wfrag16_lo[idx] = lo;
}

// =============================================================================
// xproj GEMM (fp16x3, m16n8k16) — r9 proven, standalone (occupancy 2)
// =============================================================================
#define XP_PAD 20
#define XP_A_SZ (128 * XP_PAD)
#define XP_B_SZ (64 * XP_PAD)
#define XP_AH(b) ((b) * XP_A_SZ)
#define XP_AL(b) (2 * XP_A_SZ + (b) * XP_A_SZ)
#define XP_BH(b) (4 * XP_A_SZ + (b) * XP_B_SZ)
#define XP_BL(b) (4 * XP_A_SZ + 2 * XP_B_SZ + (b) * XP_B_SZ)
#define XP_TOK   (4 * XP_A_SZ + 4 * XP_B_SZ)
#define XP_SMEM_BYTES ((4 * XP_A_SZ + 4 * XP_B_SZ + 64) * 4)   // 61696

__global__ void __launch_bounds__(256, 2)
xproj_kernel(const int* __restrict__ x,
             const float* __restrict__ emb,
             const float* __restrict__ Wf, const float* __restrict__ bf,
             const float* __restrict__ Wb, const float* __restrict__ bb) {
    extern __shared__ uint32_t sm[];
    const int tid  = threadIdx.x;
    const int n0   = blockIdx.x * 128;
    const int t    = blockIdx.y;
    const int dir  = blockIdx.z;
    const float* W    = dir ? Wb : Wf;
    const float* bias = dir ? bb : bf;

    int* tok = (int*)(sm + XP_TOK);
    if (tid < 64) tok[tid] = x[tid * T_ + t];
    __syncthreads();

    const int rowA = tid & 127;
    const int kqA  = tid >> 7;
    const int rowB = tid & 63;
    const int kqB  = tid >> 6;
    const float* Arow = W + (size_t)(n0 + rowA) * E_;
    const float* Brow = emb + (size_t)tok[rowB] * E_;

    const int wid  = tid >> 5;
    const int lane = tid & 31;
    const int r    = lane >> 2;
    const int cidx = lane & 3;
    const int row0 = wid * 16 + r;

    float acc[8][4];
#pragma unroll
    for (int i = 0; i < 8; i++)
#pragma unroll
        for (int j = 0; j < 4; j++) acc[i][j] = 0.f;

    float4 av[4];
    float4 bv[2];

#pragma unroll
    for (int j = 0; j < 4; j++) {
        int gk4 = kqA * 4 + j;
        av[j] = (gk4 < 75) ? *(const float4*)(Arow + gk4 * 4) : make_float4(0, 0, 0, 0);
    }
#pragma unroll
    for (int j = 0; j < 2; j++) {
        int gk4 = kqB * 2 + j;
        bv[j] = (gk4 < 75) ? *(const float4*)(Brow + gk4 * 4) : make_float4(0, 0, 0, 0);
    }
#pragma unroll
    for (int j = 0; j < 4; j++) {
        int k2b = kqA * 8 + j * 2;
        uint32_t h0, l0, h1, l1;
        split_pack_f16(av[j].x, av[j].y, h0, l0);
        split_pack_f16(av[j].z, av[j].w, h1, l1);
        sm[XP_AH(0) + rowA * XP_PAD + k2b]     = h0;
        sm[XP_AH(0) + rowA * XP_PAD + k2b + 1] = h1;
        sm[XP_AL(0) + rowA * XP_PAD + k2b]     = l0;
        sm[XP_AL(0) + rowA * XP_PAD + k2b + 1] = l1;
    }
#pragma unroll
    for (int j = 0; j < 2; j++) {
        int k2b = kqB * 4 + j * 2;
        uint32_t h0, l0, h1, l1;
        split_pack_f16(bv[j].x, bv[j].y, h0, l0);
        split_pack_f16(bv[j].z, bv[j].w, h1, l1);
        sm[XP_BH(0) + rowB * XP_PAD + k2b]     = h0;
        sm[XP_BH(0) + rowB * XP_PAD + k2b + 1] = h1;
        sm[XP_BL(0) + rowB * XP_PAD + k2b]     = l0;
        sm[XP_BL(0) + rowB * XP_PAD + k2b + 1] = l1;
    }
    __syncthreads();

    for (int kc = 0; kc < 10; kc++) {
        const int buf = kc & 1;
        if (kc < 9) {
#pragma unroll
            for (int j = 0; j < 4; j++) {
                int gk4 = (kc + 1) * 8 + kqA * 4 + j;
                av[j] = (gk4 < 75) ? *(const float4*)(Arow + gk4 * 4) : make_float4(0, 0, 0, 0);
            }
#pragma unroll
            for (int j = 0; j < 2; j++) {
                int gk4 = (kc + 1) * 8 + kqB * 2 + j;
                bv[j] = (gk4 < 75) ? *(const float4*)(Brow + gk4 * 4) : make_float4(0, 0, 0, 0);
            }
        }
        const uint32_t* AHp = sm + XP_AH(buf);
        const uint32_t* ALp = sm + XP_AL(buf);
        const uint32_t* BHp = sm + XP_BH(buf);
        const uint32_t* BLp = sm + XP_BL(buf);
#pragma unroll
        for (int s2 = 0; s2 < 2; s2++) {
            const int k2b = s2 * 8 + cidx;
            uint32_t ah[4], al[4];
            ah[0] = AHp[row0 * XP_PAD + k2b];
            ah[1] = AHp[(row0 + 8) * XP_PAD + k2b];
            ah[2] = AHp[row0 * XP_PAD + k2b + 4];
            ah[3] = AHp[(row0 + 8) * XP_PAD + k2b + 4];
            al[0] = ALp[row0 * XP_PAD + k2b];
            al[1] = ALp[(row0 + 8) * XP_PAD + k2b];
            al[2] = ALp[row0 * XP_PAD + k2b + 4];
            al[3] = ALp[(row0 + 8) * XP_PAD + k2b + 4];
#pragma unroll
            for (int nt = 0; nt < 8; nt++) {
                const int col = nt * 8 + r;
                uint32_t bh0 = BHp[col * XP_PAD + k2b];
                uint32_t bh1 = BHp[col * XP_PAD + k2b + 4];
                uint32_t bl0 = BLp[col * XP_PAD + k2b];
                uint32_t bl1 = BLp[col * XP_PAD + k2b + 4];
                mma_f16(acc[nt], ah, bh0, bh1);
                mma_f16(acc[nt], al, bh0, bh1);
                mma_f16(acc[nt], ah, bl0, bl1);
            }
        }
        if (kc < 9) {
            const int nb = (kc + 1) & 1;
#pragma unroll
            for (int j = 0; j < 4; j++) {
                int k2b = kqA * 8 + j * 2;
                uint32_t h0, l0, h1, l1;
                split_pack_f16(av[j].x, av[j].y, h0, l0);
                split_pack_f16(av[j].z, av[j].w, h1, l1);
                sm[XP_AH(nb) + rowA * XP_PAD + k2b]     = h0;
                sm[XP_AH(nb) + rowA * XP_PAD + k2b + 1] = h1;
                sm[XP_AL(nb) + rowA * XP_PAD + k2b]     = l0;
                sm[XP_AL(nb) + rowA * XP_PAD + k2b + 1] = l1;
            }
#pragma unroll
            for (int j = 0; j < 2; j++) {
                int k2b = kqB * 4 + j * 2;
                uint32_t h0, l0, h1, l1;
                split_pack_f16(bv[j].x, bv[j].y, h0, l0);
                split_pack_f16(bv[j].z, bv[j].w, h1, l1);
                sm[XP_BH(nb) + rowB * XP_PAD + k2b]     = h0;
                sm[XP_BH(nb) + rowB * XP_PAD + k2b + 1] = h1;
                sm[XP_BL(nb) + rowB * XP_PAD + k2b]     = l0;
                sm[XP_BL(nb) + rowB * XP_PAD + k2b + 1] = l1;
            }
        }
        __syncthreads();
    }

    const int gr0 = n0 + wid * 16 + r;
    const int gr1 = gr0 + 8;
    const float bv0 = bias[gr0];
    const float bv1 = bias[gr1];
    float* outb = g_xproj + ((size_t)(dir * T_ + t)) * (G4H * B_);
#pragma unroll
    for (int nt = 0; nt < 8; nt++) {
        const int col = nt * 8 + 2 * cidx;
        float2 o0 = make_float2(acc[nt][0] + bv0, acc[nt][1] + bv0);
        float2 o1 = make_float2(acc[nt][2] + bv1, acc[nt][3] + bv1);
        *(float2*)(outb + (size_t)gr0 * B_ + col) = o0;
        *(float2*)(outb + (size_t)gr1 * B_ + col) = o1;
    }
}

// =============================================================================
// LSTM recurrence (3xFP16 mma), persistent blocks. r9 structure with
// split-phase wait+copy: flags 0-7 -> copy chunks 0-7 -> flags 8-15 -> copy 8-15.
// 64 blocks = dir(2) x bg(2, 32 batches) x hc(16, 16 hidden units).
// =============================================================================
#define L_AHI 0
#define L_ALO 8192
#define L_BHI 16384
#define L_BLO 20480
#define L_GEX 24576
#define L_SMEM_BYTES ((24576 + 4 * 16 * 33) * 4)   // 106752

__global__ void __launch_bounds__(256, 1) lstm_kernel() {
    extern __shared__ uint32_t s[];
    uint32_t* Ahi = s + L_AHI;
    uint32_t* Alo = s + L_ALO;
    uint32_t* Bhi = s + L_BHI;
    uint32_t* Blo = s + L_BLO;
    float*    gex = (float*)(s + L_GEX);

    const int tid = threadIdx.x;
    const int bx  = blockIdx.x;
    const int dir = bx >> 5;
    const int bg  = (bx >> 4) & 1;
    const int hc  = bx & 15;
    const int grp = dir * 2 + bg;

    // ---- load this block's f16 A fragments (weights) into smem
    {
        const uint4* srcH = (const uint4*)(g_wfrag16_hi + ((size_t)(dir * 16 + hc)) * 8192);
        const uint4* srcL = (const uint4*)(g_wfrag16_lo + ((size_t)(dir * 16 + hc)) * 8192);
        uint4* dH = (uint4*)Ahi;
        uint4* dL = (uint4*)Alo;
#pragma unroll
        for (int j = 0; j < 8; j++) {
            dH[tid + j * 256] = srcH[tid + j * 256];
            dL[tid + j * 256] = srcL[tid + j * 256];
        }
    }

    const int w    = tid >> 5;
    const int lane = tid & 31;
    const int q    = w & 3;
    const int nt0  = (w >> 2) * 2;

    const int ci = (2 * tid) >> 5;     // 0..15
    const int cb = (2 * tid) & 31;     // even
    float cst0 = 0.f, cst1 = 0.f;

    // h fragment store coords (producer side), k = hc*16+ci
    const int kin   = ci;
    const int s_reg = kin >> 3;
    const int s_tig = (kin >> 1) & 3;
    const int s_half = kin & 1;

    __syncthreads();

    for (int st = 0; st < T_; st++) {
        const int t = dir ? (T_ - 1 - st) : st;

        // prefetch xproj gate pre-activations
        float2 xpv[4];
        {
            const float* xb = g_xproj + ((size_t)(dir * T_ + t)) * (G4H * B_)
                              + (size_t)(hc * 16 + ci) * B_ + bg * 32 + cb;
#pragma unroll
            for (int qq = 0; qq < 4; qq++)
                xpv[qq] = *(const float2*)(xb + (size_t)qq * (H_ * B_));
        }

        float ga[4][2];
#pragma unroll
        for (int qq = 0; qq < 4; qq++) { ga[qq][0] = xpv[qq].x; ga[qq][1] = xpv[qq].y; }

        if (st > 0) {
            const int fbase = (grp * T_ + st - 1) << 4;
            const size_t hb = ((size_t)grp * 2 + ((st - 1) & 1)) * 4096;
            const uint4* sH = (const uint4*)(g_hfrag16_hi + hb);
            const uint4* sL = (const uint4*)(g_hfrag16_lo + hb);
            uint4* dH = (uint4*)Bhi;
            uint4* dL = (uint4*)Blo;

            // ---- half 1: producers 0..7
            if (tid < 8) {
                const int* fp = g_flags + fbase + tid;
                int v;
                for (;;) {
                    asm volatile("ld.acquire.gpu.global.b32 %0, [%1];"
                                 : "=r"(v) : "l"(fp) : "memory");
                    if (__all_sync(0x000000FFu, v != 0)) break;
                    __nanosleep(30);
                }
            }
            __syncthreads();
#pragma unroll
            for (int j = 0; j < 2; j++) {
                dH[tid + j * 256] = __ldcg(sH + tid + j * 256);
                dL[tid + j * 256] = __ldcg(sL + tid + j * 256);
            }
            // ---- half 2: producers 8..15 (first-half copy overlaps this wait)
            if (tid < 8) {
                const int* fp = g_flags + fbase + 8 + tid;
                int v;
                for (;;) {
                    asm volatile("ld.acquire.gpu.global.b32 %0, [%1];"
                                 : "=r"(v) : "l"(fp) : "memory");
                    if (__all_sync(0x000000FFu, v != 0)) break;
                    __nanosleep(30);
                }
            }
            __syncthreads();
#pragma unroll
            for (int j = 2; j < 4; j++) {
                dH[tid + j * 256] = __ldcg(sH + tid + j * 256);
                dL[tid + j * 256] = __ldcg(sL + tid + j * 256);
            }
            __syncthreads();

            float acc[2][4];
#pragma unroll
            for (int e = 0; e < 2; e++)
#pragma unroll
                for (int j = 0; j < 4; j++) acc[e][j] = 0.f;

            const uint32_t* Aq_hi = Ahi + q * 2048;
            const uint32_t* Aq_lo = Alo + q * 2048;
#pragma unroll 8
            for (int kt = 0; kt < 16; kt++) {
                uint4 ahv = *(const uint4*)(Aq_hi + (kt * 32 + lane) * 4);
                uint4 alv = *(const uint4*)(Aq_lo + (kt * 32 + lane) * 4);
                const uint32_t* ah = (const uint32_t*)&ahv;
                const uint32_t* al = (const uint32_t*)&alv;
#pragma unroll
                for (int e = 0; e < 2; e++) {
                    const int nt = nt0 + e;
                    uint2 bh = *(const uint2*)(Bhi + ((kt * 4 + nt) * 32 + lane) * 2);
                    uint2 bl = *(const uint2*)(Blo + ((kt * 4 + nt) * 32 + lane) * 2);
                    mma_f16(acc[e], ah, bh.x, bh.y);
                    mma_f16(acc[e], al, bh.x, bh.y);
                    mma_f16(acc[e], ah, bl.x, bl.y);
                }
            }
            {
                const int i_lo = lane >> 2;
                const int colb = (lane & 3) * 2;
#pragma unroll
                for (int e = 0; e < 2; e++) {
                    const int col = (nt0 + e) * 8 + colb;
                    gex[(q * 16 + i_lo) * 33 + col]     = acc[e][0];
                    gex[(q * 16 + i_lo) * 33 + col + 1] = acc[e][1];
                    gex[(q * 16 + i_lo + 8) * 33 + col]     = acc[e][2];
                    gex[(q * 16 + i_lo + 8) * 33 + col + 1] = acc[e][3];
                }
            }
            __syncthreads();

#pragma unroll
            for (int qq = 0; qq < 4; qq++) {
                ga[qq][0] += gex[(qq * 16 + ci) * 33 + cb];
                ga[qq][1] += gex[(qq * 16 + ci) * 33 + cb + 1];
            }
        }

        float h0, h1;
        {
            float ig = sigf(ga[0][0]);
            float fg = sigf(ga[1][0]);
            float gg = tanhf_fast(ga[2][0]);
            float og = sigf(ga[3][0]);
            cst0 = fg * cst0 + ig * gg;
            h0 = og * tanhf_fast(cst0);
        }
        {
            float ig = sigf(ga[0][1]);
            float fg = sigf(ga[1][1]);
            float gg = tanhf_fast(ga[2][1]);
            float og = sigf(ga[3][1]);
            cst1 = fg * cst1 + ig * gg;
            h1 = og * tanhf_fast(cst1);
        }

        // write h (fp32 for fc1) and f16 hi/lo fragment halves (parity st&1)
        {
            const int k = hc * 16 + ci;
            *(float2*)(g_h + (((size_t)(dir * T_ + t)) * H_ + k) * B_ + bg * 32 + cb)
                = make_float2(h0, h1);

            const size_t hb = ((size_t)grp * 2 + (st & 1)) * 4096;
            uint16_t* HHi = (uint16_t*)g_hfrag16_hi;
            uint16_t* HLo = (uint16_t*)g_hfrag16_lo;
            uint16_t fhi, flo;
            // cell 0: n = cb
            {
                const int nt = cb >> 3;
                const int laneb = (cb & 7) * 4 + s_tig;
                const size_t word = hb + (((size_t)hc * 4 + nt) * 32 + laneb) * 2 + s_reg;
                split_f16_u16(h0, fhi, flo);
                HHi[word * 2 + s_half] = fhi;
                HLo[word * 2 + s_half] = flo;
            }
            // cell 1: n = cb+1
            {
                const int b1 = cb + 1;
                const int nt = b1 >> 3;
                const int laneb = (b1 & 7) * 4 + s_tig;
                const size_t word = hb + (((size_t)hc * 4 + nt) * 32 + laneb) * 2 + s_reg;
                split_f16_u16(h1, fhi, flo);
                HHi[word * 2 + s_half] = fhi;
                HLo[word * 2 + s_half] = flo;
            }
        }
        __syncthreads();
        if (tid == 0) {
            __threadfence();
            int* fp = g_flags + ((grp * T_ + st) << 4) + hc;
            asm volatile("st.release.gpu.global.b32 [%0], %1;" :: "l"(fp), "r"(1) : "memory");
        }
    }
}

// =============================================================================
// fc1 (3xTF32) + fused cls: writes g_unary directly (no g_inter round trip).
// =============================================================================
#define XA_PAD 136
#define XB_PAD 72
#define XA_SZ  (32 * XA_PAD)
#define XB_SZ  (32 * XB_PAD)
#define X_AH(buf) ((buf) * XA_SZ)
#define X_AL(buf) (2 * XA_SZ + (buf) * XA_SZ)
#define X_BH(buf) (4 * XA_SZ + (buf) * XB_SZ)
#define X_BL(buf) (4 * XA_SZ + 2 * XB_SZ + (buf) * XB_SZ)
#define X_SMEM_BYTES ((4 * XA_SZ + 4 * XB_SZ + 64) * 4)
// epilogue reuse of the same smem: sIf (128x65 f32) then sWc (17*128 f32)
#define XI_PITCH 65
#define XW_OFF   (128 * XI_PITCH)   // 8320

__global__ void __launch_bounds__(256, 2)
fc1_kernel(const float* __restrict__ W, const float* __restrict__ bias,
           const float* __restrict__ clsW, const float* __restrict__ clsb) {
    extern __shared__ uint32_t sm[];
    const int tid = threadIdx.x;
    const int t   = blockIdx.x;

    const int rowA = tid & 127;
    const int kqA  = tid >> 7;
    const float* Arow = W + (size_t)rowA * 512;

    const int wid  = tid >> 5;
    const int lane = tid & 31;
    const int r    = lane >> 2;
    const int cidx = lane & 3;

    float acc[8][4];
#pragma unroll
    for (int i = 0; i < 8; i++)
#pragma unroll
        for (int j = 0; j < 4; j++) acc[i][j] = 0.f;

    float4 av[4];
    float4 bv[2];

#pragma unroll
    for (int j = 0; j < 4; j++) {
        int gk4 = kqA + 2 * j;
        av[j] = *(const float4*)(Arow + gk4 * 4);
    }
#pragma unroll
    for (int j = 0; j < 2; j++) {
        int f4id = tid + j * 256;
        int kl = f4id >> 4, b4 = f4id & 15;
        int kgl = kl;
        int d = kgl >> 8, kh = kgl & 255;
        bv[j] = *(const float4*)(g_h + ((size_t)(d * T_ + t) * 256 + kh) * 64 + b4 * 4);
    }
#pragma unroll
    for (int j = 0; j < 4; j++) {
        int kl = (kqA + 2 * j) * 4;
        const float* v = (const float*)&av[j];
#pragma unroll
        for (int c = 0; c < 4; c++) {
            uint32_t hi, lo; split_tf32(v[c], hi, lo);
            sm[X_AH(0) + (kl + c) * XA_PAD + rowA] = hi;
            sm[X_AL(0) + (kl + c) * XA_PAD + rowA] = lo;
        }
    }
#pragma unroll
    for (int j = 0; j < 2; j++) {
        int f4id = tid + j * 256;
        int kl = f4id >> 4, b4 = f4id & 15;
        const float* v = (const float*)&bv[j];
#pragma unroll
        for (int c = 0; c < 4; c++) {
            uint32_t hi, lo; split_tf32(v[c], hi, lo);
            sm[X_BH(0) + kl * XB_PAD + b4 * 4 + c] = hi;
            sm[X_BL(0) + kl * XB_PAD + b4 * 4 + c] = lo;
        }
    }
    __syncthreads();

    for (int kc = 0; kc < 16; kc++) {
        const int buf = kc & 1;
        if (kc < 15) {
#pragma unroll
            for (int j = 0; j < 4; j++) {
                int gk4 = (kc + 1) * 8 + kqA + 2 * j;
                av[j] = *(const float4*)(Arow + gk4 * 4);
            }
#pragma unroll
            for (int j = 0; j < 2; j++) {
                int f4id = tid + j * 256;
                int kl = f4id >> 4, b4 = f4id & 15;
                int kgl = (kc + 1) * 32 + kl;
                int d = kgl >> 8, kh = kgl & 255;
                bv[j] = *(const float4*)(g_h + ((size_t)(d * T_ + t) * 256 + kh) * 64 + b4 * 4);
            }
        }
        const uint32_t* AH = sm + X_AH(buf);
        const uint32_t* AL = sm + X_AL(buf);
        const uint32_t* BH = sm + X_BH(buf);
        const uint32_t* BL = sm + X_BL(buf);
        const int row0 = wid * 16 + r;
#pragma unroll
        for (int kk = 0; kk < 4; kk++) {
            const int base = kk * 8 + cidx;
            uint32_t ah[4], al[4];
            ah[0] = AH[base * XA_PAD + row0];
            ah[1] = AH[base * XA_PAD + row0 + 8];
            ah[2] = AH[(base + 4) * XA_PAD + row0];
            ah[3] = AH[(base + 4) * XA_PAD + row0 + 8];
            al[0] = AL[base * XA_PAD + row0];
            al[1] = AL[base * XA_PAD + row0 + 8];
            al[2] = AL[(base + 4) * XA_PAD + row0];
            al[3] = AL[(base + 4) * XA_PAD + row0 + 8];
#pragma unroll
            for (int nt = 0; nt < 8; nt++) {
                const int col = nt * 8 + r;
                uint32_t bh0 = BH[base * XB_PAD + col];
                uint32_t bh1 = BH[(base + 4) * XB_PAD + col];
                uint32_t bl0 = BL[base * XB_PAD + col];
                uint32_t bl1 = BL[(base + 4) * XB_PAD + col];
                mma_tf32(acc[nt], ah, bh0, bh1);
                mma_tf32(acc[nt], al, bh0, bh1);
                mma_tf32(acc[nt], ah, bl0, bl1);
            }
        }
        if (kc < 15) {
            const int nb = (kc + 1) & 1;
#pragma unroll
            for (int j = 0; j < 4; j++) {
                int kl = (kqA + 2 * j) * 4;
                const float* v = (const float*)&av[j];
#pragma unroll
                for (int c = 0; c < 4; c++) {
                    uint32_t hi, lo; split_tf32(v[c], hi, lo);
                    sm[X_AH(nb) + (kl + c) * XA_PAD + rowA] = hi;
                    sm[X_AL(nb) + (kl + c) * XA_PAD + rowA] = lo;
                }
            }
#pragma unroll
            for (int j = 0; j < 2; j++) {
                int f4id = tid + j * 256;
                int kl = f4id >> 4, b4 = f4id & 15;
                const float* v = (const float*)&bv[j];
#pragma unroll
                for (int c = 0; c < 4; c++) {
                    uint32_t hi, lo; split_tf32(v[c], hi, lo);
                    sm[X_BH(nb) + kl * XB_PAD + b4 * 4 + c] = hi;
                    sm[X_BL(nb) + kl * XB_PAD + b4 * 4 + c] = lo;
                }
            }
        }
        __syncthreads();
    }

    // ---- fused epilogue: relu tile -> smem, then cls -> g_unary
    float* sIf = (float*)sm;
    float* sWc = (float*)(sm + XW_OFF);
    {
        const int gr0 = wid * 16 + r;
        const int gr1 = gr0 + 8;
        const float bv0 = bias[gr0];
        const float bv1 = bias[gr1];
#pragma unroll
        for (int nt = 0; nt < 8; nt++) {
            const int col = nt * 8 + 2 * cidx;
            sIf[gr0 * XI_PITCH + col]     = fmaxf(acc[nt][0] + bv0, 0.f);
            sIf[gr0 * XI_PITCH + col + 1] = fmaxf(acc[nt][1] + bv0, 0.f);
            sIf[gr1 * XI_PITCH + col]     = fmaxf(acc[nt][2] + bv1, 0.f);
            sIf[gr1 * XI_PITCH + col + 1] = fmaxf(acc[nt][3] + bv1, 0.f);
        }
    }
    for (int i = tid; i < NL * INTER_; i += 256) sWc[i] = clsW[i];
    __syncthreads();

    const int b  = tid & 63;
    const int lg = tid >> 6;
    for (int l = lg; l < NL; l += 4) {
        float a = clsb[l];
        const float* wr = sWc + l * INTER_;
#pragma unroll 8
        for (int n = 0; n < INTER_; n++) a += wr[n] * sIf[n * XI_PITCH + b];
        g_unary[((size_t)b * T_ + t) * TL + l] = a;
    }
    if (tid < 128) {
        int bb = tid & 63;
        int l  = NL + (tid >> 6);
        g_unary[((size_t)bb * T_ + t) * TL + l] = LOW_POT;
    }
}

// ---------------- Viterbi + backtrace (one block per batch element) ---------
__global__ void viterbi_kernel(const float* __restrict__ trans, float* __restrict__ out,
                               int score_off, int label_off) {
    __shared__ float tr[TL * TL];
    __shared__ float s0[TL], s1[TL];
    __shared__ unsigned char bp[T_][TL];
    const int b = blockIdx.x;
    const int tid = threadIdx.x;

    for (int i = tid; i < TL * TL; i += 32) tr[i] = trans[i];
    if (tid < TL) s0[tid] = (tid == START_L) ? 0.f : LOW_POT;
    __syncthreads();

    const float* ub = g_unary + (size_t)b * T_ * TL;
    float* sc = s0;
    float* sn = s1;
    for (int t = 0; t < T_; t++) {
        if (tid < TL) {
            float best = sc[0] + tr[tid * TL + 0];
            int bpi = 0;
#pragma unroll
            for (int p = 1; p < TL; p++) {
                float v = sc[p] + tr[tid * TL + p];
                if (v > best) { best = v; bpi = p; }
            }
            sn[tid] = best + ub[t * TL + tid];
            bp[t][tid] = (unsigned char)bpi;
        }
        __syncthreads();
        float* tmp = sc; sc = sn; sn = tmp;
    }
    if (tid == 0) {
        float best = sc[0] + tr[END_L * TL + 0];
        int li = 0;
        for (int l = 1; l < TL; l++) {
            float v = sc[l] + tr[END_L * TL + l];
            if (v > best) { best = v; li = l; }
        }
        if (score_off >= 0) out[score_off + b] = best;
        if (label_off >= 0) {
            int cur = li;
            for (int t = T_ - 1; t >= 0; t--) {
                out[label_off + (size_t)b * T_ + t] = (float)cur;
                cur = bp[t][cur];
            }
        }
    }
}

// ---------------- launch -----------------------------------------------------
extern "C" void kernel_launch(void* const* d_in, const int* in_sizes, int n_in,
                              void* d_out, int out_size) {
    const int*   x       = (const int*)d_in[0];
    const float* emb     = (const float*)d_in[1];
    const float* W_ih_f  = (const float*)d_in[2];
    const float* W_hh_f  = (const float*)d_in[3];
    const float* b_f     = (const float*)d_in[4];
    const float* W_ih_b  = (const float*)d_in[5];
    const float* W_hh_b  = (const float*)d_in[6];
    const float* b_b     = (const float*)d_in[7];
    const float* fc1_W   = (const float*)d_in[8];
    const float* fc1_b   = (const float*)d_in[9];
    const float* cls_W   = (const float*)d_in[10];
    const float* cls_b   = (const float*)d_in[11];
    const float* trans   = (const float*)d_in[12];
    float* out = (float*)d_out;

    int score_off = 0, label_off = B_;
    if (out_size == B_ * T_)      { score_off = -1; label_off = 0; }
    else if (out_size == B_)      { label_off = -1; }

    cudaFuncSetAttribute(lstm_kernel, cudaFuncAttributeMaxDynamicSharedMemorySize, L_SMEM_BYTES);
    cudaFuncSetAttribute(xproj_kernel, cudaFuncAttributeMaxDynamicSharedMemorySize, XP_SMEM_BYTES);
    cudaFuncSetAttribute(fc1_kernel, cudaFuncAttributeMaxDynamicSharedMemorySize, X_SMEM_BYTES);

    zero_bar_kernel<<<64, 256>>>();
    prep_whh_kernel<<<1024, 256>>>(W_hh_f, W_hh_b);
    xproj_kernel<<<dim3(8, T_, 2), 256, XP_SMEM_BYTES>>>(x, emb, W_ih_f, b_f, W_ih_b, b_b);
    lstm_kernel<<<64, 256, L_SMEM_BYTES>>>();
    fc1_kernel<<<T_, 256, X_SMEM_BYTES>>>(fc1_W, fc1_b, cls_W, cls_b);
    viterbi_kernel<<<B_, 32>>>(trans, out, score_off, label_off);
}

// round 12
// speedup vs baseline: 1.1690x; 1.0699x over previous
#include <cuda_runtime.h>
#include <cuda_bf16.h>
#include <cuda_fp16.h>
#include <math.h>
#include <stdint.h>

// Problem constants
#define B_   64
#define T_   256
#define E_   300
#define H_   256
#define G4H  1024      // 4*H
#define INTER_ 128
#define NL   17
#define TL   19        // NUM_LABELS + 2
#define START_L 17
#define END_L   18
#define LOW_POT (-10000.0f)

// ---------------- scratch (device globals; no allocations allowed) ----------
__device__ float g_xproj[(size_t)2 * T_ * G4H * B_];   // [dir][t][n(1024)][b]
__device__ float g_h[(size_t)2 * T_ * H_ * B_];        // [dir][t][k][b]
__device__ float g_unary[(size_t)B_ * T_ * TL];        // [b][t][l]
__device__ int   g_flags[4 * T_ * 16];                 // per-(grp,step,producer) flags

// W_hh in f16 mma-fragment order: [dir][hc(16)][q(4)][kt(16)][lane(32)][reg(4)]
__device__ uint32_t g_wfrag16_hi[2 * 16 * 4 * 16 * 32 * 4];
__device__ uint32_t g_wfrag16_lo[2 * 16 * 4 * 16 * 32 * 4];
// h in f16 mma B-fragment order: [grp(4)][par(2)][kt(16)][nt(4)][lane(32)][reg(2)]
__device__ uint32_t g_hfrag16_hi[4 * 2 * 16 * 4 * 32 * 2];
__device__ uint32_t g_hfrag16_lo[4 * 2 * 16 * 4 * 32 * 2];

// ---------------- helpers ----------------------------------------------------
__device__ __forceinline__ uint32_t f2tf32(float x) {
    uint32_t r;
    asm("cvt.rna.tf32.f32 %0, %1;" : "=r"(r) : "f"(x));
    return r;
}
__device__ __forceinline__ void split_tf32(float x, uint32_t& hi, uint32_t& lo) {
    hi = f2tf32(x);
    lo = f2tf32(x - __uint_as_float(hi));
}
__device__ __forceinline__ void mma_tf32(float* d, const uint32_t* a, uint32_t b0, uint32_t b1) {
    asm volatile(
        "mma.sync.aligned.m16n8k8.row.col.f32.tf32.tf32.f32 "
        "{%0,%1,%2,%3}, {%4,%5,%6,%7}, {%8,%9}, {%0,%1,%2,%3};"
        : "+f"(d[0]), "+f"(d[1]), "+f"(d[2]), "+f"(d[3])
        : "r"(a[0]), "r"(a[1]), "r"(a[2]), "r"(a[3]), "r"(b0), "r"(b1));
}
__device__ __forceinline__ void mma_f16(float* d, const uint32_t* a, uint32_t b0, uint32_t b1) {
    asm volatile(
        "mma.sync.aligned.m16n8k16.row.col.f32.f16.f16.f32 "
        "{%0,%1,%2,%3}, {%4,%5,%6,%7}, {%8,%9}, {%0,%1,%2,%3};"
        : "+f"(d[0]), "+f"(d[1]), "+f"(d[2]), "+f"(d[3])
        : "r"(a[0]), "r"(a[1]), "r"(a[2]), "r"(a[3]), "r"(b0), "r"(b1));
}
__device__ __forceinline__ void split_pack_f16(float x0, float x1, uint32_t& hi, uint32_t& lo) {
    __half h0 = __float2half_rn(x0);
    __half h1 = __float2half_rn(x1);
    __half l0 = __float2half_rn(x0 - __half2float(h0));
    __half l1 = __float2half_rn(x1 - __half2float(h1));
    hi = (uint32_t)__half_as_ushort(h0) | ((uint32_t)__half_as_ushort(h1) << 16);
    lo = (uint32_t)__half_as_ushort(l0) | ((uint32_t)__half_as_ushort(l1) << 16);
}
__device__ __forceinline__ void split_f16_u16(float x, uint16_t& hi, uint16_t& lo) {
    __half h = __float2half_rn(x);
    __half l = __float2half_rn(x - __half2float(h));
    hi = __half_as_ushort(h);
    lo = __half_as_ushort(l);
}

// fast activations (~1e-7 rel err, clamped)
__device__ __forceinline__ float sigf(float x) {
    x = fmaxf(fminf(x, 30.f), -30.f);
    return __fdividef(1.f, 1.f + __expf(-x));
}
__device__ __forceinline__ float tanhf_fast(float x) {
    x = fmaxf(fminf(x, 15.f), -15.f);
    float e = __expf(2.f * x);
    return __fdividef(e - 1.f, e + 1.f);
}

// ---------------- flag zeroing (graph-replay determinism) -------------------
__global__ void zero_bar_kernel() {
    int i = blockIdx.x * 256 + threadIdx.x;
    if (i < 4 * T_ * 16) g_flags[i] = 0;
}

// ---------------- W_hh f16 fragment prep ------------------------------------
__global__ void prep_whh_kernel(const float* __restrict__ Whf,
                                const float* __restrict__ Whb) {
    int idx = blockIdx.x * 256 + threadIdx.x;
    if (idx >= 2 * 16 * 4 * 16 * 32 * 4) return;
    int reg  = idx & 3;
    int lane = (idx >> 2) & 31;
    int kt   = (idx >> 7) & 15;
    int q    = (idx >> 11) & 3;
    int hc   = (idx >> 13) & 15;
    int dir  = (idx >> 17) & 1;
    const float* W = dir ? Whb : Whf;
    int i  = (lane >> 2) + 8 * (reg & 1);
    int g  = q * 256 + hc * 16 + i;
    int k0 = kt * 16 + (lane & 3) * 2 + 8 * (reg >> 1);
    float v0 = W[(size_t)g * H_ + k0];
    float v1 = W[(size_t)g * H_ + k0 + 1];
    uint32_t hi, lo;
    split_pack_f16(v0, v1, hi, lo);
    g_wfrag16_hi[idx] = hi;
    g_wfrag16_lo[idx] = lo;
}

// =============================================================================
// xproj GEMM (fp16x3, m16n8k16) — r9 proven, standalone (occupancy 2)
// =============================================================================
#define XP_PAD 20
#define XP_A_SZ (128 * XP_PAD)
#define XP_B_SZ (64 * XP_PAD)
#define XP_AH(b) ((b) * XP_A_SZ)
#define XP_AL(b) (2 * XP_A_SZ + (b) * XP_A_SZ)
#define XP_BH(b) (4 * XP_A_SZ + (b) * XP_B_SZ)
#define XP_BL(b) (4 * XP_A_SZ + 2 * XP_B_SZ + (b) * XP_B_SZ)
#define XP_TOK   (4 * XP_A_SZ + 4 * XP_B_SZ)
#define XP_SMEM_BYTES ((4 * XP_A_SZ + 4 * XP_B_SZ + 64) * 4)   // 61696

__global__ void __launch_bounds__(256, 2)
xproj_kernel(const int* __restrict__ x,
             const float* __restrict__ emb,
             const float* __restrict__ Wf, const float* __restrict__ bf,
             const float* __restrict__ Wb, const float* __restrict__ bb) {
    extern __shared__ uint32_t sm[];
    const int tid  = threadIdx.x;
    const int n0   = blockIdx.x * 128;
    const int t    = blockIdx.y;
    const int dir  = blockIdx.z;
    const float* W    = dir ? Wb : Wf;
    const float* bias = dir ? bb : bf;

    int* tok = (int*)(sm + XP_TOK);
    if (tid < 64) tok[tid] = x[tid * T_ + t];
    __syncthreads();

    const int rowA = tid & 127;
    const int kqA  = tid >> 7;
    const int rowB = tid & 63;
    const int kqB  = tid >> 6;
    const float* Arow = W + (size_t)(n0 + rowA) * E_;
    const float* Brow = emb + (size_t)tok[rowB] * E_;

    const int wid  = tid >> 5;
    const int lane = tid & 31;
    const int r    = lane >> 2;
    const int cidx = lane & 3;
    const int row0 = wid * 16 + r;

    float acc[8][4];
#pragma unroll
    for (int i = 0; i < 8; i++)
#pragma unroll
        for (int j = 0; j < 4; j++) acc[i][j] = 0.f;

    float4 av[4];
    float4 bv[2];

#pragma unroll
    for (int j = 0; j < 4; j++) {
        int gk4 = kqA * 4 + j;
        av[j] = (gk4 < 75) ? *(const float4*)(Arow + gk4 * 4) : make_float4(0, 0, 0, 0);
    }
#pragma unroll
    for (int j = 0; j < 2; j++) {
        int gk4 = kqB * 2 + j;
        bv[j] = (gk4 < 75) ? *(const float4*)(Brow + gk4 * 4) : make_float4(0, 0, 0, 0);
    }
#pragma unroll
    for (int j = 0; j < 4; j++) {
        int k2b = kqA * 8 + j * 2;
        uint32_t h0, l0, h1, l1;
        split_pack_f16(av[j].x, av[j].y, h0, l0);
        split_pack_f16(av[j].z, av[j].w, h1, l1);
        sm[XP_AH(0) + rowA * XP_PAD + k2b]     = h0;
        sm[XP_AH(0) + rowA * XP_PAD + k2b + 1] = h1;
        sm[XP_AL(0) + rowA * XP_PAD + k2b]     = l0;
        sm[XP_AL(0) + rowA * XP_PAD + k2b + 1] = l1;
    }
#pragma unroll
    for (int j = 0; j < 2; j++) {
        int k2b = kqB * 4 + j * 2;
        uint32_t h0, l0, h1, l1;
        split_pack_f16(bv[j].x, bv[j].y, h0, l0);
        split_pack_f16(bv[j].z, bv[j].w, h1, l1);
        sm[XP_BH(0) + rowB * XP_PAD + k2b]     = h0;
        sm[XP_BH(0) + rowB * XP_PAD + k2b + 1] = h1;
        sm[XP_BL(0) + rowB * XP_PAD + k2b]     = l0;
        sm[XP_BL(0) + rowB * XP_PAD + k2b + 1] = l1;
    }
    __syncthreads();

    for (int kc = 0; kc < 10; kc++) {
        const int buf = kc & 1;
        if (kc < 9) {
#pragma unroll
            for (int j = 0; j < 4; j++) {
                int gk4 = (kc + 1) * 8 + kqA * 4 + j;
                av[j] = (gk4 < 75) ? *(const float4*)(Arow + gk4 * 4) : make_float4(0, 0, 0, 0);
            }
#pragma unroll
            for (int j = 0; j < 2; j++) {
                int gk4 = (kc + 1) * 8 + kqB * 2 + j;
                bv[j] = (gk4 < 75) ? *(const float4*)(Brow + gk4 * 4) : make_float4(0, 0, 0, 0);
            }
        }
        const uint32_t* AHp = sm + XP_AH(buf);
        const uint32_t* ALp = sm + XP_AL(buf);
        const uint32_t* BHp = sm + XP_BH(buf);
        const uint32_t* BLp = sm + XP_BL(buf);
#pragma unroll
        for (int s2 = 0; s2 < 2; s2++) {
            const int k2b = s2 * 8 + cidx;
            uint32_t ah[4], al[4];
            ah[0] = AHp[row0 * XP_PAD + k2b];
            ah[1] = AHp[(row0 + 8) * XP_PAD + k2b];
            ah[2] = AHp[row0 * XP_PAD + k2b + 4];
            ah[3] = AHp[(row0 + 8) * XP_PAD + k2b + 4];
            al[0] = ALp[row0 * XP_PAD + k2b];
            al[1] = ALp[(row0 + 8) * XP_PAD + k2b];
            al[2] = ALp[row0 * XP_PAD + k2b + 4];
            al[3] = ALp[(row0 + 8) * XP_PAD + k2b + 4];
#pragma unroll
            for (int nt = 0; nt < 8; nt++) {
                const int col = nt * 8 + r;
                uint32_t bh0 = BHp[col * XP_PAD + k2b];
                uint32_t bh1 = BHp[col * XP_PAD + k2b + 4];
                uint32_t bl0 = BLp[col * XP_PAD + k2b];
                uint32_t bl1 = BLp[col * XP_PAD + k2b + 4];
                mma_f16(acc[nt], ah, bh0, bh1);
                mma_f16(acc[nt], al, bh0, bh1);
                mma_f16(acc[nt], ah, bl0, bl1);
            }
        }
        if (kc < 9) {
            const int nb = (kc + 1) & 1;
#pragma unroll
            for (int j = 0; j < 4; j++) {
                int k2b = kqA * 8 + j * 2;
                uint32_t h0, l0, h1, l1;
                split_pack_f16(av[j].x, av[j].y, h0, l0);
                split_pack_f16(av[j].z, av[j].w, h1, l1);
                sm[XP_AH(nb) + rowA * XP_PAD + k2b]     = h0;
                sm[XP_AH(nb) + rowA * XP_PAD + k2b + 1] = h1;
                sm[XP_AL(nb) + rowA * XP_PAD + k2b]     = l0;
                sm[XP_AL(nb) + rowA * XP_PAD + k2b + 1] = l1;
            }
#pragma unroll
            for (int j = 0; j < 2; j++) {
                int k2b = kqB * 4 + j * 2;
                uint32_t h0, l0, h1, l1;
                split_pack_f16(bv[j].x, bv[j].y, h0, l0);
                split_pack_f16(bv[j].z, bv[j].w, h1, l1);
                sm[XP_BH(nb) + rowB * XP_PAD + k2b]     = h0;
                sm[XP_BH(nb) + rowB * XP_PAD + k2b + 1] = h1;
                sm[XP_BL(nb) + rowB * XP_PAD + k2b]     = l0;
                sm[XP_BL(nb) + rowB * XP_PAD + k2b + 1] = l1;
            }
        }
        __syncthreads();
    }

    const int gr0 = n0 + wid * 16 + r;
    const int gr1 = gr0 + 8;
    const float bv0 = bias[gr0];
    const float bv1 = bias[gr1];
    float* outb = g_xproj + ((size_t)(dir * T_ + t)) * (G4H * B_);
#pragma unroll
    for (int nt = 0; nt < 8; nt++) {
        const int col = nt * 8 + 2 * cidx;
        float2 o0 = make_float2(acc[nt][0] + bv0, acc[nt][1] + bv0);
        float2 o1 = make_float2(acc[nt][2] + bv1, acc[nt][3] + bv1);
        *(float2*)(outb + (size_t)gr0 * B_ + col) = o0;
        *(float2*)(outb + (size_t)gr1 * B_ + col) = o1;
    }
}

// =============================================================================
// LSTM recurrence (3xFP16 mma) — r9 exact structure (monolithic wait + copy)
// 64 blocks = dir(2) x bg(2, 32 batches) x hc(16, 16 hidden units).
// =============================================================================
#define L_AHI 0
#define L_ALO 8192
#define L_BHI 16384
#define L_BLO 20480
#define L_GEX 24576
#define L_SMEM_BYTES ((24576 + 4 * 16 * 33) * 4)   // 106752

__global__ void __launch_bounds__(256, 1) lstm_kernel() {
    extern __shared__ uint32_t s[];
    uint32_t* Ahi = s + L_AHI;
    uint32_t* Alo = s + L_ALO;
    uint32_t* Bhi = s + L_BHI;
    uint32_t* Blo = s + L_BLO;
    float*    gex = (float*)(s + L_GEX);

    const int tid = threadIdx.x;
    const int bx  = blockIdx.x;
    const int dir = bx >> 5;
    const int bg  = (bx >> 4) & 1;
    const int hc  = bx & 15;
    const int grp = dir * 2 + bg;

    // ---- load this block's f16 A fragments (weights) into smem
    {
        const uint4* srcH = (const uint4*)(g_wfrag16_hi + ((size_t)(dir * 16 + hc)) * 8192);
        const uint4* srcL = (const uint4*)(g_wfrag16_lo + ((size_t)(dir * 16 + hc)) * 8192);
        uint4* dH = (uint4*)Ahi;
        uint4* dL = (uint4*)Alo;
#pragma unroll
        for (int j = 0; j < 8; j++) {
            dH[tid + j * 256] = srcH[tid + j * 256];
            dL[tid + j * 256] = srcL[tid + j * 256];
        }
    }

    const int w    = tid >> 5;
    const int lane = tid & 31;
    const int q    = w & 3;
    const int nt0  = (w >> 2) * 2;

    const int ci = (2 * tid) >> 5;     // 0..15
    const int cb = (2 * tid) & 31;     // even
    float cst0 = 0.f, cst1 = 0.f;

    // h fragment store coords (producer side), k = hc*16+ci
    const int kin   = ci;
    const int s_reg = kin >> 3;
    const int s_tig = (kin >> 1) & 3;
    const int s_half = kin & 1;

    __syncthreads();

    for (int st = 0; st < T_; st++) {
        const int t = dir ? (T_ - 1 - st) : st;

        // prefetch xproj gate pre-activations
        float2 xpv[4];
        {
            const float* xb = g_xproj + ((size_t)(dir * T_ + t)) * (G4H * B_)
                              + (size_t)(hc * 16 + ci) * B_ + bg * 32 + cb;
#pragma unroll
            for (int qq = 0; qq < 4; qq++)
                xpv[qq] = *(const float2*)(xb + (size_t)qq * (H_ * B_));
        }

        float ga[4][2];
#pragma unroll
        for (int qq = 0; qq < 4; qq++) { ga[qq][0] = xpv[qq].x; ga[qq][1] = xpv[qq].y; }

        if (st > 0) {
            // wait for all 16 producers of step st-1 (one flag line, acquire + backoff)
            if (tid < 16) {
                const int* fp = g_flags + ((grp * T_ + (st - 1)) << 4) + tid;
                int v;
                for (;;) {
                    asm volatile("ld.acquire.gpu.global.b32 %0, [%1];"
                                 : "=r"(v) : "l"(fp) : "memory");
                    if (__all_sync(0x0000FFFFu, v != 0)) break;
                    __nanosleep(30);
                }
            }
            __syncthreads();

            // copy h fragments (parity of step st-1) global -> smem: 4096 u32 each
            {
                const size_t hb = ((size_t)grp * 2 + ((st - 1) & 1)) * 4096;
                const uint4* sH = (const uint4*)(g_hfrag16_hi + hb);
                const uint4* sL = (const uint4*)(g_hfrag16_lo + hb);
                uint4* dH = (uint4*)Bhi;
                uint4* dL = (uint4*)Blo;
#pragma unroll
                for (int j = 0; j < 4; j++) {
                    dH[tid + j * 256] = __ldcg(sH + tid + j * 256);
                    dL[tid + j * 256] = __ldcg(sL + tid + j * 256);
                }
            }
            __syncthreads();

            float acc[2][4];
#pragma unroll
            for (int e = 0; e < 2; e++)
#pragma unroll
                for (int j = 0; j < 4; j++) acc[e][j] = 0.f;

            const uint32_t* Aq_hi = Ahi + q * 2048;
            const uint32_t* Aq_lo = Alo + q * 2048;
#pragma unroll 8
            for (int kt = 0; kt < 16; kt++) {
                uint4 ahv = *(const uint4*)(Aq_hi + (kt * 32 + lane) * 4);
                uint4 alv = *(const uint4*)(Aq_lo + (kt * 32 + lane) * 4);
                const uint32_t* ah = (const uint32_t*)&ahv;
                const uint32_t* al = (const uint32_t*)&alv;
#pragma unroll
                for (int e = 0; e < 2; e++) {
                    const int nt = nt0 + e;
                    uint2 bh = *(const uint2*)(Bhi + ((kt * 4 + nt) * 32 + lane) * 2);
                    uint2 bl = *(const uint2*)(Blo + ((kt * 4 + nt) * 32 + lane) * 2);
                    mma_f16(acc[e], ah, bh.x, bh.y);
                    mma_f16(acc[e], al, bh.x, bh.y);
                    mma_f16(acc[e], ah, bl.x, bl.y);
                }
            }
            {
                const int i_lo = lane >> 2;
                const int colb = (lane & 3) * 2;
#pragma unroll
                for (int e = 0; e < 2; e++) {
                    const int col = (nt0 + e) * 8 + colb;
                    gex[(q * 16 + i_lo) * 33 + col]     = acc[e][0];
                    gex[(q * 16 + i_lo) * 33 + col + 1] = acc[e][1];
                    gex[(q * 16 + i_lo + 8) * 33 + col]     = acc[e][2];
                    gex[(q * 16 + i_lo + 8) * 33 + col + 1] = acc[e][3];
                }
            }
            __syncthreads();

#pragma unroll
            for (int qq = 0; qq < 4; qq++) {
                ga[qq][0] += gex[(qq * 16 + ci) * 33 + cb];
                ga[qq][1] += gex[(qq * 16 + ci) * 33 + cb + 1];
            }
        }

        float h0, h1;
        {
            float ig = sigf(ga[0][0]);
            float fg = sigf(ga[1][0]);
            float gg = tanhf_fast(ga[2][0]);
            float og = sigf(ga[3][0]);
            cst0 = fg * cst0 + ig * gg;
            h0 = og * tanhf_fast(cst0);
        }
        {
            float ig = sigf(ga[0][1]);
            float fg = sigf(ga[1][1]);
            float gg = tanhf_fast(ga[2][1]);
            float og = sigf(ga[3][1]);
            cst1 = fg * cst1 + ig * gg;
            h1 = og * tanhf_fast(cst1);
        }

        // write h (fp32 for fc1) and f16 hi/lo fragment halves (parity st&1)
        {
            const int k = hc * 16 + ci;
            *(float2*)(g_h + (((size_t)(dir * T_ + t)) * H_ + k) * B_ + bg * 32 + cb)
                = make_float2(h0, h1);

            const size_t hb = ((size_t)grp * 2 + (st & 1)) * 4096;
            uint16_t* HHi = (uint16_t*)g_hfrag16_hi;
            uint16_t* HLo = (uint16_t*)g_hfrag16_lo;
            uint16_t fhi, flo;
            // cell 0: n = cb
            {
                const int nt = cb >> 3;
                const int laneb = (cb & 7) * 4 + s_tig;
                const size_t word = hb + (((size_t)hc * 4 + nt) * 32 + laneb) * 2 + s_reg;
                split_f16_u16(h0, fhi, flo);
                HHi[word * 2 + s_half] = fhi;
                HLo[word * 2 + s_half] = flo;
            }
            // cell 1: n = cb+1
            {
                const int b1 = cb + 1;
                const int nt = b1 >> 3;
                const int laneb = (b1 & 7) * 4 + s_tig;
                const size_t word = hb + (((size_t)hc * 4 + nt) * 32 + laneb) * 2 + s_reg;
                split_f16_u16(h1, fhi, flo);
                HHi[word * 2 + s_half] = fhi;
                HLo[word * 2 + s_half] = flo;
            }
        }
        __syncthreads();
        if (tid == 0) {
            __threadfence();
            int* fp = g_flags + ((grp * T_ + st) << 4) + hc;
            asm volatile("st.release.gpu.global.b32 [%0], %1;" :: "l"(fp), "r"(1) : "memory");
        }
    }
}

// =============================================================================
// fc1 (3xTF32) + fused cls: writes g_unary directly (no g_inter round trip).
// =============================================================================
#define XA_PAD 136
#define XB_PAD 72
#define XA_SZ  (32 * XA_PAD)
#define XB_SZ  (32 * XB_PAD)
#define X_AH(buf) ((buf) * XA_SZ)
#define X_AL(buf) (2 * XA_SZ + (buf) * XA_SZ)
#define X_BH(buf) (4 * XA_SZ + (buf) * XB_SZ)
#define X_BL(buf) (4 * XA_SZ + 2 * XB_SZ + (buf) * XB_SZ)
#define X_SMEM_BYTES ((4 * XA_SZ + 4 * XB_SZ + 64) * 4)
// epilogue reuse of the same smem: sIf (128x65 f32) then sWc (17*128 f32)
#define XI_PITCH 65
#define XW_OFF   (128 * XI_PITCH)   // 8320

__global__ void __launch_bounds__(256, 2)
fc1_kernel(const float* __restrict__ W, const float* __restrict__ bias,
           const float* __restrict__ clsW, const float* __restrict__ clsb) {
    extern __shared__ uint32_t sm[];
    const int tid = threadIdx.x;
    const int t   = blockIdx.x;

    const int rowA = tid & 127;
    const int kqA  = tid >> 7;
    const float* Arow = W + (size_t)rowA * 512;

    const int wid  = tid >> 5;
    const int lane = tid & 31;
    const int r    = lane >> 2;
    const int cidx = lane & 3;

    float acc[8][4];
#pragma unroll
    for (int i = 0; i < 8; i++)
#pragma unroll
        for (int j = 0; j < 4; j++) acc[i][j] = 0.f;

    float4 av[4];
    float4 bv[2];

#pragma unroll
    for (int j = 0; j < 4; j++) {
        int gk4 = kqA + 2 * j;
        av[j] = *(const float4*)(Arow + gk4 * 4);
    }
#pragma unroll
    for (int j = 0; j < 2; j++) {
        int f4id = tid + j * 256;
        int kl = f4id >> 4, b4 = f4id & 15;
        int kgl = kl;
        int d = kgl >> 8, kh = kgl & 255;
        bv[j] = *(const float4*)(g_h + ((size_t)(d * T_ + t) * 256 + kh) * 64 + b4 * 4);
    }
#pragma unroll
    for (int j = 0; j < 4; j++) {
        int kl = (kqA + 2 * j) * 4;
        const float* v = (const float*)&av[j];
#pragma unroll
        for (int c = 0; c < 4; c++) {
            uint32_t hi, lo; split_tf32(v[c], hi, lo);
            sm[X_AH(0) + (kl + c) * XA_PAD + rowA] = hi;
            sm[X_AL(0) + (kl + c) * XA_PAD + rowA] = lo;
        }
    }
#pragma unroll
    for (int j = 0; j < 2; j++) {
        int f4id = tid + j * 256;
        int kl = f4id >> 4, b4 = f4id & 15;
        const float* v = (const float*)&bv[j];
#pragma unroll
        for (int c = 0; c < 4; c++) {
            uint32_t hi, lo; split_tf32(v[c], hi, lo);
            sm[X_BH(0) + kl * XB_PAD + b4 * 4 + c] = hi;
            sm[X_BL(0) + kl * XB_PAD + b4 * 4 + c] = lo;
        }
    }
    __syncthreads();

    for (int kc = 0; kc < 16; kc++) {
        const int buf = kc & 1;
        if (kc < 15) {
#pragma unroll
            for (int j = 0; j < 4; j++) {
                int gk4 = (kc + 1) * 8 + kqA + 2 * j;
                av[j] = *(const float4*)(Arow + gk4 * 4);
            }
#pragma unroll
            for (int j = 0; j < 2; j++) {
                int f4id = tid + j * 256;
                int kl = f4id >> 4, b4 = f4id & 15;
                int kgl = (kc + 1) * 32 + kl;
                int d = kgl >> 8, kh = kgl & 255;
                bv[j] = *(const float4*)(g_h + ((size_t)(d * T_ + t) * 256 + kh) * 64 + b4 * 4);
            }
        }
        const uint32_t* AH = sm + X_AH(buf);
        const uint32_t* AL = sm + X_AL(buf);
        const uint32_t* BH = sm + X_BH(buf);
        const uint32_t* BL = sm + X_BL(buf);
        const int row0 = wid * 16 + r;
#pragma unroll
        for (int kk = 0; kk < 4; kk++) {
            const int base = kk * 8 + cidx;
            uint32_t ah[4], al[4];
            ah[0] = AH[base * XA_PAD + row0];
            ah[1] = AH[base * XA_PAD + row0 + 8];
            ah[2] = AH[(base + 4) * XA_PAD + row0];
            ah[3] = AH[(base + 4) * XA_PAD + row0 + 8];
            al[0] = AL[base * XA_PAD + row0];
            al[1] = AL[base * XA_PAD + row0 + 8];
            al[2] = AL[(base + 4) * XA_PAD + row0];
            al[3] = AL[(base + 4) * XA_PAD + row0 + 8];
#pragma unroll
            for (int nt = 0; nt < 8; nt++) {
                const int col = nt * 8 + r;
                uint32_t bh0 = BH[base * XB_PAD + col];
                uint32_t bh1 = BH[(base + 4) * XB_PAD + col];
                uint32_t bl0 = BL[base * XB_PAD + col];
                uint32_t bl1 = BL[(base + 4) * XB_PAD + col];
                mma_tf32(acc[nt], ah, bh0, bh1);
                mma_tf32(acc[nt], al, bh0, bh1);
                mma_tf32(acc[nt], ah, bl0, bl1);
            }
        }
        if (kc < 15) {
            const int nb = (kc + 1) & 1;
#pragma unroll
            for (int j = 0; j < 4; j++) {
                int kl = (kqA + 2 * j) * 4;
                const float* v = (const float*)&av[j];
#pragma unroll
                for (int c = 0; c < 4; c++) {
                    uint32_t hi, lo; split_tf32(v[c], hi, lo);
                    sm[X_AH(nb) + (kl + c) * XA_PAD + rowA] = hi;
                    sm[X_AL(nb) + (kl + c) * XA_PAD + rowA] = lo;
                }
            }
#pragma unroll
            for (int j = 0; j < 2; j++) {
                int f4id = tid + j * 256;
                int kl = f4id >> 4, b4 = f4id & 15;
                const float* v = (const float*)&bv[j];
#pragma unroll
                for (int c = 0; c < 4; c++) {
                    uint32_t hi, lo; split_tf32(v[c], hi, lo);
                    sm[X_BH(nb) + kl * XB_PAD + b4 * 4 + c] = hi;
                    sm[X_BL(nb) + kl * XB_PAD + b4 * 4 + c] = lo;
                }
            }
        }
        __syncthreads();
    }

    // ---- fused epilogue: relu tile -> smem, then cls -> g_unary
    float* sIf = (float*)sm;
    float* sWc = (float*)(sm + XW_OFF);
    {
        const int gr0 = wid * 16 + r;
        const int gr1 = gr0 + 8;
        const float bv0 = bias[gr0];
        const float bv1 = bias[gr1];
#pragma unroll
        for (int nt = 0; nt < 8; nt++) {
            const int col = nt * 8 + 2 * cidx;
            sIf[gr0 * XI_PITCH + col]     = fmaxf(acc[nt][0] + bv0, 0.f);
            sIf[gr0 * XI_PITCH + col + 1] = fmaxf(acc[nt][1] + bv0, 0.f);
            sIf[gr1 * XI_PITCH + col]     = fmaxf(acc[nt][2] + bv1, 0.f);
            sIf[gr1 * XI_PITCH + col + 1] = fmaxf(acc[nt][3] + bv1, 0.f);
        }
    }
    for (int i = tid; i < NL * INTER_; i += 256) sWc[i] = clsW[i];
    __syncthreads();

    const int b  = tid & 63;
    const int lg = tid >> 6;
    for (int l = lg; l < NL; l += 4) {
        float a = clsb[l];
        const float* wr = sWc + l * INTER_;
#pragma unroll 8
        for (int n = 0; n < INTER_; n++) a += wr[n] * sIf[n * XI_PITCH + b];
        g_unary[((size_t)b * T_ + t) * TL + l] = a;
    }
    if (tid < 128) {
        int bb = tid & 63;
        int l  = NL + (tid >> 6);
        g_unary[((size_t)bb * T_ + t) * TL + l] = LOW_POT;
    }
}

// ---------------- Viterbi + backtrace (one block per batch element) ---------
__global__ void viterbi_kernel(const float* __restrict__ trans, float* __restrict__ out,
                               int score_off, int label_off) {
    __shared__ float tr[TL * TL];
    __shared__ float s0[TL], s1[TL];
    __shared__ unsigned char bp[T_][TL];
    const int b = blockIdx.x;
    const int tid = threadIdx.x;

    for (int i = tid; i < TL * TL; i += 32) tr[i] = trans[i];
    if (tid < TL) s0[tid] = (tid == START_L) ? 0.f : LOW_POT;
    __syncthreads();

    const float* ub = g_unary + (size_t)b * T_ * TL;
    float* sc = s0;
    float* sn = s1;
    for (int t = 0; t < T_; t++) {
        if (tid < TL) {
            float best = sc[0] + tr[tid * TL + 0];
            int bpi = 0;
#pragma unroll
            for (int p = 1; p < TL; p++) {
                float v = sc[p] + tr[tid * TL + p];
                if (v > best) { best = v; bpi = p; }
            }
            sn[tid] = best + ub[t * TL + tid];
            bp[t][tid] = (unsigned char)bpi;
        }
        __syncthreads();
        float* tmp = sc; sc = sn; sn = tmp;
    }
    if (tid == 0) {
        float best = sc[0] + tr[END_L * TL + 0];
        int li = 0;
        for (int l = 1; l < TL; l++) {
            float v = sc[l] + tr[END_L * TL + l];
            if (v > best) { best = v; li = l; }
        }
        if (score_off >= 0) out[score_off + b] = best;
        if (label_off >= 0) {
            int cur = li;
            for (int t = T_ - 1; t >= 0; t--) {
                out[label_off + (size_t)b * T_ + t] = (float)cur;
                cur = bp[t][cur];
            }
        }
    }
}

// ---------------- launch -----------------------------------------------------
extern "C" void kernel_launch(void* const* d_in, const int* in_sizes, int n_in,
                              void* d_out, int out_size) {
    const int*   x       = (const int*)d_in[0];
    const float* emb     = (const float*)d_in[1];
    const float* W_ih_f  = (const float*)d_in[2];
    const float* W_hh_f  = (const float*)d_in[3];
    const float* b_f     = (const float*)d_in[4];
    const float* W_ih_b  = (const float*)d_in[5];
    const float* W_hh_b  = (const float*)d_in[6];
    const float* b_b     = (const float*)d_in[7];
    const float* fc1_W   = (const float*)d_in[8];
    const float* fc1_b   = (const float*)d_in[9];
    const float* cls_W   = (const float*)d_in[10];
    const float* cls_b   = (const float*)d_in[11];
    const float* trans   = (const float*)d_in[12];
    float* out = (float*)d_out;

    int score_off = 0, label_off = B_;
    if (out_size == B_ * T_)      { score_off = -1; label_off = 0; }
    else if (out_size == B_)      { label_off = -1; }

    cudaFuncSetAttribute(lstm_kernel, cudaFuncAttributeMaxDynamicSharedMemorySize, L_SMEM_BYTES);
    cudaFuncSetAttribute(xproj_kernel, cudaFuncAttributeMaxDynamicSharedMemorySize, XP_SMEM_BYTES);
    cudaFuncSetAttribute(fc1_kernel, cudaFuncAttributeMaxDynamicSharedMemorySize, X_SMEM_BYTES);

    zero_bar_kernel<<<64, 256>>>();
    prep_whh_kernel<<<1024, 256>>>(W_hh_f, W_hh_b);
    xproj_kernel<<<dim3(8, T_, 2), 256, XP_SMEM_BYTES>>>(x, emb, W_ih_f, b_f, W_ih_b, b_b);
    lstm_kernel<<<64, 256, L_SMEM_BYTES>>>();
    fc1_kernel<<<T_, 256, X_SMEM_BYTES>>>(fc1_W, fc1_b, cls_W, cls_b);
    viterbi_kernel<<<B_, 32>>>(trans, out, score_off, label_off);
}

// round 13
// speedup vs baseline: 1.2075x; 1.0330x over previous
#include <cuda_runtime.h>
#include <cuda_bf16.h>
#include <cuda_fp16.h>
#include <math.h>
#include <stdint.h>

// Problem constants
#define B_   64
#define T_   256
#define E_   300
#define H_   256
#define G4H  1024      // 4*H
#define INTER_ 128
#define NL   17
#define TL   19        // NUM_LABELS + 2
#define START_L 17
#define END_L   18
#define LOW_POT (-10000.0f)

#define N_LSTM_BLK 64
#define N_WORKERS  168
#define N_ITEMS    4096      // 512 slices x 8 n-tiles

// ---------------- scratch (device globals; no allocations allowed) ----------
__device__ float g_xproj[(size_t)2 * T_ * G4H * B_];   // [dir][t][n(1024)][b]
__device__ float g_h[(size_t)2 * T_ * H_ * B_];        // [dir][t][k][b]
__device__ float g_unary[(size_t)B_ * T_ * TL];        // [b][t][l]
__device__ int   g_flags[4 * T_ * 16];                 // per-(grp,step,producer) flags
__device__ int   g_xslice[512];                        // per-slice tile counters (8 = ready)

// W_hh in f16 mma-fragment order: [dir][hc(16)][q(4)][kt(16)][lane(32)][reg(4)]
__device__ uint32_t g_wfrag16_hi[2 * 16 * 4 * 16 * 32 * 4];
__device__ uint32_t g_wfrag16_lo[2 * 16 * 4 * 16 * 32 * 4];
// h in f16 mma B-fragment order: [grp(4)][par(2)][kt(16)][nt(4)][lane(32)][reg(2)]
__device__ uint32_t g_hfrag16_hi[4 * 2 * 16 * 4 * 32 * 2];
__device__ uint32_t g_hfrag16_lo[4 * 2 * 16 * 4 * 32 * 2];

// ---------------- helpers ----------------------------------------------------
__device__ __forceinline__ uint32_t f2tf32(float x) {
    uint32_t r;
    asm("cvt.rna.tf32.f32 %0, %1;" : "=r"(r) : "f"(x));
    return r;
}
__device__ __forceinline__ void split_tf32(float x, uint32_t& hi, uint32_t& lo) {
    hi = f2tf32(x);
    lo = f2tf32(x - __uint_as_float(hi));
}
__device__ __forceinline__ void mma_tf32(float* d, const uint32_t* a, uint32_t b0, uint32_t b1) {
    asm volatile(
        "mma.sync.aligned.m16n8k8.row.col.f32.tf32.tf32.f32 "
        "{%0,%1,%2,%3}, {%4,%5,%6,%7}, {%8,%9}, {%0,%1,%2,%3};"
        : "+f"(d[0]), "+f"(d[1]), "+f"(d[2]), "+f"(d[3])
        : "r"(a[0]), "r"(a[1]), "r"(a[2]), "r"(a[3]), "r"(b0), "r"(b1));
}
__device__ __forceinline__ void mma_f16(float* d, const uint32_t* a, uint32_t b0, uint32_t b1) {
    asm volatile(
        "mma.sync.aligned.m16n8k16.row.col.f32.f16.f16.f32 "
        "{%0,%1,%2,%3}, {%4,%5,%6,%7}, {%8,%9}, {%0,%1,%2,%3};"
        : "+f"(d[0]), "+f"(d[1]), "+f"(d[2]), "+f"(d[3])
        : "r"(a[0]), "r"(a[1]), "r"(a[2]), "r"(a[3]), "r"(b0), "r"(b1));
}
__device__ __forceinline__ void split_pack_f16(float x0, float x1, uint32_t& hi, uint32_t& lo) {
    __half h0 = __float2half_rn(x0);
    __half h1 = __float2half_rn(x1);
    __half l0 = __float2half_rn(x0 - __half2float(h0));
    __half l1 = __float2half_rn(x1 - __half2float(h1));
    hi = (uint32_t)__half_as_ushort(h0) | ((uint32_t)__half_as_ushort(h1) << 16);
    lo = (uint32_t)__half_as_ushort(l0) | ((uint32_t)__half_as_ushort(l1) << 16);
}
__device__ __forceinline__ void split_f16_u16(float x, uint16_t& hi, uint16_t& lo) {
    __half h = __float2half_rn(x);
    __half l = __float2half_rn(x - __half2float(h));
    hi = __half_as_ushort(h);
    lo = __half_as_ushort(l);
}

// fast activations (~1e-7 rel err, clamped)
__device__ __forceinline__ float sigf(float x) {
    x = fmaxf(fminf(x, 30.f), -30.f);
    return __fdividef(1.f, 1.f + __expf(-x));
}
__device__ __forceinline__ float tanhf_fast(float x) {
    x = fmaxf(fminf(x, 15.f), -15.f);
    float e = __expf(2.f * x);
    return __fdividef(e - 1.f, e + 1.f);
}

// ---------------- flag zeroing (graph-replay determinism) -------------------
__global__ void zero_bar_kernel() {
    int i = blockIdx.x * 256 + threadIdx.x;
    if (i < 4 * T_ * 16) g_flags[i] = 0;
    if (i < 512) g_xslice[i] = 0;
}

// ---------------- W_hh f16 fragment prep ------------------------------------
__global__ void prep_whh_kernel(const float* __restrict__ Whf,
                                const float* __restrict__ Whb) {
    int idx = blockIdx.x * 256 + threadIdx.x;
    if (idx >= 2 * 16 * 4 * 16 * 32 * 4) return;
    int reg  = idx & 3;
    int lane = (idx >> 2) & 31;
    int kt   = (idx >> 7) & 15;
    int q    = (idx >> 11) & 3;
    int hc   = (idx >> 13) & 15;
    int dir  = (idx >> 17) & 1;
    const float* W = dir ? Whb : Whf;
    int i  = (lane >> 2) + 8 * (reg & 1);
    int g  = q * 256 + hc * 16 + i;
    int k0 = kt * 16 + (lane & 3) * 2 + 8 * (reg >> 1);
    float v0 = W[(size_t)g * H_ + k0];
    float v1 = W[(size_t)g * H_ + k0 + 1];
    uint32_t hi, lo;
    split_pack_f16(v0, v1, hi, lo);
    g_wfrag16_hi[idx] = hi;
    g_wfrag16_lo[idx] = lo;
}

// ---------------- smem layouts ------------------------------------------------
// xproj worker area (61.7KB, fits inside LSTM's 107KB allocation)
#define XP_PAD 20
#define XP_A_SZ (128 * XP_PAD)
#define XP_B_SZ (64 * XP_PAD)
#define XP_AH(b) ((b) * XP_A_SZ)
#define XP_AL(b) (2 * XP_A_SZ + (b) * XP_A_SZ)
#define XP_BH(b) (4 * XP_A_SZ + (b) * XP_B_SZ)
#define XP_BL(b) (4 * XP_A_SZ + 2 * XP_B_SZ + (b) * XP_B_SZ)
#define XP_TOK   (4 * XP_A_SZ + 4 * XP_B_SZ)

// LSTM area
#define L_AHI 0
#define L_ALO 8192
#define L_BHI 16384
#define L_BLO 20480
#define L_GEX 24576
#define L_SMEM_BYTES ((24576 + 4 * 16 * 33) * 4)   // 106752

// =============================================================================
// xproj worker (device fn): fp16x3 m16n8k16, item queue, per-slice signaling.
// item -> slice s = item>>3 (dir = s&1, kk = s>>1, t = dir ? 255-kk : kk), ntile.
// =============================================================================
__device__ void xproj_worker(uint32_t* sm, int wkr,
                             const int* __restrict__ x,
                             const float* __restrict__ emb,
                             const float* __restrict__ Wf, const float* __restrict__ bf,
                             const float* __restrict__ Wb, const float* __restrict__ bb) {
    const int tid = threadIdx.x;
    const int rowA = tid & 127;
    const int kqA  = tid >> 7;
    const int rowB = tid & 63;
    const int kqB  = tid >> 6;
    const int wid  = tid >> 5;
    const int lane = tid & 31;
    const int r    = lane >> 2;
    const int cidx = lane & 3;
    const int row0 = wid * 16 + r;
    int* tok = (int*)(sm + XP_TOK);

    for (int item = wkr; item < N_ITEMS; item += N_WORKERS) {
        const int s_  = item >> 3;
        const int n0  = (item & 7) * 128;
        const int dir = s_ & 1;
        const int kk  = s_ >> 1;
        const int t   = dir ? (T_ - 1 - kk) : kk;
        const float* W    = dir ? Wb : Wf;
        const float* bias = dir ? bb : bf;

        if (tid < 64) tok[tid] = x[tid * T_ + t];
        __syncthreads();

        const float* Arow = W + (size_t)(n0 + rowA) * E_;
        const float* Brow = emb + (size_t)tok[rowB] * E_;

        float acc[8][4];
#pragma unroll
        for (int i = 0; i < 8; i++)
#pragma unroll
            for (int j = 0; j < 4; j++) acc[i][j] = 0.f;

        float4 av[4];
        float4 bv[2];

#pragma unroll
        for (int j = 0; j < 4; j++) {
            int gk4 = kqA * 4 + j;
            av[j] = (gk4 < 75) ? *(const float4*)(Arow + gk4 * 4) : make_float4(0, 0, 0, 0);
        }
#pragma unroll
        for (int j = 0; j < 2; j++) {
            int gk4 = kqB * 2 + j;
            bv[j] = (gk4 < 75) ? *(const float4*)(Brow + gk4 * 4) : make_float4(0, 0, 0, 0);
        }
#pragma unroll
        for (int j = 0; j < 4; j++) {
            int k2b = kqA * 8 + j * 2;
            uint32_t h0, l0, h1, l1;
            split_pack_f16(av[j].x, av[j].y, h0, l0);
            split_pack_f16(av[j].z, av[j].w, h1, l1);
            sm[XP_AH(0) + rowA * XP_PAD + k2b]     = h0;
            sm[XP_AH(0) + rowA * XP_PAD + k2b + 1] = h1;
            sm[XP_AL(0) + rowA * XP_PAD + k2b]     = l0;
            sm[XP_AL(0) + rowA * XP_PAD + k2b + 1] = l1;
        }
#pragma unroll
        for (int j = 0; j < 2; j++) {
            int k2b = kqB * 4 + j * 2;
            uint32_t h0, l0, h1, l1;
            split_pack_f16(bv[j].x, bv[j].y, h0, l0);
            split_pack_f16(bv[j].z, bv[j].w, h1, l1);
            sm[XP_BH(0) + rowB * XP_PAD + k2b]     = h0;
            sm[XP_BH(0) + rowB * XP_PAD + k2b + 1] = h1;
            sm[XP_BL(0) + rowB * XP_PAD + k2b]     = l0;
            sm[XP_BL(0) + rowB * XP_PAD + k2b + 1] = l1;
        }
        __syncthreads();

        for (int kc = 0; kc < 10; kc++) {
            const int buf = kc & 1;
            if (kc < 9) {
#pragma unroll
                for (int j = 0; j < 4; j++) {
                    int gk4 = (kc + 1) * 8 + kqA * 4 + j;
                    av[j] = (gk4 < 75) ? *(const float4*)(Arow + gk4 * 4) : make_float4(0, 0, 0, 0);
                }
#pragma unroll
                for (int j = 0; j < 2; j++) {
                    int gk4 = (kc + 1) * 8 + kqB * 2 + j;
                    bv[j] = (gk4 < 75) ? *(const float4*)(Brow + gk4 * 4) : make_float4(0, 0, 0, 0);
                }
            }
            const uint32_t* AHp = sm + XP_AH(buf);
            const uint32_t* ALp = sm + XP_AL(buf);
            const uint32_t* BHp = sm + XP_BH(buf);
            const uint32_t* BLp = sm + XP_BL(buf);
#pragma unroll
            for (int s2 = 0; s2 < 2; s2++) {
                const int k2b = s2 * 8 + cidx;
                uint32_t ah[4], al[4];
                ah[0] = AHp[row0 * XP_PAD + k2b];
                ah[1] = AHp[(row0 + 8) * XP_PAD + k2b];
                ah[2] = AHp[row0 * XP_PAD + k2b + 4];
                ah[3] = AHp[(row0 + 8) * XP_PAD + k2b + 4];
                al[0] = ALp[row0 * XP_PAD + k2b];
                al[1] = ALp[(row0 + 8) * XP_PAD + k2b];
                al[2] = ALp[row0 * XP_PAD + k2b + 4];
                al[3] = ALp[(row0 + 8) * XP_PAD + k2b + 4];
#pragma unroll
                for (int nt = 0; nt < 8; nt++) {
                    const int col = nt * 8 + r;
                    uint32_t bh0 = BHp[col * XP_PAD + k2b];
                    uint32_t bh1 = BHp[col * XP_PAD + k2b + 4];
                    uint32_t bl0 = BLp[col * XP_PAD + k2b];
                    uint32_t bl1 = BLp[col * XP_PAD + k2b + 4];
                    mma_f16(acc[nt], ah, bh0, bh1);
                    mma_f16(acc[nt], al, bh0, bh1);
                    mma_f16(acc[nt], ah, bl0, bl1);
                }
            }
            if (kc < 9) {
                const int nb = (kc + 1) & 1;
#pragma unroll
                for (int j = 0; j < 4; j++) {
                    int k2b = kqA * 8 + j * 2;
                    uint32_t h0, l0, h1, l1;
                    split_pack_f16(av[j].x, av[j].y, h0, l0);
                    split_pack_f16(av[j].z, av[j].w, h1, l1);
                    sm[XP_AH(nb) + rowA * XP_PAD + k2b]     = h0;
                    sm[XP_AH(nb) + rowA * XP_PAD + k2b + 1] = h1;
                    sm[XP_AL(nb) + rowA * XP_PAD + k2b]     = l0;
                    sm[XP_AL(nb) + rowA * XP_PAD + k2b + 1] = l1;
                }
#pragma unroll
                for (int j = 0; j < 2; j++) {
                    int k2b = kqB * 4 + j * 2;
                    uint32_t h0, l0, h1, l1;
                    split_pack_f16(bv[j].x, bv[j].y, h0, l0);
                    split_pack_f16(bv[j].z, bv[j].w, h1, l1);
                    sm[XP_BH(nb) + rowB * XP_PAD + k2b]     = h0;
                    sm[XP_BH(nb) + rowB * XP_PAD + k2b + 1] = h1;
                    sm[XP_BL(nb) + rowB * XP_PAD + k2b]     = l0;
                    sm[XP_BL(nb) + rowB * XP_PAD + k2b + 1] = l1;
                }
            }
            __syncthreads();
        }

        // epilogue: +bias, write [dir][t][n][b], then signal slice
        const int gr0 = n0 + wid * 16 + r;
        const int gr1 = gr0 + 8;
        const float bv0 = bias[gr0];
        const float bv1 = bias[gr1];
        float* outb = g_xproj + ((size_t)(dir * T_ + t)) * (G4H * B_);
#pragma unroll
        for (int nt = 0; nt < 8; nt++) {
            const int col = nt * 8 + 2 * cidx;
            float2 o0 = make_float2(acc[nt][0] + bv0, acc[nt][1] + bv0);
            float2 o1 = make_float2(acc[nt][2] + bv1, acc[nt][3] + bv1);
            *(float2*)(outb + (size_t)gr0 * B_ + col) = o0;
            *(float2*)(outb + (size_t)gr1 * B_ + col) = o1;
        }
        __threadfence();
        __syncthreads();
        if (tid == 0) atomicAdd(&g_xslice[s_], 1);
    }
}

// =============================================================================
// LSTM chain block (device fn) — r12 exact structure + slice-wait per step.
// 64 blocks = dir(2) x bg(2, 32 batches) x hc(16, 16 hidden units).
// =============================================================================
__device__ void lstm_block(uint32_t* s, int bx) {
    uint32_t* Ahi = s + L_AHI;
    uint32_t* Alo = s + L_ALO;
    uint32_t* Bhi = s + L_BHI;
    uint32_t* Blo = s + L_BLO;
    float*    gex = (float*)(s + L_GEX);

    const int tid = threadIdx.x;
    const int dir = bx >> 5;
    const int bg  = (bx >> 4) & 1;
    const int hc  = bx & 15;
    const int grp = dir * 2 + bg;

    // ---- load this block's f16 A fragments (weights) into smem
    {
        const uint4* srcH = (const uint4*)(g_wfrag16_hi + ((size_t)(dir * 16 + hc)) * 8192);
        const uint4* srcL = (const uint4*)(g_wfrag16_lo + ((size_t)(dir * 16 + hc)) * 8192);
        uint4* dH = (uint4*)Ahi;
        uint4* dL = (uint4*)Alo;
#pragma unroll
        for (int j = 0; j < 8; j++) {
            dH[tid + j * 256] = srcH[tid + j * 256];
            dL[tid + j * 256] = srcL[tid + j * 256];
        }
    }

    const int w    = tid >> 5;
    const int lane = tid & 31;
    const int q    = w & 3;
    const int nt0  = (w >> 2) * 2;

    const int ci = (2 * tid) >> 5;     // 0..15
    const int cb = (2 * tid) & 31;     // even
    float cst0 = 0.f, cst1 = 0.f;

    // h fragment store coords (producer side), k = hc*16+ci
    const int kin   = ci;
    const int s_reg = kin >> 3;
    const int s_tig = (kin >> 1) & 3;
    const int s_half = kin & 1;

    __syncthreads();

    for (int st = 0; st < T_; st++) {
        const int t = dir ? (T_ - 1 - st) : st;

        // wait for xproj slice (produced by concurrent workers)
        {
            const int* cp = g_xslice + (st * 2 + dir);
            int v;
            for (;;) {
                asm volatile("ld.acquire.gpu.global.b32 %0, [%1];"
                             : "=r"(v) : "l"(cp) : "memory");
                if (v >= 8) break;
                __nanosleep(60);
            }
        }

        // prefetch xproj gate pre-activations
        float2 xpv[4];
        {
            const float* xb = g_xproj + ((size_t)(dir * T_ + t)) * (G4H * B_)
                              + (size_t)(hc * 16 + ci) * B_ + bg * 32 + cb;
#pragma unroll
            for (int qq = 0; qq < 4; qq++)
                xpv[qq] = *(const float2*)(xb + (size_t)qq * (H_ * B_));
        }

        float ga[4][2];
#pragma unroll
        for (int qq = 0; qq < 4; qq++) { ga[qq][0] = xpv[qq].x; ga[qq][1] = xpv[qq].y; }

        if (st > 0) {
            // wait for all 16 producers of step st-1 (one flag line, acquire + backoff)
            if (tid < 16) {
                const int* fp = g_flags + ((grp * T_ + (st - 1)) << 4) + tid;
                int v;
                for (;;) {
                    asm volatile("ld.acquire.gpu.global.b32 %0, [%1];"
                                 : "=r"(v) : "l"(fp) : "memory");
                    if (__all_sync(0x0000FFFFu, v != 0)) break;
                    __nanosleep(30);
                }
            }
            __syncthreads();

            // copy h fragments (parity of step st-1) global -> smem
            {
                const size_t hb = ((size_t)grp * 2 + ((st - 1) & 1)) * 4096;
                const uint4* sH = (const uint4*)(g_hfrag16_hi + hb);
                const uint4* sL = (const uint4*)(g_hfrag16_lo + hb);
                uint4* dH = (uint4*)Bhi;
                uint4* dL = (uint4*)Blo;
#pragma unroll
                for (int j = 0; j < 4; j++) {
                    dH[tid + j * 256] = __ldcg(sH + tid + j * 256);
                    dL[tid + j * 256] = __ldcg(sL + tid + j * 256);
                }
            }
            __syncthreads();

            float acc[2][4];
#pragma unroll
            for (int e = 0; e < 2; e++)
#pragma unroll
                for (int j = 0; j < 4; j++) acc[e][j] = 0.f;

            const uint32_t* Aq_hi = Ahi + q * 2048;
            const uint32_t* Aq_lo = Alo + q * 2048;
#pragma unroll 8
            for (int kt = 0; kt < 16; kt++) {
                uint4 ahv = *(const uint4*)(Aq_hi + (kt * 32 + lane) * 4);
                uint4 alv = *(const uint4*)(Aq_lo + (kt * 32 + lane) * 4);
                const uint32_t* ah = (const uint32_t*)&ahv;
                const uint32_t* al = (const uint32_t*)&alv;
#pragma unroll
                for (int e = 0; e < 2; e++) {
                    const int nt = nt0 + e;
                    uint2 bh = *(const uint2*)(Bhi + ((kt * 4 + nt) * 32 + lane) * 2);
                    uint2 bl = *(const uint2*)(Blo + ((kt * 4 + nt) * 32 + lane) * 2);
                    mma_f16(acc[e], ah, bh.x, bh.y);
                    mma_f16(acc[e], al, bh.x, bh.y);
                    mma_f16(acc[e], ah, bl.x, bl.y);
                }
            }
            {
                const int i_lo = lane >> 2;
                const int colb = (lane & 3) * 2;
#pragma unroll
                for (int e = 0; e < 2; e++) {
                    const int col = (nt0 + e) * 8 + colb;
                    gex[(q * 16 + i_lo) * 33 + col]     = acc[e][0];
                    gex[(q * 16 + i_lo) * 33 + col + 1] = acc[e][1];
                    gex[(q * 16 + i_lo + 8) * 33 + col]     = acc[e][2];
                    gex[(q * 16 + i_lo + 8) * 33 + col + 1] = acc[e][3];
                }
            }
            __syncthreads();

#pragma unroll
            for (int qq = 0; qq < 4; qq++) {
                ga[qq][0] += gex[(qq * 16 + ci) * 33 + cb];
                ga[qq][1] += gex[(qq * 16 + ci) * 33 + cb + 1];
            }
        }

        float h0, h1;
        {
            float ig = sigf(ga[0][0]);
            float fg = sigf(ga[1][0]);
            float gg = tanhf_fast(ga[2][0]);
            float og = sigf(ga[3][0]);
            cst0 = fg * cst0 + ig * gg;
            h0 = og * tanhf_fast(cst0);
        }
        {
            float ig = sigf(ga[0][1]);
            float fg = sigf(ga[1][1]);
            float gg = tanhf_fast(ga[2][1]);
            float og = sigf(ga[3][1]);
            cst1 = fg * cst1 + ig * gg;
            h1 = og * tanhf_fast(cst1);
        }

        // write h (fp32 for fc1) and f16 hi/lo fragment halves (parity st&1)
        {
            const int k = hc * 16 + ci;
            *(float2*)(g_h + (((size_t)(dir * T_ + t)) * H_ + k) * B_ + bg * 32 + cb)
                = make_float2(h0, h1);

            const size_t hb = ((size_t)grp * 2 + (st & 1)) * 4096;
            uint16_t* HHi = (uint16_t*)g_hfrag16_hi;
            uint16_t* HLo = (uint16_t*)g_hfrag16_lo;
            uint16_t fhi, flo;
            // cell 0: n = cb
            {
                const int nt = cb >> 3;
                const int laneb = (cb & 7) * 4 + s_tig;
                const size_t word = hb + (((size_t)hc * 4 + nt) * 32 + laneb) * 2 + s_reg;
                split_f16_u16(h0, fhi, flo);
                HHi[word * 2 + s_half] = fhi;
                HLo[word * 2 + s_half] = flo;
            }
            // cell 1: n = cb+1
            {
                const int b1 = cb + 1;
                const int nt = b1 >> 3;
                const int laneb = (b1 & 7) * 4 + s_tig;
                const size_t word = hb + (((size_t)hc * 4 + nt) * 32 + laneb) * 2 + s_reg;
                split_f16_u16(h1, fhi, flo);
                HHi[word * 2 + s_half] = fhi;
                HLo[word * 2 + s_half] = flo;
            }
        }
        __syncthreads();
        if (tid == 0) {
            __threadfence();
            int* fp = g_flags + ((grp * T_ + st) << 4) + hc;
            asm volatile("st.release.gpu.global.b32 [%0], %1;" :: "l"(fp), "r"(1) : "memory");
        }
    }
}

// =============================================================================
// fused kernel: blocks 0..63 = LSTM chains, 64..231 = xproj workers.
// Uniform 107KB dynamic smem -> 2 blocks/SM -> all 232 blocks wave-1 resident.
// =============================================================================
__global__ void __launch_bounds__(256, 2)
fused_kernel(const int* __restrict__ x,
             const float* __restrict__ emb,
             const float* __restrict__ Wf, const float* __restrict__ bf,
             const float* __restrict__ Wb, const float* __restrict__ bb) {
    extern __shared__ uint32_t s[];
    const int bx = blockIdx.x;
    if (bx < N_LSTM_BLK) {
        lstm_block(s, bx);
    } else {
        xproj_worker(s, bx - N_LSTM_BLK, x, emb, Wf, bf, Wb, bb);
    }
}

// =============================================================================
// fc1 (3xTF32) + fused cls — r12 proven; unchanged
// =============================================================================
#define XA_PAD 136
#define XB_PAD 72
#define XA_SZ  (32 * XA_PAD)
#define XB_SZ  (32 * XB_PAD)
#define X_AH(buf) ((buf) * XA_SZ)
#define X_AL(buf) (2 * XA_SZ + (buf) * XA_SZ)
#define X_BH(buf) (4 * XA_SZ + (buf) * XB_SZ)
#define X_BL(buf) (4 * XA_SZ + 2 * XB_SZ + (buf) * XB_SZ)
#define X_SMEM_BYTES ((4 * XA_SZ + 4 * XB_SZ + 64) * 4)
#define XI_PITCH 65
#define XW_OFF   (128 * XI_PITCH)

__global__ void __launch_bounds__(256, 2)
fc1_kernel(const float* __restrict__ W, const float* __restrict__ bias,
           const float* __restrict__ clsW, const float* __restrict__ clsb) {
    extern __shared__ uint32_t sm[];
    const int tid = threadIdx.x;
    const int t   = blockIdx.x;

    const int rowA = tid & 127;
    const int kqA  = tid >> 7;
    const float* Arow = W + (size_t)rowA * 512;

    const int wid  = tid >> 5;
    const int lane = tid & 31;
    const int r    = lane >> 2;
    const int cidx = lane & 3;

    float acc[8][4];
#pragma unroll
    for (int i = 0; i < 8; i++)
#pragma unroll
        for (int j = 0; j < 4; j++) acc[i][j] = 0.f;

    float4 av[4];
    float4 bv[2];

#pragma unroll
    for (int j = 0; j < 4; j++) {
        int gk4 = kqA + 2 * j;
        av[j] = *(const float4*)(Arow + gk4 * 4);
    }
#pragma unroll
    for (int j = 0; j < 2; j++) {
        int f4id = tid + j * 256;
        int kl = f4id >> 4, b4 = f4id & 15;
        int kgl = kl;
        int d = kgl >> 8, kh = kgl & 255;
        bv[j] = *(const float4*)(g_h + ((size_t)(d * T_ + t) * 256 + kh) * 64 + b4 * 4);
    }
#pragma unroll
    for (int j = 0; j < 4; j++) {
        int kl = (kqA + 2 * j) * 4;
        const float* v = (const float*)&av[j];
#pragma unroll
        for (int c = 0; c < 4; c++) {
            uint32_t hi, lo; split_tf32(v[c], hi, lo);
            sm[X_AH(0) + (kl + c) * XA_PAD + rowA] = hi;
            sm[X_AL(0) + (kl + c) * XA_PAD + rowA] = lo;
        }
    }
#pragma unroll
    for (int j = 0; j < 2; j++) {
        int f4id = tid + j * 256;
        int kl = f4id >> 4, b4 = f4id & 15;
        const float* v = (const float*)&bv[j];
#pragma unroll
        for (int c = 0; c < 4; c++) {
            uint32_t hi, lo; split_tf32(v[c], hi, lo);
            sm[X_BH(0) + kl * XB_PAD + b4 * 4 + c] = hi;
            sm[X_BL(0) + kl * XB_PAD + b4 * 4 + c] = lo;
        }
    }
    __syncthreads();

    for (int kc = 0; kc < 16; kc++) {
        const int buf = kc & 1;
        if (kc < 15) {
#pragma unroll
            for (int j = 0; j < 4; j++) {
                int gk4 = (kc + 1) * 8 + kqA + 2 * j;
                av[j] = *(const float4*)(Arow + gk4 * 4);
            }
#pragma unroll
            for (int j = 0; j < 2; j++) {
                int f4id = tid + j * 256;
                int kl = f4id >> 4, b4 = f4id & 15;
                int kgl = (kc + 1) * 32 + kl;
                int d = kgl >> 8, kh = kgl & 255;
                bv[j] = *(const float4*)(g_h + ((size_t)(d * T_ + t) * 256 + kh) * 64 + b4 * 4);
            }
        }
        const uint32_t* AH = sm + X_AH(buf);
        const uint32_t* AL = sm + X_AL(buf);
        const uint32_t* BH = sm + X_BH(buf);
        const uint32_t* BL = sm + X_BL(buf);
        const int row0 = wid * 16 + r;
#pragma unroll
        for (int kk = 0; kk < 4; kk++) {
            const int base = kk * 8 + cidx;
            uint32_t ah[4], al[4];
            ah[0] = AH[base * XA_PAD + row0];
            ah[1] = AH[base * XA_PAD + row0 + 8];
            ah[2] = AH[(base + 4) * XA_PAD + row0];
            ah[3] = AH[(base + 4) * XA_PAD + row0 + 8];
            al[0] = AL[base * XA_PAD + row0];
            al[1] = AL[base * XA_PAD + row0 + 8];
            al[2] = AL[(base + 4) * XA_PAD + row0];
            al[3] = AL[(base + 4) * XA_PAD + row0 + 8];
#pragma unroll
            for (int nt = 0; nt < 8; nt++) {
                const int col = nt * 8 + r;
                uint32_t bh0 = BH[base * XB_PAD + col];
                uint32_t bh1 = BH[(base + 4) * XB_PAD + col];
                uint32_t bl0 = BL[base * XB_PAD + col];
                uint32_t bl1 = BL[(base + 4) * XB_PAD + col];
                mma_tf32(acc[nt], ah, bh0, bh1);
                mma_tf32(acc[nt], al, bh0, bh1);
                mma_tf32(acc[nt], ah, bl0, bl1);
            }
        }
        if (kc < 15) {
            const int nb = (kc + 1) & 1;
#pragma unroll
            for (int j = 0; j < 4; j++) {
                int kl = (kqA + 2 * j) * 4;
                const float* v = (const float*)&av[j];
#pragma unroll
                for (int c = 0; c < 4; c++) {
                    uint32_t hi, lo; split_tf32(v[c], hi, lo);
                    sm[X_AH(nb) + (kl + c) * XA_PAD + rowA] = hi;
                    sm[X_AL(nb) + (kl + c) * XA_PAD + rowA] = lo;
                }
            }
#pragma unroll
            for (int j = 0; j < 2; j++) {
                int f4id = tid + j * 256;
                int kl = f4id >> 4, b4 = f4id & 15;
                const float* v = (const float*)&bv[j];
#pragma unroll
                for (int c = 0; c < 4; c++) {
                    uint32_t hi, lo; split_tf32(v[c], hi, lo);
                    sm[X_BH(nb) + kl * XB_PAD + b4 * 4 + c] = hi;
                    sm[X_BL(nb) + kl * XB_PAD + b4 * 4 + c] = lo;
                }
            }
        }
        __syncthreads();
    }

    // ---- fused epilogue: relu tile -> smem, then cls -> g_unary
    float* sIf = (float*)sm;
    float* sWc = (float*)(sm + XW_OFF);
    {
        const int gr0 = wid * 16 + r;
        const int gr1 = gr0 + 8;
        const float bv0 = bias[gr0];
        const float bv1 = bias[gr1];
#pragma unroll
        for (int nt = 0; nt < 8; nt++) {
            const int col = nt * 8 + 2 * cidx;
            sIf[gr0 * XI_PITCH + col]     = fmaxf(acc[nt][0] + bv0, 0.f);
            sIf[gr0 * XI_PITCH + col + 1] = fmaxf(acc[nt][1] + bv0, 0.f);
            sIf[gr1 * XI_PITCH + col]     = fmaxf(acc[nt][2] + bv1, 0.f);
            sIf[gr1 * XI_PITCH + col + 1] = fmaxf(acc[nt][3] + bv1, 0.f);
        }
    }
    for (int i = tid; i < NL * INTER_; i += 256) sWc[i] = clsW[i];
    __syncthreads();

    const int b  = tid & 63;
    const int lg = tid >> 6;
    for (int l = lg; l < NL; l += 4) {
        float a = clsb[l];
        const float* wr = sWc + l * INTER_;
#pragma unroll 8
        for (int n = 0; n < INTER_; n++) a += wr[n] * sIf[n * XI_PITCH + b];
        g_unary[((size_t)b * T_ + t) * TL + l] = a;
    }
    if (tid < 128) {
        int bb = tid & 63;
        int l  = NL + (tid >> 6);
        g_unary[((size_t)bb * T_ + t) * TL + l] = LOW_POT;
    }
}

// ---------------- Viterbi + backtrace (one block per batch element) ---------
__global__ void viterbi_kernel(const float* __restrict__ trans, float* __restrict__ out,
                               int score_off, int label_off) {
    __shared__ float tr[TL * TL];
    __shared__ float s0[TL], s1[TL];
    __shared__ unsigned char bp[T_][TL];
    const int b = blockIdx.x;
    const int tid = threadIdx.x;

    for (int i = tid; i < TL * TL; i += 32) tr[i] = trans[i];
    if (tid < TL) s0[tid] = (tid == START_L) ? 0.f : LOW_POT;
    __syncthreads();

    const float* ub = g_unary + (size_t)b * T_ * TL;
    float* sc = s0;
    float* sn = s1;
    for (int t = 0; t < T_; t++) {
        if (tid < TL) {
            float best = sc[0] + tr[tid * TL + 0];
            int bpi = 0;
#pragma unroll
            for (int p = 1; p < TL; p++) {
                float v = sc[p] + tr[tid * TL + p];
                if (v > best) { best = v; bpi = p; }
            }
            sn[tid] = best + ub[t * TL + tid];
            bp[t][tid] = (unsigned char)bpi;
        }
        __syncthreads();
        float* tmp = sc; sc = sn; sn = tmp;
    }
    if (tid == 0) {
        float best = sc[0] + tr[END_L * TL + 0];
        int li = 0;
        for (int l = 1; l < TL; l++) {
            float v = sc[l] + tr[END_L * TL + l];
            if (v > best) { best = v; li = l; }
        }
        if (score_off >= 0) out[score_off + b] = best;
        if (label_off >= 0) {
            int cur = li;
            for (int t = T_ - 1; t >= 0; t--) {
                out[label_off + (size_t)b * T_ + t] = (float)cur;
                cur = bp[t][cur];
            }
        }
    }
}

// ---------------- launch -----------------------------------------------------
extern "C" void kernel_launch(void* const* d_in, const int* in_sizes, int n_in,
                              void* d_out, int out_size) {
    const int*   x       = (const int*)d_in[0];
    const float* emb     = (const float*)d_in[1];
    const float* W_ih_f  = (const float*)d_in[2];
    const float* W_hh_f  = (const float*)d_in[3];
    const float* b_f     = (const float*)d_in[4];
    const float* W_ih_b  = (const float*)d_in[5];
    const float* W_hh_b  = (const float*)d_in[6];
    const float* b_b     = (const float*)d_in[7];
    const float* fc1_W   = (const float*)d_in[8];
    const float* fc1_b   = (const float*)d_in[9];
    const float* cls_W   = (const float*)d_in[10];
    const float* cls_b   = (const float*)d_in[11];
    const float* trans   = (const float*)d_in[12];
    float* out = (float*)d_out;

    int score_off = 0, label_off = B_;
    if (out_size == B_ * T_)      { score_off = -1; label_off = 0; }
    else if (out_size == B_)      { label_off = -1; }

    cudaFuncSetAttribute(fused_kernel, cudaFuncAttributeMaxDynamicSharedMemorySize, L_SMEM_BYTES);
    cudaFuncSetAttribute(fc1_kernel, cudaFuncAttributeMaxDynamicSharedMemorySize, X_SMEM_BYTES);

    zero_bar_kernel<<<64, 256>>>();
    prep_whh_kernel<<<1024, 256>>>(W_hh_f, W_hh_b);
    fused_kernel<<<N_LSTM_BLK + N_WORKERS, 256, L_SMEM_BYTES>>>(x, emb, W_ih_f, b_f, W_ih_b, b_b);
    fc1_kernel<<<T_, 256, X_SMEM_BYTES>>>(fc1_W, fc1_b, cls_W, cls_b);
    viterbi_kernel<<<B_, 32>>>(trans, out, score_off, label_off);
}

// round 15
// speedup vs baseline: 1.3611x; 1.1271x over previous
#include <cuda_runtime.h>
#include <cuda_bf16.h>
#include <cuda_fp16.h>
#include <math.h>
#include <stdint.h>

// Problem constants
#define B_   64
#define T_   256
#define E_   300
#define H_   256
#define G4H  1024      // 4*H
#define INTER_ 128
#define NL   17
#define TL   19        // NUM_LABELS + 2
#define START_L 17
#define END_L   18
#define LOW_POT (-10000.0f)

#define N_LSTM_BLK 64
#define N_WORKERS  84
#define N_ITEMS    4096      // 512 slices x 8 n-tiles

// ---------------- scratch (device globals; no allocations allowed) ----------
__device__ float g_xproj[(size_t)2 * T_ * G4H * B_];   // [dir][t][n(1024)][b]
__device__ float g_h[(size_t)2 * T_ * H_ * B_];        // [dir][t][k][b]
__device__ float g_unary[(size_t)B_ * T_ * TL];        // [b][t][l]
__device__ int   g_flags[4 * T_ * 16];                 // per-(grp,step,producer) flags
__device__ int   g_xslice[512];                        // per-slice tile counters (8 = ready)

// W_hh in f16 mma-fragment order: [dir][hc(16)][q(4)][kt(16)][lane(32)][reg(4)]
__device__ uint32_t g_wfrag16_hi[2 * 16 * 4 * 16 * 32 * 4];
__device__ uint32_t g_wfrag16_lo[2 * 16 * 4 * 16 * 32 * 4];
// h in f16 mma B-fragment order: [grp(4)][par(2)][kt(16)][nt(4)][lane(32)][reg(2)]
__device__ uint32_t g_hfrag16_hi[4 * 2 * 16 * 4 * 32 * 2];
__device__ uint32_t g_hfrag16_lo[4 * 2 * 16 * 4 * 32 * 2];

// ---------------- helpers ----------------------------------------------------
__device__ __forceinline__ uint32_t f2tf32(float x) {
    uint32_t r;
    asm("cvt.rna.tf32.f32 %0, %1;" : "=r"(r) : "f"(x));
    return r;
}
__device__ __forceinline__ void split_tf32(float x, uint32_t& hi, uint32_t& lo) {
    hi = f2tf32(x);
    lo = f2tf32(x - __uint_as_float(hi));
}
__device__ __forceinline__ void mma_tf32(float* d, const uint32_t* a, uint32_t b0, uint32_t b1) {
    asm volatile(
        "mma.sync.aligned.m16n8k8.row.col.f32.tf32.tf32.f32 "
        "{%0,%1,%2,%3}, {%4,%5,%6,%7}, {%8,%9}, {%0,%1,%2,%3};"
        : "+f"(d[0]), "+f"(d[1]), "+f"(d[2]), "+f"(d[3])
        : "r"(a[0]), "r"(a[1]), "r"(a[2]), "r"(a[3]), "r"(b0), "r"(b1));
}
__device__ __forceinline__ void mma_f16(float* d, const uint32_t* a, uint32_t b0, uint32_t b1) {
    asm volatile(
        "mma.sync.aligned.m16n8k16.row.col.f32.f16.f16.f32 "
        "{%0,%1,%2,%3}, {%4,%5,%6,%7}, {%8,%9}, {%0,%1,%2,%3};"
        : "+f"(d[0]), "+f"(d[1]), "+f"(d[2]), "+f"(d[3])
        : "r"(a[0]), "r"(a[1]), "r"(a[2]), "r"(a[3]), "r"(b0), "r"(b1));
}
__device__ __forceinline__ void split_pack_f16(float x0, float x1, uint32_t& hi, uint32_t& lo) {
    __half h0 = __float2half_rn(x0);
    __half h1 = __float2half_rn(x1);
    __half l0 = __float2half_rn(x0 - __half2float(h0));
    __half l1 = __float2half_rn(x1 - __half2float(h1));
    hi = (uint32_t)__half_as_ushort(h0) | ((uint32_t)__half_as_ushort(h1) << 16);
    lo = (uint32_t)__half_as_ushort(l0) | ((uint32_t)__half_as_ushort(l1) << 16);
}
__device__ __forceinline__ void split_f16_u16(float x, uint16_t& hi, uint16_t& lo) {
    __half h = __float2half_rn(x);
    __half l = __float2half_rn(x - __half2float(h));
    hi = __half_as_ushort(h);
    lo = __half_as_ushort(l);
}

// fast activations (~1e-7 rel err, clamped)
__device__ __forceinline__ float sigf(float x) {
    x = fmaxf(fminf(x, 30.f), -30.f);
    return __fdividef(1.f, 1.f + __expf(-x));
}
__device__ __forceinline__ float tanhf_fast(float x) {
    x = fmaxf(fminf(x, 15.f), -15.f);
    float e = __expf(2.f * x);
    return __fdividef(e - 1.f, e + 1.f);
}

// ---------------- flag zeroing (graph-replay determinism) -------------------
__global__ void zero_bar_kernel() {
    int i = blockIdx.x * 256 + threadIdx.x;
    if (i < 4 * T_ * 16) g_flags[i] = 0;
    if (i < 512) g_xslice[i] = 0;
}

// ---------------- W_hh f16 fragment prep ------------------------------------
__global__ void prep_whh_kernel(const float* __restrict__ Whf,
                                const float* __restrict__ Whb) {
    int idx = blockIdx.x * 256 + threadIdx.x;
    if (idx >= 2 * 16 * 4 * 16 * 32 * 4) return;
    int reg  = idx & 3;
    int lane = (idx >> 2) & 31;
    int kt   = (idx >> 7) & 15;
    int q    = (idx >> 11) & 3;
    int hc   = (idx >> 13) & 15;
    int dir  = (idx >> 17) & 1;
    const float* W = dir ? Whb : Whf;
    int i  = (lane >> 2) + 8 * (reg & 1);
    int g  = q * 256 + hc * 16 + i;
    int k0 = kt * 16 + (lane & 3) * 2 + 8 * (reg >> 1);
    float v0 = W[(size_t)g * H_ + k0];
    float v1 = W[(size_t)g * H_ + k0 + 1];
    uint32_t hi, lo;
    split_pack_f16(v0, v1, hi, lo);
    g_wfrag16_hi[idx] = hi;
    g_wfrag16_lo[idx] = lo;
}

// ---------------- smem layouts ------------------------------------------------
// xproj worker area (61.7KB, fits inside LSTM's 107KB allocation)
#define XP_PAD 20
#define XP_A_SZ (128 * XP_PAD)
#define XP_B_SZ (64 * XP_PAD)
#define XP_AH(b) ((b) * XP_A_SZ)
#define XP_AL(b) (2 * XP_A_SZ + (b) * XP_A_SZ)
#define XP_BH(b) (4 * XP_A_SZ + (b) * XP_B_SZ)
#define XP_BL(b) (4 * XP_A_SZ + 2 * XP_B_SZ + (b) * XP_B_SZ)
#define XP_TOK   (4 * XP_A_SZ + 4 * XP_B_SZ)

// LSTM area
#define L_AHI 0
#define L_ALO 8192
#define L_BHI 16384
#define L_BLO 20480
#define L_GEX 24576
#define L_SMEM_BYTES ((24576 + 4 * 16 * 33) * 4)   // 106752

// =============================================================================
// xproj worker (device fn): fp16x3 m16n8k16, item queue, per-slice signaling.
// item -> slice s = item>>3 (dir = s&1, kk = s>>1, t = dir ? 255-kk : kk), ntile.
// =============================================================================
__device__ void xproj_worker(uint32_t* sm, int wkr,
                             const int* __restrict__ x,
                             const float* __restrict__ emb,
                             const float* __restrict__ Wf, const float* __restrict__ bf,
                             const float* __restrict__ Wb, const float* __restrict__ bb) {
    const int tid = threadIdx.x;
    const int rowA = tid & 127;
    const int kqA  = tid >> 7;
    const int rowB = tid & 63;
    const int kqB  = tid >> 6;
    const int wid  = tid >> 5;
    const int lane = tid & 31;
    const int r    = lane >> 2;
    const int cidx = lane & 3;
    const int row0 = wid * 16 + r;
    int* tok = (int*)(sm + XP_TOK);

    for (int item = wkr; item < N_ITEMS; item += N_WORKERS) {
        const int s_  = item >> 3;
        const int n0  = (item & 7) * 128;
        const int dir = s_ & 1;
        const int kk  = s_ >> 1;
        const int t   = dir ? (T_ - 1 - kk) : kk;
        const float* W    = dir ? Wb : Wf;
        const float* bias = dir ? bb : bf;

        if (tid < 64) tok[tid] = x[tid * T_ + t];
        __syncthreads();

        const float* Arow = W + (size_t)(n0 + rowA) * E_;
        const float* Brow = emb + (size_t)tok[rowB] * E_;

        float acc[8][4];
#pragma unroll
        for (int i = 0; i < 8; i++)
#pragma unroll
            for (int j = 0; j < 4; j++) acc[i][j] = 0.f;

        float4 av[4];
        float4 bv[2];

#pragma unroll
        for (int j = 0; j < 4; j++) {
            int gk4 = kqA * 4 + j;
            av[j] = (gk4 < 75) ? *(const float4*)(Arow + gk4 * 4) : make_float4(0, 0, 0, 0);
        }
#pragma unroll
        for (int j = 0; j < 2; j++) {
            int gk4 = kqB * 2 + j;
            bv[j] = (gk4 < 75) ? *(const float4*)(Brow + gk4 * 4) : make_float4(0, 0, 0, 0);
        }
#pragma unroll
        for (int j = 0; j < 4; j++) {
            int k2b = kqA * 8 + j * 2;
            uint32_t h0, l0, h1, l1;
            split_pack_f16(av[j].x, av[j].y, h0, l0);
            split_pack_f16(av[j].z, av[j].w, h1, l1);
            sm[XP_AH(0) + rowA * XP_PAD + k2b]     = h0;
            sm[XP_AH(0) + rowA * XP_PAD + k2b + 1] = h1;
            sm[XP_AL(0) + rowA * XP_PAD + k2b]     = l0;
            sm[XP_AL(0) + rowA * XP_PAD + k2b + 1] = l1;
        }
#pragma unroll
        for (int j = 0; j < 2; j++) {
            int k2b = kqB * 4 + j * 2;
            uint32_t h0, l0, h1, l1;
            split_pack_f16(bv[j].x, bv[j].y, h0, l0);
            split_pack_f16(bv[j].z, bv[j].w, h1, l1);
            sm[XP_BH(0) + rowB * XP_PAD + k2b]     = h0;
            sm[XP_BH(0) + rowB * XP_PAD + k2b + 1] = h1;
            sm[XP_BL(0) + rowB * XP_PAD + k2b]     = l0;
            sm[XP_BL(0) + rowB * XP_PAD + k2b + 1] = l1;
        }
        __syncthreads();

        for (int kc = 0; kc < 10; kc++) {
            const int buf = kc & 1;
            if (kc < 9) {
#pragma unroll
                for (int j = 0; j < 4; j++) {
                    int gk4 = (kc + 1) * 8 + kqA * 4 + j;
                    av[j] = (gk4 < 75) ? *(const float4*)(Arow + gk4 * 4) : make_float4(0, 0, 0, 0);
                }
#pragma unroll
                for (int j = 0; j < 2; j++) {
                    int gk4 = (kc + 1) * 8 + kqB * 2 + j;
                    bv[j] = (gk4 < 75) ? *(const float4*)(Brow + gk4 * 4) : make_float4(0, 0, 0, 0);
                }
            }
            const uint32_t* AHp = sm + XP_AH(buf);
            const uint32_t* ALp = sm + XP_AL(buf);
            const uint32_t* BHp = sm + XP_BH(buf);
            const uint32_t* BLp = sm + XP_BL(buf);
#pragma unroll
            for (int s2 = 0; s2 < 2; s2++) {
                const int k2b = s2 * 8 + cidx;
                uint32_t ah[4], al[4];
                ah[0] = AHp[row0 * XP_PAD + k2b];
                ah[1] = AHp[(row0 + 8) * XP_PAD + k2b];
                ah[2] = AHp[row0 * XP_PAD + k2b + 4];
                ah[3] = AHp[(row0 + 8) * XP_PAD + k2b + 4];
                al[0] = ALp[row0 * XP_PAD + k2b];
                al[1] = ALp[(row0 + 8) * XP_PAD + k2b];
                al[2] = ALp[row0 * XP_PAD + k2b + 4];
                al[3] = ALp[(row0 + 8) * XP_PAD + k2b + 4];
#pragma unroll
                for (int nt = 0; nt < 8; nt++) {
                    const int col = nt * 8 + r;
                    uint32_t bh0 = BHp[col * XP_PAD + k2b];
                    uint32_t bh1 = BHp[col * XP_PAD + k2b + 4];
                    uint32_t bl0 = BLp[col * XP_PAD + k2b];
                    uint32_t bl1 = BLp[col * XP_PAD + k2b + 4];
                    mma_f16(acc[nt], ah, bh0, bh1);
                    mma_f16(acc[nt], al, bh0, bh1);
                    mma_f16(acc[nt], ah, bl0, bl1);
                }
            }
            if (kc < 9) {
                const int nb = (kc + 1) & 1;
#pragma unroll
                for (int j = 0; j < 4; j++) {
                    int k2b = kqA * 8 + j * 2;
                    uint32_t h0, l0, h1, l1;
                    split_pack_f16(av[j].x, av[j].y, h0, l0);
                    split_pack_f16(av[j].z, av[j].w, h1, l1);
                    sm[XP_AH(nb) + rowA * XP_PAD + k2b]     = h0;
                    sm[XP_AH(nb) + rowA * XP_PAD + k2b + 1] = h1;
                    sm[XP_AL(nb) + rowA * XP_PAD + k2b]     = l0;
                    sm[XP_AL(nb) + rowA * XP_PAD + k2b + 1] = l1;
                }
#pragma unroll
                for (int j = 0; j < 2; j++) {
                    int k2b = kqB * 4 + j * 2;
                    uint32_t h0, l0, h1, l1;
                    split_pack_f16(bv[j].x, bv[j].y, h0, l0);
                    split_pack_f16(bv[j].z, bv[j].w, h1, l1);
                    sm[XP_BH(nb) + rowB * XP_PAD + k2b]     = h0;
                    sm[XP_BH(nb) + rowB * XP_PAD + k2b + 1] = h1;
                    sm[XP_BL(nb) + rowB * XP_PAD + k2b]     = l0;
                    sm[XP_BL(nb) + rowB * XP_PAD + k2b + 1] = l1;
                }
            }
            __syncthreads();
        }

        // epilogue: +bias, write [dir][t][n][b], then signal slice
        const int gr0 = n0 + wid * 16 + r;
        const int gr1 = gr0 + 8;
        const float bv0 = bias[gr0];
        const float bv1 = bias[gr1];
        float* outb = g_xproj + ((size_t)(dir * T_ + t)) * (G4H * B_);
#pragma unroll
        for (int nt = 0; nt < 8; nt++) {
            const int col = nt * 8 + 2 * cidx;
            float2 o0 = make_float2(acc[nt][0] + bv0, acc[nt][1] + bv0);
            float2 o1 = make_float2(acc[nt][2] + bv1, acc[nt][3] + bv1);
            *(float2*)(outb + (size_t)gr0 * B_ + col) = o0;
            *(float2*)(outb + (size_t)gr1 * B_ + col) = o1;
        }
        __threadfence();
        __syncthreads();
        if (tid == 0) atomicAdd(&g_xslice[s_], 1);
    }
}

// =============================================================================
// LSTM chain block (device fn) — r12 exact structure + slice-wait per step.
// 64 blocks = dir(2) x bg(2, 32 batches) x hc(16, 16 hidden units).
// =============================================================================
__device__ void lstm_block(uint32_t* s, int bx) {
    uint32_t* Ahi = s + L_AHI;
    uint32_t* Alo = s + L_ALO;
    uint32_t* Bhi = s + L_BHI;
    uint32_t* Blo = s + L_BLO;
    float*    gex = (float*)(s + L_GEX);

    const int tid = threadIdx.x;
    const int dir = bx >> 5;
    const int bg  = (bx >> 4) & 1;
    const int hc  = bx & 15;
    const int grp = dir * 2 + bg;

    // ---- load this block's f16 A fragments (weights) into smem
    {
        const uint4* srcH = (const uint4*)(g_wfrag16_hi + ((size_t)(dir * 16 + hc)) * 8192);
        const uint4* srcL = (const uint4*)(g_wfrag16_lo + ((size_t)(dir * 16 + hc)) * 8192);
        uint4* dH = (uint4*)Ahi;
        uint4* dL = (uint4*)Alo;
#pragma unroll
        for (int j = 0; j < 8; j++) {
            dH[tid + j * 256] = srcH[tid + j * 256];
            dL[tid + j * 256] = srcL[tid + j * 256];
        }
    }

    const int w    = tid >> 5;
    const int lane = tid & 31;
    const int q    = w & 3;
    const int nt0  = (w >> 2) * 2;

    const int ci = (2 * tid) >> 5;     // 0..15
    const int cb = (2 * tid) & 31;     // even
    float cst0 = 0.f, cst1 = 0.f;

    // h fragment store coords (producer side), k = hc*16+ci
    const int kin   = ci;
    const int s_reg = kin >> 3;
    const int s_tig = (kin >> 1) & 3;
    const int s_half = kin & 1;

    __syncthreads();

    for (int st = 0; st < T_; st++) {
        const int t = dir ? (T_ - 1 - st) : st;

        // wait for xproj slice (produced by concurrent workers)
        {
            const int* cp = g_xslice + (st * 2 + dir);
            int v;
            for (;;) {
                asm volatile("ld.acquire.gpu.global.b32 %0, [%1];"
                             : "=r"(v) : "l"(cp) : "memory");
                if (v >= 8) break;
                __nanosleep(60);
            }
        }

        // prefetch xproj gate pre-activations
        float2 xpv[4];
        {
            const float* xb = g_xproj + ((size_t)(dir * T_ + t)) * (G4H * B_)
                              + (size_t)(hc * 16 + ci) * B_ + bg * 32 + cb;
#pragma unroll
            for (int qq = 0; qq < 4; qq++)
                xpv[qq] = *(const float2*)(xb + (size_t)qq * (H_ * B_));
        }

        float ga[4][2];
#pragma unroll
        for (int qq = 0; qq < 4; qq++) { ga[qq][0] = xpv[qq].x; ga[qq][1] = xpv[qq].y; }

        if (st > 0) {
            // wait for all 16 producers of step st-1 (one flag line, acquire + backoff)
            if (tid < 16) {
                const int* fp = g_flags + ((grp * T_ + (st - 1)) << 4) + tid;
                int v;
                for (;;) {
                    asm volatile("ld.acquire.gpu.global.b32 %0, [%1];"
                                 : "=r"(v) : "l"(fp) : "memory");
                    if (__all_sync(0x0000FFFFu, v != 0)) break;
                    __nanosleep(30);
                }
            }
            __syncthreads();

            // copy h fragments (parity of step st-1) global -> smem
            {
                const size_t hb = ((size_t)grp * 2 + ((st - 1) & 1)) * 4096;
                const uint4* sH = (const uint4*)(g_hfrag16_hi + hb);
                const uint4* sL = (const uint4*)(g_hfrag16_lo + hb);
                uint4* dH = (uint4*)Bhi;
                uint4* dL = (uint4*)Blo;
#pragma unroll
                for (int j = 0; j < 4; j++) {
                    dH[tid + j * 256] = __ldcg(sH + tid + j * 256);
                    dL[tid + j * 256] = __ldcg(sL + tid + j * 256);
                }
            }
            __syncthreads();

            float acc[2][4];
#pragma unroll
            for (int e = 0; e < 2; e++)
#pragma unroll
                for (int j = 0; j < 4; j++) acc[e][j] = 0.f;

            const uint32_t* Aq_hi = Ahi + q * 2048;
            const uint32_t* Aq_lo = Alo + q * 2048;
#pragma unroll 8
            for (int kt = 0; kt < 16; kt++) {
                uint4 ahv = *(const uint4*)(Aq_hi + (kt * 32 + lane) * 4);
                uint4 alv = *(const uint4*)(Aq_lo + (kt * 32 + lane) * 4);
                const uint32_t* ah = (const uint32_t*)&ahv;
                const uint32_t* al = (const uint32_t*)&alv;
#pragma unroll
                for (int e = 0; e < 2; e++) {
                    const int nt = nt0 + e;
                    uint2 bh = *(const uint2*)(Bhi + ((kt * 4 + nt) * 32 + lane) * 2);
                    uint2 bl = *(const uint2*)(Blo + ((kt * 4 + nt) * 32 + lane) * 2);
                    mma_f16(acc[e], ah, bh.x, bh.y);
                    mma_f16(acc[e], al, bh.x, bh.y);
                    mma_f16(acc[e], ah, bl.x, bl.y);
                }
            }
            {
                const int i_lo = lane >> 2;
                const int colb = (lane & 3) * 2;
#pragma unroll
                for (int e = 0; e < 2; e++) {
                    const int col = (nt0 + e) * 8 + colb;
                    gex[(q * 16 + i_lo) * 33 + col]     = acc[e][0];
                    gex[(q * 16 + i_lo) * 33 + col + 1] = acc[e][1];
                    gex[(q * 16 + i_lo + 8) * 33 + col]     = acc[e][2];
                    gex[(q * 16 + i_lo + 8) * 33 + col + 1] = acc[e][3];
                }
            }
            __syncthreads();

#pragma unroll
            for (int qq = 0; qq < 4; qq++) {
                ga[qq][0] += gex[(qq * 16 + ci) * 33 + cb];
                ga[qq][1] += gex[(qq * 16 + ci) * 33 + cb + 1];
            }
        }

        float h0, h1;
        {
            float ig = sigf(ga[0][0]);
            float fg = sigf(ga[1][0]);
            float gg = tanhf_fast(ga[2][0]);
            float og = sigf(ga[3][0]);
            cst0 = fg * cst0 + ig * gg;
            h0 = og * tanhf_fast(cst0);
        }
        {
            float ig = sigf(ga[0][1]);
            float fg = sigf(ga[1][1]);
            float gg = tanhf_fast(ga[2][1]);
            float og = sigf(ga[3][1]);
            cst1 = fg * cst1 + ig * gg;
            h1 = og * tanhf_fast(cst1);
        }

        // write h (fp32 for fc1) and f16 hi/lo fragment halves (parity st&1)
        {
            const int k = hc * 16 + ci;
            *(float2*)(g_h + (((size_t)(dir * T_ + t)) * H_ + k) * B_ + bg * 32 + cb)
                = make_float2(h0, h1);

            const size_t hb = ((size_t)grp * 2 + (st & 1)) * 4096;
            uint16_t* HHi = (uint16_t*)g_hfrag16_hi;
            uint16_t* HLo = (uint16_t*)g_hfrag16_lo;
            uint16_t fhi, flo;
            // cell 0: n = cb
            {
                const int nt = cb >> 3;
                const int laneb = (cb & 7) * 4 + s_tig;
                const size_t word = hb + (((size_t)hc * 4 + nt) * 32 + laneb) * 2 + s_reg;
                split_f16_u16(h0, fhi, flo);
                HHi[word * 2 + s_half] = fhi;
                HLo[word * 2 + s_half] = flo;
            }
            // cell 1: n = cb+1
            {
                const int b1 = cb + 1;
                const int nt = b1 >> 3;
                const int laneb = (b1 & 7) * 4 + s_tig;
                const size_t word = hb + (((size_t)hc * 4 + nt) * 32 + laneb) * 2 + s_reg;
                split_f16_u16(h1, fhi, flo);
                HHi[word * 2 + s_half] = fhi;
                HLo[word * 2 + s_half] = flo;
            }
        }
        __syncthreads();
        if (tid == 0) {
            __threadfence();
            int* fp = g_flags + ((grp * T_ + st) << 4) + hc;
            asm volatile("st.release.gpu.global.b32 [%0], %1;" :: "l"(fp), "r"(1) : "memory");
        }
    }
}

// =============================================================================
// fused kernel: blocks 0..63 = LSTM chains, 64..147 = xproj workers.
// grid 148 -> one block per SM (classic bid%148 map): LSTM gets dedicated SMs.
// =============================================================================
__global__ void __launch_bounds__(256, 2)
fused_kernel(const int* __restrict__ x,
             const float* __restrict__ emb,
             const float* __restrict__ Wf, const float* __restrict__ bf,
             const float* __restrict__ Wb, const float* __restrict__ bb) {
    extern __shared__ uint32_t s[];
    const int bx = blockIdx.x;
    if (bx < N_LSTM_BLK) {
        lstm_block(s, bx);
    } else {
        xproj_worker(s, bx - N_LSTM_BLK, x, emb, Wf, bf, Wb, bb);
    }
}

// =============================================================================
// fc1 (3xTF32) + fused cls — r12 proven; unchanged
// =============================================================================
#define XA_PAD 136
#define XB_PAD 72
#define XA_SZ  (32 * XA_PAD)
#define XB_SZ  (32 * XB_PAD)
#define X_AH(buf) ((buf) * XA_SZ)
#define X_AL(buf) (2 * XA_SZ + (buf) * XA_SZ)
#define X_BH(buf) (4 * XA_SZ + (buf) * XB_SZ)
#define X_BL(buf) (4 * XA_SZ + 2 * XB_SZ + (buf) * XB_SZ)
#define X_SMEM_BYTES ((4 * XA_SZ + 4 * XB_SZ + 64) * 4)
#define XI_PITCH 65
#define XW_OFF   (128 * XI_PITCH)

__global__ void __launch_bounds__(256, 2)
fc1_kernel(const float* __restrict__ W, const float* __restrict__ bias,
           const float* __restrict__ clsW, const float* __restrict__ clsb) {
    extern __shared__ uint32_t sm[];
    const int tid = threadIdx.x;
    const int t   = blockIdx.x;

    const int rowA = tid & 127;
    const int kqA  = tid >> 7;
    const float* Arow = W + (size_t)rowA * 512;

    const int wid  = tid >> 5;
    const int lane = tid & 31;
    const int r    = lane >> 2;
    const int cidx = lane & 3;

    float acc[8][4];
#pragma unroll
    for (int i = 0; i < 8; i++)
#pragma unroll
        for (int j = 0; j < 4; j++) acc[i][j] = 0.f;

    float4 av[4];
    float4 bv[2];

#pragma unroll
    for (int j = 0; j < 4; j++) {
        int gk4 = kqA + 2 * j;
        av[j] = *(const float4*)(Arow + gk4 * 4);
    }
#pragma unroll
    for (int j = 0; j < 2; j++) {
        int f4id = tid + j * 256;
        int kl = f4id >> 4, b4 = f4id & 15;
        int kgl = kl;
        int d = kgl >> 8, kh = kgl & 255;
        bv[j] = *(const float4*)(g_h + ((size_t)(d * T_ + t) * 256 + kh) * 64 + b4 * 4);
    }
#pragma unroll
    for (int j = 0; j < 4; j++) {
        int kl = (kqA + 2 * j) * 4;
        const float* v = (const float*)&av[j];
#pragma unroll
        for (int c = 0; c < 4; c++) {
            uint32_t hi, lo; split_tf32(v[c], hi, lo);
            sm[X_AH(0) + (kl + c) * XA_PAD + rowA] = hi;
            sm[X_AL(0) + (kl + c) * XA_PAD + rowA] = lo;
        }
    }
#pragma unroll
    for (int j = 0; j < 2; j++) {
        int f4id = tid + j * 256;
        int kl = f4id >> 4, b4 = f4id & 15;
        const float* v = (const float*)&bv[j];
#pragma unroll
        for (int c = 0; c < 4; c++) {
            uint32_t hi, lo; split_tf32(v[c], hi, lo);
            sm[X_BH(0) + kl * XB_PAD + b4 * 4 + c] = hi;
            sm[X_BL(0) + kl * XB_PAD + b4 * 4 + c] = lo;
        }
    }
    __syncthreads();

    for (int kc = 0; kc < 16; kc++) {
        const int buf = kc & 1;
        if (kc < 15) {
#pragma unroll
            for (int j = 0; j < 4; j++) {
                int gk4 = (kc + 1) * 8 + kqA + 2 * j;
                av[j] = *(const float4*)(Arow + gk4 * 4);
            }
#pragma unroll
            for (int j = 0; j < 2; j++) {
                int f4id = tid + j * 256;
                int kl = f4id >> 4, b4 = f4id & 15;
                int kgl = (kc + 1) * 32 + kl;
                int d = kgl >> 8, kh = kgl & 255;
                bv[j] = *(const float4*)(g_h + ((size_t)(d * T_ + t) * 256 + kh) * 64 + b4 * 4);
            }
        }
        const uint32_t* AH = sm + X_AH(buf);
        const uint32_t* AL = sm + X_AL(buf);
        const uint32_t* BH = sm + X_BH(buf);
        const uint32_t* BL = sm + X_BL(buf);
        const int row0 = wid * 16 + r;
#pragma unroll
        for (int kk = 0; kk < 4; kk++) {
            const int base = kk * 8 + cidx;
            uint32_t ah[4], al[4];
            ah[0] = AH[base * XA_PAD + row0];
            ah[1] = AH[base * XA_PAD + row0 + 8];
            ah[2] = AH[(base + 4) * XA_PAD + row0];
            ah[3] = AH[(base + 4) * XA_PAD + row0 + 8];
            al[0] = AL[base * XA_PAD + row0];
            al[1] = AL[base * XA_PAD + row0 + 8];
            al[2] = AL[(base + 4) * XA_PAD + row0];
            al[3] = AL[(base + 4) * XA_PAD + row0 + 8];
#pragma unroll
            for (int nt = 0; nt < 8; nt++) {
                const int col = nt * 8 + r;
                uint32_t bh0 = BH[base * XB_PAD + col];
                uint32_t bh1 = BH[(base + 4) * XB_PAD + col];
                uint32_t bl0 = BL[base * XB_PAD + col];
                uint32_t bl1 = BL[(base + 4) * XB_PAD + col];
                mma_tf32(acc[nt], ah, bh0, bh1);
                mma_tf32(acc[nt], al, bh0, bh1);
                mma_tf32(acc[nt], ah, bl0, bl1);
            }
        }
        if (kc < 15) {
            const int nb = (kc + 1) & 1;
#pragma unroll
            for (int j = 0; j < 4; j++) {
                int kl = (kqA + 2 * j) * 4;
                const float* v = (const float*)&av[j];
#pragma unroll
                for (int c = 0; c < 4; c++) {
                    uint32_t hi, lo; split_tf32(v[c], hi, lo);
                    sm[X_AH(nb) + (kl + c) * XA_PAD + rowA] = hi;
                    sm[X_AL(nb) + (kl + c) * XA_PAD + rowA] = lo;
                }
            }
#pragma unroll
            for (int j = 0; j < 2; j++) {
                int f4id = tid + j * 256;
                int kl = f4id >> 4, b4 = f4id & 15;
                const float* v = (const float*)&bv[j];
#pragma unroll
                for (int c = 0; c < 4; c++) {
                    uint32_t hi, lo; split_tf32(v[c], hi, lo);
                    sm[X_BH(nb) + kl * XB_PAD + b4 * 4 + c] = hi;
                    sm[X_BL(nb) + kl * XB_PAD + b4 * 4 + c] = lo;
                }
            }
        }
        __syncthreads();
    }

    // ---- fused epilogue: relu tile -> smem, then cls -> g_unary
    float* sIf = (float*)sm;
    float* sWc = (float*)(sm + XW_OFF);
    {
        const int gr0 = wid * 16 + r;
        const int gr1 = gr0 + 8;
        const float bv0 = bias[gr0];
        const float bv1 = bias[gr1];
#pragma unroll
        for (int nt = 0; nt < 8; nt++) {
            const int col = nt * 8 + 2 * cidx;
            sIf[gr0 * XI_PITCH + col]     = fmaxf(acc[nt][0] + bv0, 0.f);
            sIf[gr0 * XI_PITCH + col + 1] = fmaxf(acc[nt][1] + bv0, 0.f);
            sIf[gr1 * XI_PITCH + col]     = fmaxf(acc[nt][2] + bv1, 0.f);
            sIf[gr1 * XI_PITCH + col + 1] = fmaxf(acc[nt][3] + bv1, 0.f);
        }
    }
    for (int i = tid; i < NL * INTER_; i += 256) sWc[i] = clsW[i];
    __syncthreads();

    const int b  = tid & 63;
    const int lg = tid >> 6;
    for (int l = lg; l < NL; l += 4) {
        float a = clsb[l];
        const float* wr = sWc + l * INTER_;
#pragma unroll 8
        for (int n = 0; n < INTER_; n++) a += wr[n] * sIf[n * XI_PITCH + b];
        g_unary[((size_t)b * T_ + t) * TL + l] = a;
    }
    if (tid < 128) {
        int bb = tid & 63;
        int l  = NL + (tid >> 6);
        g_unary[((size_t)bb * T_ + t) * TL + l] = LOW_POT;
    }
}

// ---------------- Viterbi + backtrace (one block per batch element) ---------
__global__ void viterbi_kernel(const float* __restrict__ trans, float* __restrict__ out,
                               int score_off, int label_off) {
    __shared__ float tr[TL * TL];
    __shared__ float s0[TL], s1[TL];
    __shared__ unsigned char bp[T_][TL];
    const int b = blockIdx.x;
    const int tid = threadIdx.x;

    for (int i = tid; i < TL * TL; i += 32) tr[i] = trans[i];
    if (tid < TL) s0[tid] = (tid == START_L) ? 0.f : LOW_POT;
    __syncthreads();

    const float* ub = g_unary + (size_t)b * T_ * TL;
    float* sc = s0;
    float* sn = s1;
    for (int t = 0; t < T_; t++) {
        if (tid < TL) {
            float best = sc[0] + tr[tid * TL + 0];
            int bpi = 0;
#pragma unroll
            for (int p = 1; p < TL; p++) {
                float v = sc[p] + tr[tid * TL + p];
                if (v > best) { best = v; bpi = p; }
            }
            sn[tid] = best + ub[t * TL + tid];
            bp[t][tid] = (unsigned char)bpi;
        }
        __syncthreads();
        float* tmp = sc; sc = sn; sn = tmp;
    }
    if (tid == 0) {
        float best = sc[0] + tr[END_L * TL + 0];
        int li = 0;
        for (int l = 1; l < TL; l++) {
            float v = sc[l] + tr[END_L * TL + l];
            if (v > best) { best = v; li = l; }
        }
        if (score_off >= 0) out[score_off + b] = best;
        if (label_off >= 0) {
            int cur = li;
            for (int t = T_ - 1; t >= 0; t--) {
                out[label_off + (size_t)b * T_ + t] = (float)cur;
                cur = bp[t][cur];
            }
        }
    }
}

// ---------------- launch -----------------------------------------------------
extern "C" void kernel_launch(void* const* d_in, const int* in_sizes, int n_in,
                              void* d_out, int out_size) {
    const int*   x       = (const int*)d_in[0];
    const float* emb     = (const float*)d_in[1];
    const float* W_ih_f  = (const float*)d_in[2];
    const float* W_hh_f  = (const float*)d_in[3];
    const float* b_f     = (const float*)d_in[4];
    const float* W_ih_b  = (const float*)d_in[5];
    const float* W_hh_b  = (const float*)d_in[6];
    const float* b_b     = (const float*)d_in[7];
    const float* fc1_W   = (const float*)d_in[8];
    const float* fc1_b   = (const float*)d_in[9];
    const float* cls_W   = (const float*)d_in[10];
    const float* cls_b   = (const float*)d_in[11];
    const float* trans   = (const float*)d_in[12];
    float* out = (float*)d_out;

    int score_off = 0, label_off = B_;
    if (out_size == B_ * T_)      { score_off = -1; label_off = 0; }
    else if (out_size == B_)      { label_off = -1; }

    cudaFuncSetAttribute(fused_kernel, cudaFuncAttributeMaxDynamicSharedMemorySize, L_SMEM_BYTES);
    cudaFuncSetAttribute(fc1_kernel, cudaFuncAttributeMaxDynamicSharedMemorySize, X_SMEM_BYTES);

    zero_bar_kernel<<<64, 256>>>();
    prep_whh_kernel<<<1024, 256>>>(W_hh_f, W_hh_b);
    fused_kernel<<<N_LSTM_BLK + N_WORKERS, 256, L_SMEM_BYTES>>>(x, emb, W_ih_f, b_f, W_ih_b, b_b);
    fc1_kernel<<<T_, 256, X_SMEM_BYTES>>>(fc1_W, fc1_b, cls_W, cls_b);
    viterbi_kernel<<<B_, 32>>>(trans, out, score_off, label_off);
}

// round 16
// speedup vs baseline: 1.4337x; 1.0533x over previous
#include <cuda_runtime.h>
#include <cuda_bf16.h>
#include <cuda_fp16.h>
#include <math.h>
#include <stdint.h>

// Problem constants
#define B_   64
#define T_   256
#define E_   300
#define H_   256
#define G4H  1024      // 4*H
#define INTER_ 128
#define NL   17
#define TL   19        // NUM_LABELS + 2
#define START_L 17
#define END_L   18
#define LOW_POT (-10000.0f)

#define N_LSTM_BLK 64
#define N_WORKERS  84
#define N_ITEMS    4096      // 512 slices x 8 n-tiles

// ---------------- scratch (device globals; no allocations allowed) ----------
__device__ float g_xproj[(size_t)2 * T_ * G4H * B_];   // [dir][t][n(1024)][b]
__device__ float g_h[(size_t)2 * T_ * H_ * B_];        // [dir][t][k][b]
__device__ float g_unary[(size_t)B_ * T_ * TL];        // [b][t][l]
__device__ int   g_flags[4 * T_ * 16];                 // per-(grp,step,producer) flags
__device__ int   g_xslice[512];                        // per-slice tile counters (8 = ready)

// W_hh in f16 mma-fragment order: [dir][hc(16)][q(4)][kt(16)][lane(32)][reg(4)]
__device__ uint32_t g_wfrag16_hi[2 * 16 * 4 * 16 * 32 * 4];
__device__ uint32_t g_wfrag16_lo[2 * 16 * 4 * 16 * 32 * 4];
// h in f16 mma B-fragment order: [grp(4)][par(2)][kt(16)][nt(4)][lane(32)][reg(2)]
__device__ uint32_t g_hfrag16_hi[4 * 2 * 16 * 4 * 32 * 2];
__device__ uint32_t g_hfrag16_lo[4 * 2 * 16 * 4 * 32 * 2];

// ---------------- helpers ----------------------------------------------------
__device__ __forceinline__ uint32_t f2tf32(float x) {
    uint32_t r;
    asm("cvt.rna.tf32.f32 %0, %1;" : "=r"(r) : "f"(x));
    return r;
}
__device__ __forceinline__ void split_tf32(float x, uint32_t& hi, uint32_t& lo) {
    hi = f2tf32(x);
    lo = f2tf32(x - __uint_as_float(hi));
}
__device__ __forceinline__ void mma_tf32(float* d, const uint32_t* a, uint32_t b0, uint32_t b1) {
    asm volatile(
        "mma.sync.aligned.m16n8k8.row.col.f32.tf32.tf32.f32 "
        "{%0,%1,%2,%3}, {%4,%5,%6,%7}, {%8,%9}, {%0,%1,%2,%3};"
        : "+f"(d[0]), "+f"(d[1]), "+f"(d[2]), "+f"(d[3])
        : "r"(a[0]), "r"(a[1]), "r"(a[2]), "r"(a[3]), "r"(b0), "r"(b1));
}
__device__ __forceinline__ void mma_f16(float* d, const uint32_t* a, uint32_t b0, uint32_t b1) {
    asm volatile(
        "mma.sync.aligned.m16n8k16.row.col.f32.f16.f16.f32 "
        "{%0,%1,%2,%3}, {%4,%5,%6,%7}, {%8,%9}, {%0,%1,%2,%3};"
        : "+f"(d[0]), "+f"(d[1]), "+f"(d[2]), "+f"(d[3])
        : "r"(a[0]), "r"(a[1]), "r"(a[2]), "r"(a[3]), "r"(b0), "r"(b1));
}
__device__ __forceinline__ void split_pack_f16(float x0, float x1, uint32_t& hi, uint32_t& lo) {
    __half h0 = __float2half_rn(x0);
    __half h1 = __float2half_rn(x1);
    __half l0 = __float2half_rn(x0 - __half2float(h0));
    __half l1 = __float2half_rn(x1 - __half2float(h1));
    hi = (uint32_t)__half_as_ushort(h0) | ((uint32_t)__half_as_ushort(h1) << 16);
    lo = (uint32_t)__half_as_ushort(l0) | ((uint32_t)__half_as_ushort(l1) << 16);
}
__device__ __forceinline__ void split_f16_u16(float x, uint16_t& hi, uint16_t& lo) {
    __half h = __float2half_rn(x);
    __half l = __float2half_rn(x - __half2float(h));
    hi = __half_as_ushort(h);
    lo = __half_as_ushort(l);
}
__device__ __forceinline__ uint2 ldcg_u2(const uint32_t* p) {
    uint2 v;
    asm volatile("ld.global.cg.v2.u32 {%0,%1}, [%2];" : "=r"(v.x), "=r"(v.y) : "l"(p));
    return v;
}

// fast activations (~1e-7 rel err, clamped)
__device__ __forceinline__ float sigf(float x) {
    x = fmaxf(fminf(x, 30.f), -30.f);
    return __fdividef(1.f, 1.f + __expf(-x));
}
__device__ __forceinline__ float tanhf_fast(float x) {
    x = fmaxf(fminf(x, 15.f), -15.f);
    float e = __expf(2.f * x);
    return __fdividef(e - 1.f, e + 1.f);
}

// ---------------- flag zeroing (graph-replay determinism) -------------------
__global__ void zero_bar_kernel() {
    int i = blockIdx.x * 256 + threadIdx.x;
    if (i < 4 * T_ * 16) g_flags[i] = 0;
    if (i < 512) g_xslice[i] = 0;
}

// ---------------- W_hh f16 fragment prep ------------------------------------
__global__ void prep_whh_kernel(const float* __restrict__ Whf,
                                const float* __restrict__ Whb) {
    int idx = blockIdx.x * 256 + threadIdx.x;
    if (idx >= 2 * 16 * 4 * 16 * 32 * 4) return;
    int reg  = idx & 3;
    int lane = (idx >> 2) & 31;
    int kt   = (idx >> 7) & 15;
    int q    = (idx >> 11) & 3;
    int hc   = (idx >> 13) & 15;
    int dir  = (idx >> 17) & 1;
    const float* W = dir ? Whb : Whf;
    int i  = (lane >> 2) + 8 * (reg & 1);
    int g  = q * 256 + hc * 16 + i;
    int k0 = kt * 16 + (lane & 3) * 2 + 8 * (reg >> 1);
    float v0 = W[(size_t)g * H_ + k0];
    float v1 = W[(size_t)g * H_ + k0 + 1];
    uint32_t hi, lo;
    split_pack_f16(v0, v1, hi, lo);
    g_wfrag16_hi[idx] = hi;
    g_wfrag16_lo[idx] = lo;
}

// ---------------- smem layouts ------------------------------------------------
// xproj worker area (61.7KB)
#define XP_PAD 20
#define XP_A_SZ (128 * XP_PAD)
#define XP_B_SZ (64 * XP_PAD)
#define XP_AH(b) ((b) * XP_A_SZ)
#define XP_AL(b) (2 * XP_A_SZ + (b) * XP_A_SZ)
#define XP_BH(b) (4 * XP_A_SZ + (b) * XP_B_SZ)
#define XP_BL(b) (4 * XP_A_SZ + 2 * XP_B_SZ + (b) * XP_B_SZ)
#define XP_TOK   (4 * XP_A_SZ + 4 * XP_B_SZ)

// LSTM area: weights + gate exchange only (B frags read direct from L2)
#define L_AHI 0
#define L_ALO 8192
#define L_GEX 16384
#define L_SMEM_BYTES ((16384 + 4 * 16 * 33) * 4)   // 74112

// =============================================================================
// xproj worker (device fn) — r15 proven; unchanged
// =============================================================================
__device__ void xproj_worker(uint32_t* sm, int wkr,
                             const int* __restrict__ x,
                             const float* __restrict__ emb,
                             const float* __restrict__ Wf, const float* __restrict__ bf,
                             const float* __restrict__ Wb, const float* __restrict__ bb) {
    const int tid = threadIdx.x;
    const int rowA = tid & 127;
    const int kqA  = tid >> 7;
    const int rowB = tid & 63;
    const int kqB  = tid >> 6;
    const int wid  = tid >> 5;
    const int lane = tid & 31;
    const int r    = lane >> 2;
    const int cidx = lane & 3;
    const int row0 = wid * 16 + r;
    int* tok = (int*)(sm + XP_TOK);

    for (int item = wkr; item < N_ITEMS; item += N_WORKERS) {
        const int s_  = item >> 3;
        const int n0  = (item & 7) * 128;
        const int dir = s_ & 1;
        const int kk  = s_ >> 1;
        const int t   = dir ? (T_ - 1 - kk) : kk;
        const float* W    = dir ? Wb : Wf;
        const float* bias = dir ? bb : bf;

        if (tid < 64) tok[tid] = x[tid * T_ + t];
        __syncthreads();

        const float* Arow = W + (size_t)(n0 + rowA) * E_;
        const float* Brow = emb + (size_t)tok[rowB] * E_;

        float acc[8][4];
#pragma unroll
        for (int i = 0; i < 8; i++)
#pragma unroll
            for (int j = 0; j < 4; j++) acc[i][j] = 0.f;

        float4 av[4];
        float4 bv[2];

#pragma unroll
        for (int j = 0; j < 4; j++) {
            int gk4 = kqA * 4 + j;
            av[j] = (gk4 < 75) ? *(const float4*)(Arow + gk4 * 4) : make_float4(0, 0, 0, 0);
        }
#pragma unroll
        for (int j = 0; j < 2; j++) {
            int gk4 = kqB * 2 + j;
            bv[j] = (gk4 < 75) ? *(const float4*)(Brow + gk4 * 4) : make_float4(0, 0, 0, 0);
        }
#pragma unroll
        for (int j = 0; j < 4; j++) {
            int k2b = kqA * 8 + j * 2;
            uint32_t h0, l0, h1, l1;
            split_pack_f16(av[j].x, av[j].y, h0, l0);
            split_pack_f16(av[j].z, av[j].w, h1, l1);
            sm[XP_AH(0) + rowA * XP_PAD + k2b]     = h0;
            sm[XP_AH(0) + rowA * XP_PAD + k2b + 1] = h1;
            sm[XP_AL(0) + rowA * XP_PAD + k2b]     = l0;
            sm[XP_AL(0) + rowA * XP_PAD + k2b + 1] = l1;
        }
#pragma unroll
        for (int j = 0; j < 2; j++) {
            int k2b = kqB * 4 + j * 2;
            uint32_t h0, l0, h1, l1;
            split_pack_f16(bv[j].x, bv[j].y, h0, l0);
            split_pack_f16(bv[j].z, bv[j].w, h1, l1);
            sm[XP_BH(0) + rowB * XP_PAD + k2b]     = h0;
            sm[XP_BH(0) + rowB * XP_PAD + k2b + 1] = h1;
            sm[XP_BL(0) + rowB * XP_PAD + k2b]     = l0;
            sm[XP_BL(0) + rowB * XP_PAD + k2b + 1] = l1;
        }
        __syncthreads();

        for (int kc = 0; kc < 10; kc++) {
            const int buf = kc & 1;
            if (kc < 9) {
#pragma unroll
                for (int j = 0; j < 4; j++) {
                    int gk4 = (kc + 1) * 8 + kqA * 4 + j;
                    av[j] = (gk4 < 75) ? *(const float4*)(Arow + gk4 * 4) : make_float4(0, 0, 0, 0);
                }
#pragma unroll
                for (int j = 0; j < 2; j++) {
                    int gk4 = (kc + 1) * 8 + kqB * 2 + j;
                    bv[j] = (gk4 < 75) ? *(const float4*)(Brow + gk4 * 4) : make_float4(0, 0, 0, 0);
                }
            }
            const uint32_t* AHp = sm + XP_AH(buf);
            const uint32_t* ALp = sm + XP_AL(buf);
            const uint32_t* BHp = sm + XP_BH(buf);
            const uint32_t* BLp = sm + XP_BL(buf);
#pragma unroll
            for (int s2 = 0; s2 < 2; s2++) {
                const int k2b = s2 * 8 + cidx;
                uint32_t ah[4], al[4];
                ah[0] = AHp[row0 * XP_PAD + k2b];
                ah[1] = AHp[(row0 + 8) * XP_PAD + k2b];
                ah[2] = AHp[row0 * XP_PAD + k2b + 4];
                ah[3] = AHp[(row0 + 8) * XP_PAD + k2b + 4];
                al[0] = ALp[row0 * XP_PAD + k2b];
                al[1] = ALp[(row0 + 8) * XP_PAD + k2b];
                al[2] = ALp[row0 * XP_PAD + k2b + 4];
                al[3] = ALp[(row0 + 8) * XP_PAD + k2b + 4];
#pragma unroll
                for (int nt = 0; nt < 8; nt++) {
                    const int col = nt * 8 + r;
                    uint32_t bh0 = BHp[col * XP_PAD + k2b];
                    uint32_t bh1 = BHp[col * XP_PAD + k2b + 4];
                    uint32_t bl0 = BLp[col * XP_PAD + k2b];
                    uint32_t bl1 = BLp[col * XP_PAD + k2b + 4];
                    mma_f16(acc[nt], ah, bh0, bh1);
                    mma_f16(acc[nt], al, bh0, bh1);
                    mma_f16(acc[nt], ah, bl0, bl1);
                }
            }
            if (kc < 9) {
                const int nb = (kc + 1) & 1;
#pragma unroll
                for (int j = 0; j < 4; j++) {
                    int k2b = kqA * 8 + j * 2;
                    uint32_t h0, l0, h1, l1;
                    split_pack_f16(av[j].x, av[j].y, h0, l0);
                    split_pack_f16(av[j].z, av[j].w, h1, l1);
                    sm[XP_AH(nb) + rowA * XP_PAD + k2b]     = h0;
                    sm[XP_AH(nb) + rowA * XP_PAD + k2b + 1] = h1;
                    sm[XP_AL(nb) + rowA * XP_PAD + k2b]     = l0;
                    sm[XP_AL(nb) + rowA * XP_PAD + k2b + 1] = l1;
                }
#pragma unroll
                for (int j = 0; j < 2; j++) {
                    int k2b = kqB * 4 + j * 2;
                    uint32_t h0, l0, h1, l1;
                    split_pack_f16(bv[j].x, bv[j].y, h0, l0);
                    split_pack_f16(bv[j].z, bv[j].w, h1, l1);
                    sm[XP_BH(nb) + rowB * XP_PAD + k2b]     = h0;
                    sm[XP_BH(nb) + rowB * XP_PAD + k2b + 1] = h1;
                    sm[XP_BL(nb) + rowB * XP_PAD + k2b]     = l0;
                    sm[XP_BL(nb) + rowB * XP_PAD + k2b + 1] = l1;
                }
            }
            __syncthreads();
        }

        // epilogue: +bias, write [dir][t][n][b], then signal slice
        const int gr0 = n0 + wid * 16 + r;
        const int gr1 = gr0 + 8;
        const float bv0 = bias[gr0];
        const float bv1 = bias[gr1];
        float* outb = g_xproj + ((size_t)(dir * T_ + t)) * (G4H * B_);
#pragma unroll
        for (int nt = 0; nt < 8; nt++) {
            const int col = nt * 8 + 2 * cidx;
            float2 o0 = make_float2(acc[nt][0] + bv0, acc[nt][1] + bv0);
            float2 o1 = make_float2(acc[nt][2] + bv1, acc[nt][3] + bv1);
            *(float2*)(outb + (size_t)gr0 * B_ + col) = o0;
            *(float2*)(outb + (size_t)gr1 * B_ + col) = o1;
        }
        __threadfence();
        __syncthreads();
        if (tid == 0) atomicAdd(&g_xslice[s_], 1);
    }
}

// =============================================================================
// LSTM chain block (device fn): B fragments read DIRECT from L2 in the mma
// loop (no smem staging, no copy barriers). Flag wait + syncthreads orders.
// 64 blocks = dir(2) x bg(2, 32 batches) x hc(16, 16 hidden units).
// =============================================================================
__device__ void lstm_block(uint32_t* s, int bx) {
    uint32_t* Ahi = s + L_AHI;
    uint32_t* Alo = s + L_ALO;
    float*    gex = (float*)(s + L_GEX);

    const int tid = threadIdx.x;
    const int dir = bx >> 5;
    const int bg  = (bx >> 4) & 1;
    const int hc  = bx & 15;
    const int grp = dir * 2 + bg;

    // ---- load this block's f16 A fragments (weights) into smem
    {
        const uint4* srcH = (const uint4*)(g_wfrag16_hi + ((size_t)(dir * 16 + hc)) * 8192);
        const uint4* srcL = (const uint4*)(g_wfrag16_lo + ((size_t)(dir * 16 + hc)) * 8192);
        uint4* dH = (uint4*)Ahi;
        uint4* dL = (uint4*)Alo;
#pragma unroll
        for (int j = 0; j < 8; j++) {
            dH[tid + j * 256] = srcH[tid + j * 256];
            dL[tid + j * 256] = srcL[tid + j * 256];
        }
    }

    const int w    = tid >> 5;
    const int lane = tid & 31;
    const int q    = w & 3;
    const int nt0  = (w >> 2) * 2;

    const int ci = (2 * tid) >> 5;     // 0..15
    const int cb = (2 * tid) & 31;     // even
    float cst0 = 0.f, cst1 = 0.f;

    // h fragment store coords (producer side), k = hc*16+ci
    const int kin   = ci;
    const int s_reg = kin >> 3;
    const int s_tig = (kin >> 1) & 3;
    const int s_half = kin & 1;

    __syncthreads();

    for (int st = 0; st < T_; st++) {
        const int t = dir ? (T_ - 1 - st) : st;

        // wait for xproj slice (produced by concurrent workers)
        {
            const int* cp = g_xslice + (st * 2 + dir);
            int v;
            for (;;) {
                asm volatile("ld.acquire.gpu.global.b32 %0, [%1];"
                             : "=r"(v) : "l"(cp) : "memory");
                if (v >= 8) break;
                __nanosleep(60);
            }
        }

        // prefetch xproj gate pre-activations
        float2 xpv[4];
        {
            const float* xb = g_xproj + ((size_t)(dir * T_ + t)) * (G4H * B_)
                              + (size_t)(hc * 16 + ci) * B_ + bg * 32 + cb;
#pragma unroll
            for (int qq = 0; qq < 4; qq++)
                xpv[qq] = *(const float2*)(xb + (size_t)qq * (H_ * B_));
        }

        float ga[4][2];
#pragma unroll
        for (int qq = 0; qq < 4; qq++) { ga[qq][0] = xpv[qq].x; ga[qq][1] = xpv[qq].y; }

        if (st > 0) {
            // wait for all 16 producers of step st-1 (one flag line, acquire + backoff)
            if (tid < 16) {
                const int* fp = g_flags + ((grp * T_ + (st - 1)) << 4) + tid;
                int v;
                for (;;) {
                    asm volatile("ld.acquire.gpu.global.b32 %0, [%1];"
                                 : "=r"(v) : "l"(fp) : "memory");
                    if (__all_sync(0x0000FFFFu, v != 0)) break;
                    __nanosleep(30);
                }
            }
            __syncthreads();

            // mma phase: B fragments streamed directly from L2 (.cg)
            const size_t hb = ((size_t)grp * 2 + ((st - 1) & 1)) * 4096;
            const uint32_t* GH = g_hfrag16_hi + hb;
            const uint32_t* GL = g_hfrag16_lo + hb;

            float acc[2][4];
#pragma unroll
            for (int e = 0; e < 2; e++)
#pragma unroll
                for (int j = 0; j < 4; j++) acc[e][j] = 0.f;

            const uint32_t* Aq_hi = Ahi + q * 2048;
            const uint32_t* Aq_lo = Alo + q * 2048;
#pragma unroll 8
            for (int kt = 0; kt < 16; kt++) {
                uint4 ahv = *(const uint4*)(Aq_hi + (kt * 32 + lane) * 4);
                uint4 alv = *(const uint4*)(Aq_lo + (kt * 32 + lane) * 4);
                const uint32_t* ah = (const uint32_t*)&ahv;
                const uint32_t* al = (const uint32_t*)&alv;
#pragma unroll
                for (int e = 0; e < 2; e++) {
                    const int nt = nt0 + e;
                    uint2 bh = ldcg_u2(GH + ((kt * 4 + nt) * 32 + lane) * 2);
                    uint2 bl = ldcg_u2(GL + ((kt * 4 + nt) * 32 + lane) * 2);
                    mma_f16(acc[e], ah, bh.x, bh.y);
                    mma_f16(acc[e], al, bh.x, bh.y);
                    mma_f16(acc[e], ah, bl.x, bl.y);
                }
            }
            {
                const int i_lo = lane >> 2;
                const int colb = (lane & 3) * 2;
#pragma unroll
                for (int e = 0; e < 2; e++) {
                    const int col = (nt0 + e) * 8 + colb;
                    gex[(q * 16 + i_lo) * 33 + col]     = acc[e][0];
                    gex[(q * 16 + i_lo) * 33 + col + 1] = acc[e][1];
                    gex[(q * 16 + i_lo + 8) * 33 + col]     = acc[e][2];
                    gex[(q * 16 + i_lo + 8) * 33 + col + 1] = acc[e][3];
                }
            }
            __syncthreads();

#pragma unroll
            for (int qq = 0; qq < 4; qq++) {
                ga[qq][0] += gex[(qq * 16 + ci) * 33 + cb];
                ga[qq][1] += gex[(qq * 16 + ci) * 33 + cb + 1];
            }
        }

        float h0, h1;
        {
            float ig = sigf(ga[0][0]);
            float fg = sigf(ga[1][0]);
            float gg = tanhf_fast(ga[2][0]);
            float og = sigf(ga[3][0]);
            cst0 = fg * cst0 + ig * gg;
            h0 = og * tanhf_fast(cst0);
        }
        {
            float ig = sigf(ga[0][1]);
            float fg = sigf(ga[1][1]);
            float gg = tanhf_fast(ga[2][1]);
            float og = sigf(ga[3][1]);
            cst1 = fg * cst1 + ig * gg;
            h1 = og * tanhf_fast(cst1);
        }

        // write h (fp32 for fc1) and f16 hi/lo fragment halves (parity st&1)
        {
            const int k = hc * 16 + ci;
            *(float2*)(g_h + (((size_t)(dir * T_ + t)) * H_ + k) * B_ + bg * 32 + cb)
                = make_float2(h0, h1);

            const size_t hb = ((size_t)grp * 2 + (st & 1)) * 4096;
            uint16_t* HHi = (uint16_t*)g_hfrag16_hi;
            uint16_t* HLo = (uint16_t*)g_hfrag16_lo;
            uint16_t fhi, flo;
            // cell 0: n = cb
            {
                const int nt = cb >> 3;
                const int laneb = (cb & 7) * 4 + s_tig;
                const size_t word = hb + (((size_t)hc * 4 + nt) * 32 + laneb) * 2 + s_reg;
                split_f16_u16(h0, fhi, flo);
                HHi[word * 2 + s_half] = fhi;
                HLo[word * 2 + s_half] = flo;
            }
            // cell 1: n = cb+1
            {
                const int b1 = cb + 1;
                const int nt = b1 >> 3;
                const int laneb = (b1 & 7) * 4 + s_tig;
                const size_t word = hb + (((size_t)hc * 4 + nt) * 32 + laneb) * 2 + s_reg;
                split_f16_u16(h1, fhi, flo);
                HHi[word * 2 + s_half] = fhi;
                HLo[word * 2 + s_half] = flo;
            }
        }
        __syncthreads();
        if (tid == 0) {
            __threadfence();
            int* fp = g_flags + ((grp * T_ + st) << 4) + hc;
            asm volatile("st.release.gpu.global.b32 [%0], %1;" :: "l"(fp), "r"(1) : "memory");
        }
    }
}

// =============================================================================
// fused kernel: blocks 0..63 = LSTM chains, 64..147 = xproj workers.
// grid 148 -> one block per SM: LSTM gets dedicated SMs.
// =============================================================================
__global__ void __launch_bounds__(256, 2)
fused_kernel(const int* __restrict__ x,
             const float* __restrict__ emb,
             const float* __restrict__ Wf, const float* __restrict__ bf,
             const float* __restrict__ Wb, const float* __restrict__ bb) {
    extern __shared__ uint32_t s[];
    const int bx = blockIdx.x;
    if (bx < N_LSTM_BLK) {
        lstm_block(s, bx);
    } else {
        xproj_worker(s, bx - N_LSTM_BLK, x, emb, Wf, bf, Wb, bb);
    }
}

// =============================================================================
// fc1 (3xTF32) + fused cls — r12 proven; unchanged
// =============================================================================
#define XA_PAD 136
#define XB_PAD 72
#define XA_SZ  (32 * XA_PAD)
#define XB_SZ  (32 * XB_PAD)
#define X_AH(buf) ((buf) * XA_SZ)
#define X_AL(buf) (2 * XA_SZ + (buf) * XA_SZ)
#define X_BH(buf) (4 * XA_SZ + (buf) * XB_SZ)
#define X_BL(buf) (4 * XA_SZ + 2 * XB_SZ + (buf) * XB_SZ)
#define X_SMEM_BYTES ((4 * XA_SZ + 4 * XB_SZ + 64) * 4)
#define XI_PITCH 65
#define XW_OFF   (128 * XI_PITCH)

__global__ void __launch_bounds__(256, 2)
fc1_kernel(const float* __restrict__ W, const float* __restrict__ bias,
           const float* __restrict__ clsW, const float* __restrict__ clsb) {
    extern __shared__ uint32_t sm[];
    const int tid = threadIdx.x;
    const int t   = blockIdx.x;

    const int rowA = tid & 127;
    const int kqA  = tid >> 7;
    const float* Arow = W + (size_t)rowA * 512;

    const int wid  = tid >> 5;
    const int lane = tid & 31;
    const int r    = lane >> 2;
    const int cidx = lane & 3;

    float acc[8][4];
#pragma unroll
    for (int i = 0; i < 8; i++)
#pragma unroll
        for (int j = 0; j < 4; j++) acc[i][j] = 0.f;

    float4 av[4];
    float4 bv[2];

#pragma unroll
    for (int j = 0; j < 4; j++) {
        int gk4 = kqA + 2 * j;
        av[j] = *(const float4*)(Arow + gk4 * 4);
    }
#pragma unroll
    for (int j = 0; j < 2; j++) {
        int f4id = tid + j * 256;
        int kl = f4id >> 4, b4 = f4id & 15;
        int kgl = kl;
        int d = kgl >> 8, kh = kgl & 255;
        bv[j] = *(const float4*)(g_h + ((size_t)(d * T_ + t) * 256 + kh) * 64 + b4 * 4);
    }
#pragma unroll
    for (int j = 0; j < 4; j++) {
        int kl = (kqA + 2 * j) * 4;
        const float* v = (const float*)&av[j];
#pragma unroll
        for (int c = 0; c < 4; c++) {
            uint32_t hi, lo; split_tf32(v[c], hi, lo);
            sm[X_AH(0) + (kl + c) * XA_PAD + rowA] = hi;
            sm[X_AL(0) + (kl + c) * XA_PAD + rowA] = lo;
        }
    }
#pragma unroll
    for (int j = 0; j < 2; j++) {
        int f4id = tid + j * 256;
        int kl = f4id >> 4, b4 = f4id & 15;
        const float* v = (const float*)&bv[j];
#pragma unroll
        for (int c = 0; c < 4; c++) {
            uint32_t hi, lo; split_tf32(v[c], hi, lo);
            sm[X_BH(0) + kl * XB_PAD + b4 * 4 + c] = hi;
            sm[X_BL(0) + kl * XB_PAD + b4 * 4 + c] = lo;
        }
    }
    __syncthreads();

    for (int kc = 0; kc < 16; kc++) {
        const int buf = kc & 1;
        if (kc < 15) {
#pragma unroll
            for (int j = 0; j < 4; j++) {
                int gk4 = (kc + 1) * 8 + kqA + 2 * j;
                av[j] = *(const float4*)(Arow + gk4 * 4);
            }
#pragma unroll
            for (int j = 0; j < 2; j++) {
                int f4id = tid + j * 256;
                int kl = f4id >> 4, b4 = f4id & 15;
                int kgl = (kc + 1) * 32 + kl;
                int d = kgl >> 8, kh = kgl & 255;
                bv[j] = *(const float4*)(g_h + ((size_t)(d * T_ + t) * 256 + kh) * 64 + b4 * 4);
            }
        }
        const uint32_t* AH = sm + X_AH(buf);
        const uint32_t* AL = sm + X_AL(buf);
        const uint32_t* BH = sm + X_BH(buf);
        const uint32_t* BL = sm + X_BL(buf);
        const int row0 = wid * 16 + r;
#pragma unroll
        for (int kk = 0; kk < 4; kk++) {
            const int base = kk * 8 + cidx;
            uint32_t ah[4], al[4];
            ah[0] = AH[base * XA_PAD + row0];
            ah[1] = AH[base * XA_PAD + row0 + 8];
            ah[2] = AH[(base + 4) * XA_PAD + row0];
            ah[3] = AH[(base + 4) * XA_PAD + row0 + 8];
            al[0] = AL[base * XA_PAD + row0];
            al[1] = AL[base * XA_PAD + row0 + 8];
            al[2] = AL[(base + 4) * XA_PAD + row0];
            al[3] = AL[(base + 4) * XA_PAD + row0 + 8];
#pragma unroll
            for (int nt = 0; nt < 8; nt++) {
                const int col = nt * 8 + r;
                uint32_t bh0 = BH[base * XB_PAD + col];
                uint32_t bh1 = BH[(base + 4) * XB_PAD + col];
                uint32_t bl0 = BL[base * XB_PAD + col];
                uint32_t bl1 = BL[(base + 4) * XB_PAD + col];
                mma_tf32(acc[nt], ah, bh0, bh1);
                mma_tf32(acc[nt], al, bh0, bh1);
                mma_tf32(acc[nt], ah, bl0, bl1);
            }
        }
        if (kc < 15) {
            const int nb = (kc + 1) & 1;
#pragma unroll
            for (int j = 0; j < 4; j++) {
                int kl = (kqA + 2 * j) * 4;
                const float* v = (const float*)&av[j];
#pragma unroll
                for (int c = 0; c < 4; c++) {
                    uint32_t hi, lo; split_tf32(v[c], hi, lo);
                    sm[X_AH(nb) + (kl + c) * XA_PAD + rowA] = hi;
                    sm[X_AL(nb) + (kl + c) * XA_PAD + rowA] = lo;
                }
            }
#pragma unroll
            for (int j = 0; j < 2; j++) {
                int f4id = tid + j * 256;
                int kl = f4id >> 4, b4 = f4id & 15;
                const float* v = (const float*)&bv[j];
#pragma unroll
                for (int c = 0; c < 4; c++) {
                    uint32_t hi, lo; split_tf32(v[c], hi, lo);
                    sm[X_BH(nb) + kl * XB_PAD + b4 * 4 + c] = hi;
                    sm[X_BL(nb) + kl * XB_PAD + b4 * 4 + c] = lo;
                }
            }
        }
        __syncthreads();
    }

    // ---- fused epilogue: relu tile -> smem, then cls -> g_unary
    float* sIf = (float*)sm;
    float* sWc = (float*)(sm + XW_OFF);
    {
        const int gr0 = wid * 16 + r;
        const int gr1 = gr0 + 8;
        const float bv0 = bias[gr0];
        const float bv1 = bias[gr1];
#pragma unroll
        for (int nt = 0; nt < 8; nt++) {
            const int col = nt * 8 + 2 * cidx;
            sIf[gr0 * XI_PITCH + col]     = fmaxf(acc[nt][0] + bv0, 0.f);
            sIf[gr0 * XI_PITCH + col + 1] = fmaxf(acc[nt][1] + bv0, 0.f);
            sIf[gr1 * XI_PITCH + col]     = fmaxf(acc[nt][2] + bv1, 0.f);
            sIf[gr1 * XI_PITCH + col + 1] = fmaxf(acc[nt][3] + bv1, 0.f);
        }
    }
    for (int i = tid; i < NL * INTER_; i += 256) sWc[i] = clsW[i];
    __syncthreads();

    const int b  = tid & 63;
    const int lg = tid >> 6;
    for (int l = lg; l < NL; l += 4) {
        float a = clsb[l];
        const float* wr = sWc + l * INTER_;
#pragma unroll 8
        for (int n = 0; n < INTER_; n++) a += wr[n] * sIf[n * XI_PITCH + b];
        g_unary[((size_t)b * T_ + t) * TL + l] = a;
    }
    if (tid < 128) {
        int bb = tid & 63;
        int l  = NL + (tid >> 6);
        g_unary[((size_t)bb * T_ + t) * TL + l] = LOW_POT;
    }
}

// ---------------- Viterbi + backtrace (one block per batch element) ---------
__global__ void viterbi_kernel(const float* __restrict__ trans, float* __restrict__ out,
                               int score_off, int label_off) {
    __shared__ float tr[TL * TL];
    __shared__ float s0[TL], s1[TL];
    __shared__ unsigned char bp[T_][TL];
    const int b = blockIdx.x;
    const int tid = threadIdx.x;

    for (int i = tid; i < TL * TL; i += 32) tr[i] = trans[i];
    if (tid < TL) s0[tid] = (tid == START_L) ? 0.f : LOW_POT;
    __syncthreads();

    const float* ub = g_unary + (size_t)b * T_ * TL;
    float* sc = s0;
    float* sn = s1;
    for (int t = 0; t < T_; t++) {
        if (tid < TL) {
            float best = sc[0] + tr[tid * TL + 0];
            int bpi = 0;
#pragma unroll
            for (int p = 1; p < TL; p++) {
                float v = sc[p] + tr[tid * TL + p];
                if (v > best) { best = v; bpi = p; }
            }
            sn[tid] = best + ub[t * TL + tid];
            bp[t][tid] = (unsigned char)bpi;
        }
        __syncthreads();
        float* tmp = sc; sc = sn; sn = tmp;
    }
    if (tid == 0) {
        float best = sc[0] + tr[END_L * TL + 0];
        int li = 0;
        for (int l = 1; l < TL; l++) {
            float v = sc[l] + tr[END_L * TL + l];
            if (v > best) { best = v; li = l; }
        }
        if (score_off >= 0) out[score_off + b] = best;
        if (label_off >= 0) {
            int cur = li;
            for (int t = T_ - 1; t >= 0; t--) {
                out[label_off + (size_t)b * T_ + t] = (float)cur;
                cur = bp[t][cur];
            }
        }
    }
}

// ---------------- launch -----------------------------------------------------
extern "C" void kernel_launch(void* const* d_in, const int* in_sizes, int n_in,
                              void* d_out, int out_size) {
    const int*   x       = (const int*)d_in[0];
    const float* emb     = (const float*)d_in[1];
    const float* W_ih_f  = (const float*)d_in[2];
    const float* W_hh_f  = (const float*)d_in[3];
    const float* b_f     = (const float*)d_in[4];
    const float* W_ih_b  = (const float*)d_in[5];
    const float* W_hh_b  = (const float*)d_in[6];
    const float* b_b     = (const float*)d_in[7];
    const float* fc1_W   = (const float*)d_in[8];
    const float* fc1_b   = (const float*)d_in[9];
    const float* cls_W   = (const float*)d_in[10];
    const float* cls_b   = (const float*)d_in[11];
    const float* trans   = (const float*)d_in[12];
    float* out = (float*)d_out;

    int score_off = 0, label_off = B_;
    if (out_size == B_ * T_)      { score_off = -1; label_off = 0; }
    else if (out_size == B_)      { label_off = -1; }

    cudaFuncSetAttribute(fused_kernel, cudaFuncAttributeMaxDynamicSharedMemorySize, L_SMEM_BYTES);
    cudaFuncSetAttribute(fc1_kernel, cudaFuncAttributeMaxDynamicSharedMemorySize, X_SMEM_BYTES);

    zero_bar_kernel<<<64, 256>>>();
    prep_whh_kernel<<<1024, 256>>>(W_hh_f, W_hh_b);
    fused_kernel<<<N_LSTM_BLK + N_WORKERS, 256, L_SMEM_BYTES>>>(x, emb, W_ih_f, b_f, W_ih_b, b_b);
    fc1_kernel<<<T_, 256, X_SMEM_BYTES>>>(fc1_W, fc1_b, cls_W, cls_b);
    viterbi_kernel<<<B_, 32>>>(trans, out, score_off, label_off);
}

// round 17
// speedup vs baseline: 1.4392x; 1.0038x over previous
#include <cuda_runtime.h>
#include <cuda_bf16.h>
#include <cuda_fp16.h>
#include <math.h>
#include <stdint.h>

// Problem constants
#define B_   64
#define T_   256
#define E_   300
#define H_   256
#define G4H  1024      // 4*H
#define INTER_ 128
#define NL   17
#define TL   19        // NUM_LABELS + 2
#define START_L 17
#define END_L   18
#define LOW_POT (-10000.0f)

#define N_LSTM_BLK 64
#define N_WORKERS  84
#define N_ITEMS    4096      // 512 slices x 8 n-tiles

// ---------------- scratch (device globals; no allocations allowed) ----------
__device__ float g_xproj[(size_t)2 * T_ * G4H * B_];   // [dir][t][n(1024)][b]
__device__ float g_h[(size_t)2 * T_ * H_ * B_];        // [dir][t][k][b]
__device__ float g_unary[(size_t)B_ * T_ * TL];        // [b][t][l]
__device__ int   g_flags[4 * T_ * 16];                 // per-(grp,step,producer) flags
__device__ int   g_xslice[512];                        // per-slice tile counters (8 = ready)

// W_hh in f16 mma-fragment order: [dir][hc(16)][q(4)][kt(16)][lane(32)][reg(4)]
__device__ uint32_t g_wfrag16_hi[2 * 16 * 4 * 16 * 32 * 4];
__device__ uint32_t g_wfrag16_lo[2 * 16 * 4 * 16 * 32 * 4];
// h in f16 mma B-fragment order: [grp(4)][par(2)][kt(16)][nt(4)][lane(32)][reg(2)]
__device__ uint32_t g_hfrag16_hi[4 * 2 * 16 * 4 * 32 * 2];
__device__ uint32_t g_hfrag16_lo[4 * 2 * 16 * 4 * 32 * 2];

// ---------------- helpers ----------------------------------------------------
__device__ __forceinline__ void mma_f16(float* d, const uint32_t* a, uint32_t b0, uint32_t b1) {
    asm volatile(
        "mma.sync.aligned.m16n8k16.row.col.f32.f16.f16.f32 "
        "{%0,%1,%2,%3}, {%4,%5,%6,%7}, {%8,%9}, {%0,%1,%2,%3};"
        : "+f"(d[0]), "+f"(d[1]), "+f"(d[2]), "+f"(d[3])
        : "r"(a[0]), "r"(a[1]), "r"(a[2]), "r"(a[3]), "r"(b0), "r"(b1));
}
__device__ __forceinline__ void split_pack_f16(float x0, float x1, uint32_t& hi, uint32_t& lo) {
    __half h0 = __float2half_rn(x0);
    __half h1 = __float2half_rn(x1);
    __half l0 = __float2half_rn(x0 - __half2float(h0));
    __half l1 = __float2half_rn(x1 - __half2float(h1));
    hi = (uint32_t)__half_as_ushort(h0) | ((uint32_t)__half_as_ushort(h1) << 16);
    lo = (uint32_t)__half_as_ushort(l0) | ((uint32_t)__half_as_ushort(l1) << 16);
}
__device__ __forceinline__ void split_f16_u16(float x, uint16_t& hi, uint16_t& lo) {
    __half h = __float2half_rn(x);
    __half l = __float2half_rn(x - __half2float(h));
    hi = __half_as_ushort(h);
    lo = __half_as_ushort(l);
}
__device__ __forceinline__ uint2 ldcg_u2(const uint32_t* p) {
    uint2 v;
    asm volatile("ld.global.cg.v2.u32 {%0,%1}, [%2];" : "=r"(v.x), "=r"(v.y) : "l"(p));
    return v;
}

// fast activations (~1e-7 rel err, clamped)
__device__ __forceinline__ float sigf(float x) {
    x = fmaxf(fminf(x, 30.f), -30.f);
    return __fdividef(1.f, 1.f + __expf(-x));
}
__device__ __forceinline__ float tanhf_fast(float x) {
    x = fmaxf(fminf(x, 15.f), -15.f);
    float e = __expf(2.f * x);
    return __fdividef(e - 1.f, e + 1.f);
}

// ---------------- flag zeroing (graph-replay determinism) -------------------
__global__ void zero_bar_kernel() {
    int i = blockIdx.x * 256 + threadIdx.x;
    if (i < 4 * T_ * 16) g_flags[i] = 0;
    if (i < 512) g_xslice[i] = 0;
}

// ---------------- W_hh f16 fragment prep ------------------------------------
__global__ void prep_whh_kernel(const float* __restrict__ Whf,
                                const float* __restrict__ Whb) {
    int idx = blockIdx.x * 256 + threadIdx.x;
    if (idx >= 2 * 16 * 4 * 16 * 32 * 4) return;
    int reg  = idx & 3;
    int lane = (idx >> 2) & 31;
    int kt   = (idx >> 7) & 15;
    int q    = (idx >> 11) & 3;
    int hc   = (idx >> 13) & 15;
    int dir  = (idx >> 17) & 1;
    const float* W = dir ? Whb : Whf;
    int i  = (lane >> 2) + 8 * (reg & 1);
    int g  = q * 256 + hc * 16 + i;
    int k0 = kt * 16 + (lane & 3) * 2 + 8 * (reg >> 1);
    float v0 = W[(size_t)g * H_ + k0];
    float v1 = W[(size_t)g * H_ + k0 + 1];
    uint32_t hi, lo;
    split_pack_f16(v0, v1, hi, lo);
    g_wfrag16_hi[idx] = hi;
    g_wfrag16_lo[idx] = lo;
}

// ---------------- smem layouts ------------------------------------------------
// fp16x3 tile area (shared by xproj worker and fc1): 61.7KB
#define XP_PAD 20
#define XP_A_SZ (128 * XP_PAD)
#define XP_B_SZ (64 * XP_PAD)
#define XP_AH(b) ((b) * XP_A_SZ)
#define XP_AL(b) (2 * XP_A_SZ + (b) * XP_A_SZ)
#define XP_BH(b) (4 * XP_A_SZ + (b) * XP_B_SZ)
#define XP_BL(b) (4 * XP_A_SZ + 2 * XP_B_SZ + (b) * XP_B_SZ)
#define XP_TOK   (4 * XP_A_SZ + 4 * XP_B_SZ)
#define XP_SMEM_BYTES ((4 * XP_A_SZ + 4 * XP_B_SZ + 64) * 4)   // 61696

// LSTM area: weights + gate exchange only (B frags read direct from L2)
#define L_AHI 0
#define L_ALO 8192
#define L_GEX 16384
#define L_SMEM_BYTES ((16384 + 4 * 16 * 33) * 4)   // 74112

// fc1 epilogue smem reuse
#define XI_PITCH 65
#define XW_OFF   (128 * XI_PITCH)

// =============================================================================
// xproj worker (device fn) — r15/r16 proven; unchanged
// =============================================================================
__device__ void xproj_worker(uint32_t* sm, int wkr,
                             const int* __restrict__ x,
                             const float* __restrict__ emb,
                             const float* __restrict__ Wf, const float* __restrict__ bf,
                             const float* __restrict__ Wb, const float* __restrict__ bb) {
    const int tid = threadIdx.x;
    const int rowA = tid & 127;
    const int kqA  = tid >> 7;
    const int rowB = tid & 63;
    const int kqB  = tid >> 6;
    const int wid  = tid >> 5;
    const int lane = tid & 31;
    const int r    = lane >> 2;
    const int cidx = lane & 3;
    const int row0 = wid * 16 + r;
    int* tok = (int*)(sm + XP_TOK);

    for (int item = wkr; item < N_ITEMS; item += N_WORKERS) {
        const int s_  = item >> 3;
        const int n0  = (item & 7) * 128;
        const int dir = s_ & 1;
        const int kk  = s_ >> 1;
        const int t   = dir ? (T_ - 1 - kk) : kk;
        const float* W    = dir ? Wb : Wf;
        const float* bias = dir ? bb : bf;

        if (tid < 64) tok[tid] = x[tid * T_ + t];
        __syncthreads();

        const float* Arow = W + (size_t)(n0 + rowA) * E_;
        const float* Brow = emb + (size_t)tok[rowB] * E_;

        float acc[8][4];
#pragma unroll
        for (int i = 0; i < 8; i++)
#pragma unroll
            for (int j = 0; j < 4; j++) acc[i][j] = 0.f;

        float4 av[4];
        float4 bv[2];

#pragma unroll
        for (int j = 0; j < 4; j++) {
            int gk4 = kqA * 4 + j;
            av[j] = (gk4 < 75) ? *(const float4*)(Arow + gk4 * 4) : make_float4(0, 0, 0, 0);
        }
#pragma unroll
        for (int j = 0; j < 2; j++) {
            int gk4 = kqB * 2 + j;
            bv[j] = (gk4 < 75) ? *(const float4*)(Brow + gk4 * 4) : make_float4(0, 0, 0, 0);
        }
#pragma unroll
        for (int j = 0; j < 4; j++) {
            int k2b = kqA * 8 + j * 2;
            uint32_t h0, l0, h1, l1;
            split_pack_f16(av[j].x, av[j].y, h0, l0);
            split_pack_f16(av[j].z, av[j].w, h1, l1);
            sm[XP_AH(0) + rowA * XP_PAD + k2b]     = h0;
            sm[XP_AH(0) + rowA * XP_PAD + k2b + 1] = h1;
            sm[XP_AL(0) + rowA * XP_PAD + k2b]     = l0;
            sm[XP_AL(0) + rowA * XP_PAD + k2b + 1] = l1;
        }
#pragma unroll
        for (int j = 0; j < 2; j++) {
            int k2b = kqB * 4 + j * 2;
            uint32_t h0, l0, h1, l1;
            split_pack_f16(bv[j].x, bv[j].y, h0, l0);
            split_pack_f16(bv[j].z, bv[j].w, h1, l1);
            sm[XP_BH(0) + rowB * XP_PAD + k2b]     = h0;
            sm[XP_BH(0) + rowB * XP_PAD + k2b + 1] = h1;
            sm[XP_BL(0) + rowB * XP_PAD + k2b]     = l0;
            sm[XP_BL(0) + rowB * XP_PAD + k2b + 1] = l1;
        }
        __syncthreads();

        for (int kc = 0; kc < 10; kc++) {
            const int buf = kc & 1;
            if (kc < 9) {
#pragma unroll
                for (int j = 0; j < 4; j++) {
                    int gk4 = (kc + 1) * 8 + kqA * 4 + j;
                    av[j] = (gk4 < 75) ? *(const float4*)(Arow + gk4 * 4) : make_float4(0, 0, 0, 0);
                }
#pragma unroll
                for (int j = 0; j < 2; j++) {
                    int gk4 = (kc + 1) * 8 + kqB * 2 + j;
                    bv[j] = (gk4 < 75) ? *(const float4*)(Brow + gk4 * 4) : make_float4(0, 0, 0, 0);
                }
            }
            const uint32_t* AHp = sm + XP_AH(buf);
            const uint32_t* ALp = sm + XP_AL(buf);
            const uint32_t* BHp = sm + XP_BH(buf);
            const uint32_t* BLp = sm + XP_BL(buf);
#pragma unroll
            for (int s2 = 0; s2 < 2; s2++) {
                const int k2b = s2 * 8 + cidx;
                uint32_t ah[4], al[4];
                ah[0] = AHp[row0 * XP_PAD + k2b];
                ah[1] = AHp[(row0 + 8) * XP_PAD + k2b];
                ah[2] = AHp[row0 * XP_PAD + k2b + 4];
                ah[3] = AHp[(row0 + 8) * XP_PAD + k2b + 4];
                al[0] = ALp[row0 * XP_PAD + k2b];
                al[1] = ALp[(row0 + 8) * XP_PAD + k2b];
                al[2] = ALp[row0 * XP_PAD + k2b + 4];
                al[3] = ALp[(row0 + 8) * XP_PAD + k2b + 4];
#pragma unroll
                for (int nt = 0; nt < 8; nt++) {
                    const int col = nt * 8 + r;
                    uint32_t bh0 = BHp[col * XP_PAD + k2b];
                    uint32_t bh1 = BHp[col * XP_PAD + k2b + 4];
                    uint32_t bl0 = BLp[col * XP_PAD + k2b];
                    uint32_t bl1 = BLp[col * XP_PAD + k2b + 4];
                    mma_f16(acc[nt], ah, bh0, bh1);
                    mma_f16(acc[nt], al, bh0, bh1);
                    mma_f16(acc[nt], ah, bl0, bl1);
                }
            }
            if (kc < 9) {
                const int nb = (kc + 1) & 1;
#pragma unroll
                for (int j = 0; j < 4; j++) {
                    int k2b = kqA * 8 + j * 2;
                    uint32_t h0, l0, h1, l1;
                    split_pack_f16(av[j].x, av[j].y, h0, l0);
                    split_pack_f16(av[j].z, av[j].w, h1, l1);
                    sm[XP_AH(nb) + rowA * XP_PAD + k2b]     = h0;
                    sm[XP_AH(nb) + rowA * XP_PAD + k2b + 1] = h1;
                    sm[XP_AL(nb) + rowA * XP_PAD + k2b]     = l0;
                    sm[XP_AL(nb) + rowA * XP_PAD + k2b + 1] = l1;
                }
#pragma unroll
                for (int j = 0; j < 2; j++) {
                    int k2b = kqB * 4 + j * 2;
                    uint32_t h0, l0, h1, l1;
                    split_pack_f16(bv[j].x, bv[j].y, h0, l0);
                    split_pack_f16(bv[j].z, bv[j].w, h1, l1);
                    sm[XP_BH(nb) + rowB * XP_PAD + k2b]     = h0;
                    sm[XP_BH(nb) + rowB * XP_PAD + k2b + 1] = h1;
                    sm[XP_BL(nb) + rowB * XP_PAD + k2b]     = l0;
                    sm[XP_BL(nb) + rowB * XP_PAD + k2b + 1] = l1;
                }
            }
            __syncthreads();
        }

        // epilogue: +bias, write [dir][t][n][b], then signal slice
        const int gr0 = n0 + wid * 16 + r;
        const int gr1 = gr0 + 8;
        const float bv0 = bias[gr0];
        const float bv1 = bias[gr1];
        float* outb = g_xproj + ((size_t)(dir * T_ + t)) * (G4H * B_);
#pragma unroll
        for (int nt = 0; nt < 8; nt++) {
            const int col = nt * 8 + 2 * cidx;
            float2 o0 = make_float2(acc[nt][0] + bv0, acc[nt][1] + bv0);
            float2 o1 = make_float2(acc[nt][2] + bv1, acc[nt][3] + bv1);
            *(float2*)(outb + (size_t)gr0 * B_ + col) = o0;
            *(float2*)(outb + (size_t)gr1 * B_ + col) = o1;
        }
        __threadfence();
        __syncthreads();
        if (tid == 0) atomicAdd(&g_xslice[s_], 1);
    }
}

// =============================================================================
// LSTM chain block (device fn) — r16 proven; unchanged
// =============================================================================
__device__ void lstm_block(uint32_t* s, int bx) {
    uint32_t* Ahi = s + L_AHI;
    uint32_t* Alo = s + L_ALO;
    float*    gex = (float*)(s + L_GEX);

    const int tid = threadIdx.x;
    const int dir = bx >> 5;
    const int bg  = (bx >> 4) & 1;
    const int hc  = bx & 15;
    const int grp = dir * 2 + bg;

    {
        const uint4* srcH = (const uint4*)(g_wfrag16_hi + ((size_t)(dir * 16 + hc)) * 8192);
        const uint4* srcL = (const uint4*)(g_wfrag16_lo + ((size_t)(dir * 16 + hc)) * 8192);
        uint4* dH = (uint4*)Ahi;
        uint4* dL = (uint4*)Alo;
#pragma unroll
        for (int j = 0; j < 8; j++) {
            dH[tid + j * 256] = srcH[tid + j * 256];
            dL[tid + j * 256] = srcL[tid + j * 256];
        }
    }

    const int w    = tid >> 5;
    const int lane = tid & 31;
    const int q    = w & 3;
    const int nt0  = (w >> 2) * 2;

    const int ci = (2 * tid) >> 5;     // 0..15
    const int cb = (2 * tid) & 31;     // even
    float cst0 = 0.f, cst1 = 0.f;

    const int kin   = ci;
    const int s_reg = kin >> 3;
    const int s_tig = (kin >> 1) & 3;
    const int s_half = kin & 1;

    __syncthreads();

    for (int st = 0; st < T_; st++) {
        const int t = dir ? (T_ - 1 - st) : st;

        {
            const int* cp = g_xslice + (st * 2 + dir);
            int v;
            for (;;) {
                asm volatile("ld.acquire.gpu.global.b32 %0, [%1];"
                             : "=r"(v) : "l"(cp) : "memory");
                if (v >= 8) break;
                __nanosleep(60);
            }
        }

        float2 xpv[4];
        {
            const float* xb = g_xproj + ((size_t)(dir * T_ + t)) * (G4H * B_)
                              + (size_t)(hc * 16 + ci) * B_ + bg * 32 + cb;
#pragma unroll
            for (int qq = 0; qq < 4; qq++)
                xpv[qq] = *(const float2*)(xb + (size_t)qq * (H_ * B_));
        }

        float ga[4][2];
#pragma unroll
        for (int qq = 0; qq < 4; qq++) { ga[qq][0] = xpv[qq].x; ga[qq][1] = xpv[qq].y; }

        if (st > 0) {
            if (tid < 16) {
                const int* fp = g_flags + ((grp * T_ + (st - 1)) << 4) + tid;
                int v;
                for (;;) {
                    asm volatile("ld.acquire.gpu.global.b32 %0, [%1];"
                                 : "=r"(v) : "l"(fp) : "memory");
                    if (__all_sync(0x0000FFFFu, v != 0)) break;
                    __nanosleep(30);
                }
            }
            __syncthreads();

            const size_t hb = ((size_t)grp * 2 + ((st - 1) & 1)) * 4096;
            const uint32_t* GH = g_hfrag16_hi + hb;
            const uint32_t* GL = g_hfrag16_lo + hb;

            float acc[2][4];
#pragma unroll
            for (int e = 0; e < 2; e++)
#pragma unroll
                for (int j = 0; j < 4; j++) acc[e][j] = 0.f;

            const uint32_t* Aq_hi = Ahi + q * 2048;
            const uint32_t* Aq_lo = Alo + q * 2048;
#pragma unroll 8
            for (int kt = 0; kt < 16; kt++) {
                uint4 ahv = *(const uint4*)(Aq_hi + (kt * 32 + lane) * 4);
                uint4 alv = *(const uint4*)(Aq_lo + (kt * 32 + lane) * 4);
                const uint32_t* ah = (const uint32_t*)&ahv;
                const uint32_t* al = (const uint32_t*)&alv;
#pragma unroll
                for (int e = 0; e < 2; e++) {
                    const int nt = nt0 + e;
                    uint2 bh = ldcg_u2(GH + ((kt * 4 + nt) * 32 + lane) * 2);
                    uint2 bl = ldcg_u2(GL + ((kt * 4 + nt) * 32 + lane) * 2);
                    mma_f16(acc[e], ah, bh.x, bh.y);
                    mma_f16(acc[e], al, bh.x, bh.y);
                    mma_f16(acc[e], ah, bl.x, bl.y);
                }
            }
            {
                const int i_lo = lane >> 2;
                const int colb = (lane & 3) * 2;
#pragma unroll
                for (int e = 0; e < 2; e++) {
                    const int col = (nt0 + e) * 8 + colb;
                    gex[(q * 16 + i_lo) * 33 + col]     = acc[e][0];
                    gex[(q * 16 + i_lo) * 33 + col + 1] = acc[e][1];
                    gex[(q * 16 + i_lo + 8) * 33 + col]     = acc[e][2];
                    gex[(q * 16 + i_lo + 8) * 33 + col + 1] = acc[e][3];
                }
            }
            __syncthreads();

#pragma unroll
            for (int qq = 0; qq < 4; qq++) {
                ga[qq][0] += gex[(qq * 16 + ci) * 33 + cb];
                ga[qq][1] += gex[(qq * 16 + ci) * 33 + cb + 1];
            }
        }

        float h0, h1;
        {
            float ig = sigf(ga[0][0]);
            float fg = sigf(ga[1][0]);
            float gg = tanhf_fast(ga[2][0]);
            float og = sigf(ga[3][0]);
            cst0 = fg * cst0 + ig * gg;
            h0 = og * tanhf_fast(cst0);
        }
        {
            float ig = sigf(ga[0][1]);
            float fg = sigf(ga[1][1]);
            float gg = tanhf_fast(ga[2][1]);
            float og = sigf(ga[3][1]);
            cst1 = fg * cst1 + ig * gg;
            h1 = og * tanhf_fast(cst1);
        }

        {
            const int k = hc * 16 + ci;
            *(float2*)(g_h + (((size_t)(dir * T_ + t)) * H_ + k) * B_ + bg * 32 + cb)
                = make_float2(h0, h1);

            const size_t hb = ((size_t)grp * 2 + (st & 1)) * 4096;
            uint16_t* HHi = (uint16_t*)g_hfrag16_hi;
            uint16_t* HLo = (uint16_t*)g_hfrag16_lo;
            uint16_t fhi, flo;
            {
                const int nt = cb >> 3;
                const int laneb = (cb & 7) * 4 + s_tig;
                const size_t word = hb + (((size_t)hc * 4 + nt) * 32 + laneb) * 2 + s_reg;
                split_f16_u16(h0, fhi, flo);
                HHi[word * 2 + s_half] = fhi;
                HLo[word * 2 + s_half] = flo;
            }
            {
                const int b1 = cb + 1;
                const int nt = b1 >> 3;
                const int laneb = (b1 & 7) * 4 + s_tig;
                const size_t word = hb + (((size_t)hc * 4 + nt) * 32 + laneb) * 2 + s_reg;
                split_f16_u16(h1, fhi, flo);
                HHi[word * 2 + s_half] = fhi;
                HLo[word * 2 + s_half] = flo;
            }
        }
        __syncthreads();
        if (tid == 0) {
            __threadfence();
            int* fp = g_flags + ((grp * T_ + st) << 4) + hc;
            asm volatile("st.release.gpu.global.b32 [%0], %1;" :: "l"(fp), "r"(1) : "memory");
        }
    }
}

// =============================================================================
// fused kernel: blocks 0..63 = LSTM chains, 64..147 = xproj workers.
// =============================================================================
__global__ void __launch_bounds__(256, 2)
fused_kernel(const int* __restrict__ x,
             const float* __restrict__ emb,
             const float* __restrict__ Wf, const float* __restrict__ bf,
             const float* __restrict__ Wb, const float* __restrict__ bb) {
    extern __shared__ uint32_t s[];
    const int bx = blockIdx.x;
    if (bx < N_LSTM_BLK) {
        lstm_block(s, bx);
    } else {
        xproj_worker(s, bx - N_LSTM_BLK, x, emb, Wf, bf, Wb, bb);
    }
}

// =============================================================================
// fc1 (fp16x3, m16n8k16) + fused cls. K=512 = 16 chunks of 32.
// B operand transposed into [b][k-pair] f16 layout via u16 smem scatter.
// =============================================================================
__global__ void __launch_bounds__(256, 2)
fc1_kernel(const float* __restrict__ W, const float* __restrict__ bias,
           const float* __restrict__ clsW, const float* __restrict__ clsb) {
    extern __shared__ uint32_t sm[];
    const int tid = threadIdx.x;
    const int t   = blockIdx.x;

    const int rowA = tid & 127;
    const int kqA  = tid >> 7;
    const float* Arow = W + (size_t)rowA * 512;

    const int wid  = tid >> 5;
    const int lane = tid & 31;
    const int r    = lane >> 2;
    const int cidx = lane & 3;
    const int row0 = wid * 16 + r;

    float acc[8][4];
#pragma unroll
    for (int i = 0; i < 8; i++)
#pragma unroll
        for (int j = 0; j < 4; j++) acc[i][j] = 0.f;

    float4 av[4];
    float4 bv[2];

    // ---- prologue: chunk 0
#pragma unroll
    for (int j = 0; j < 4; j++) {
        int gk4 = kqA * 4 + j;
        av[j] = *(const float4*)(Arow + gk4 * 4);
    }
#pragma unroll
    for (int j = 0; j < 2; j++) {
        int f4id = tid + j * 256;
        int kl = f4id >> 4, b4 = f4id & 15;
        int kgl = kl;                       // chunk 0
        int d = kgl >> 8, kh = kgl & 255;
        bv[j] = *(const float4*)(g_h + ((size_t)(d * T_ + t) * 256 + kh) * 64 + b4 * 4);
    }
#pragma unroll
    for (int j = 0; j < 4; j++) {
        int k2b = kqA * 8 + j * 2;
        uint32_t h0, l0, h1, l1;
        split_pack_f16(av[j].x, av[j].y, h0, l0);
        split_pack_f16(av[j].z, av[j].w, h1, l1);
        sm[XP_AH(0) + rowA * XP_PAD + k2b]     = h0;
        sm[XP_AH(0) + rowA * XP_PAD + k2b + 1] = h1;
        sm[XP_AL(0) + rowA * XP_PAD + k2b]     = l0;
        sm[XP_AL(0) + rowA * XP_PAD + k2b + 1] = l1;
    }
    {
        uint16_t* BH16 = (uint16_t*)(sm + XP_BH(0));
        uint16_t* BL16 = (uint16_t*)(sm + XP_BL(0));
#pragma unroll
        for (int j = 0; j < 2; j++) {
            int f4id = tid + j * 256;
            int kl = f4id >> 4, b4 = f4id & 15;
            const float* v = (const float*)&bv[j];
            int kp = kl >> 1, half = kl & 1;
#pragma unroll
            for (int c = 0; c < 4; c++) {
                uint16_t fhi, flo;
                split_f16_u16(v[c], fhi, flo);
                int word = (b4 * 4 + c) * XP_PAD + kp;
                BH16[word * 2 + half] = fhi;
                BL16[word * 2 + half] = flo;
            }
        }
    }
    __syncthreads();

    for (int kc = 0; kc < 16; kc++) {
        const int buf = kc & 1;
        if (kc < 15) {
#pragma unroll
            for (int j = 0; j < 4; j++) {
                int gk4 = (kc + 1) * 8 + kqA * 4 + j;
                av[j] = *(const float4*)(Arow + gk4 * 4);
            }
#pragma unroll
            for (int j = 0; j < 2; j++) {
                int f4id = tid + j * 256;
                int kl = f4id >> 4, b4 = f4id & 15;
                int kgl = (kc + 1) * 32 + kl;
                int d = kgl >> 8, kh = kgl & 255;
                bv[j] = *(const float4*)(g_h + ((size_t)(d * T_ + t) * 256 + kh) * 64 + b4 * 4);
            }
        }
        const uint32_t* AHp = sm + XP_AH(buf);
        const uint32_t* ALp = sm + XP_AL(buf);
        const uint32_t* BHp = sm + XP_BH(buf);
        const uint32_t* BLp = sm + XP_BL(buf);
#pragma unroll
        for (int s2 = 0; s2 < 2; s2++) {
            const int k2b = s2 * 8 + cidx;
            uint32_t ah[4], al[4];
            ah[0] = AHp[row0 * XP_PAD + k2b];
            ah[1] = AHp[(row0 + 8) * XP_PAD + k2b];
            ah[2] = AHp[row0 * XP_PAD + k2b + 4];
            ah[3] = AHp[(row0 + 8) * XP_PAD + k2b + 4];
            al[0] = ALp[row0 * XP_PAD + k2b];
            al[1] = ALp[(row0 + 8) * XP_PAD + k2b];
            al[2] = ALp[row0 * XP_PAD + k2b + 4];
            al[3] = ALp[(row0 + 8) * XP_PAD + k2b + 4];
#pragma unroll
            for (int nt = 0; nt < 8; nt++) {
                const int col = nt * 8 + r;
                uint32_t bh0 = BHp[col * XP_PAD + k2b];
                uint32_t bh1 = BHp[col * XP_PAD + k2b + 4];
                uint32_t bl0 = BLp[col * XP_PAD + k2b];
                uint32_t bl1 = BLp[col * XP_PAD + k2b + 4];
                mma_f16(acc[nt], ah, bh0, bh1);
                mma_f16(acc[nt], al, bh0, bh1);
                mma_f16(acc[nt], ah, bl0, bl1);
            }
        }
        if (kc < 15) {
            const int nb = (kc + 1) & 1;
#pragma unroll
            for (int j = 0; j < 4; j++) {
                int k2b = kqA * 8 + j * 2;
                uint32_t h0, l0, h1, l1;
                split_pack_f16(av[j].x, av[j].y, h0, l0);
                split_pack_f16(av[j].z, av[j].w, h1, l1);
                sm[XP_AH(nb) + rowA * XP_PAD + k2b]     = h0;
                sm[XP_AH(nb) + rowA * XP_PAD + k2b + 1] = h1;
                sm[XP_AL(nb) + rowA * XP_PAD + k2b]     = l0;
                sm[XP_AL(nb) + rowA * XP_PAD + k2b + 1] = l1;
            }
            uint16_t* BH16 = (uint16_t*)(sm + XP_BH(nb));
            uint16_t* BL16 = (uint16_t*)(sm + XP_BL(nb));
#pragma unroll
            for (int j = 0; j < 2; j++) {
                int f4id = tid + j * 256;
                int kl = f4id >> 4, b4 = f4id & 15;
                const float* v = (const float*)&bv[j];
                int kp = kl >> 1, half = kl & 1;
#pragma unroll
                for (int c = 0; c < 4; c++) {
                    uint16_t fhi, flo;
                    split_f16_u16(v[c], fhi, flo);
                    int word = (b4 * 4 + c) * XP_PAD + kp;
                    BH16[word * 2 + half] = fhi;
                    BL16[word * 2 + half] = flo;
                }
            }
        }
        __syncthreads();
    }

    // ---- fused epilogue: relu tile -> smem, then cls -> g_unary
    float* sIf = (float*)sm;
    float* sWc = (float*)(sm + XW_OFF);
    {
        const int gr0 = wid * 16 + r;
        const int gr1 = gr0 + 8;
        const float bv0 = bias[gr0];
        const float bv1 = bias[gr1];
#pragma unroll
        for (int nt = 0; nt < 8; nt++) {
            const int col = nt * 8 + 2 * cidx;
            sIf[gr0 * XI_PITCH + col]     = fmaxf(acc[nt][0] + bv0, 0.f);
            sIf[gr0 * XI_PITCH + col + 1] = fmaxf(acc[nt][1] + bv0, 0.f);
            sIf[gr1 * XI_PITCH + col]     = fmaxf(acc[nt][2] + bv1, 0.f);
            sIf[gr1 * XI_PITCH + col + 1] = fmaxf(acc[nt][3] + bv1, 0.f);
        }
    }
    for (int i = tid; i < NL * INTER_; i += 256) sWc[i] = clsW[i];
    __syncthreads();

    const int b  = tid & 63;
    const int lg = tid >> 6;
    for (int l = lg; l < NL; l += 4) {
        float a = clsb[l];
        const float* wr = sWc + l * INTER_;
#pragma unroll 8
        for (int n = 0; n < INTER_; n++) a += wr[n] * sIf[n * XI_PITCH + b];
        g_unary[((size_t)b * T_ + t) * TL + l] = a;
    }
    if (tid < 128) {
        int bb = tid & 63;
        int l  = NL + (tid >> 6);
        g_unary[((size_t)bb * T_ + t) * TL + l] = LOW_POT;
    }
}

// ---------------- Viterbi + backtrace (one block per batch element) ---------
__global__ void viterbi_kernel(const float* __restrict__ trans, float* __restrict__ out,
                               int score_off, int label_off) {
    __shared__ float tr[TL * TL];
    __shared__ float s0[TL], s1[TL];
    __shared__ unsigned char bp[T_][TL];
    const int b = blockIdx.x;
    const int tid = threadIdx.x;

    for (int i = tid; i < TL * TL; i += 32) tr[i] = trans[i];
    if (tid < TL) s0[tid] = (tid == START_L) ? 0.f : LOW_POT;
    __syncthreads();

    const float* ub = g_unary + (size_t)b * T_ * TL;
    float* sc = s0;
    float* sn = s1;
    for (int t = 0; t < T_; t++) {
        if (tid < TL) {
            float best = sc[0] + tr[tid * TL + 0];
            int bpi = 0;
#pragma unroll
            for (int p = 1; p < TL; p++) {
                float v = sc[p] + tr[tid * TL + p];
                if (v > best) { best = v; bpi = p; }
            }
            sn[tid] = best + ub[t * TL + tid];
            bp[t][tid] = (unsigned char)bpi;
        }
        __syncthreads();
        float* tmp = sc; sc = sn; sn = tmp;
    }
    if (tid == 0) {
        float best = sc[0] + tr[END_L * TL + 0];
        int li = 0;
        for (int l = 1; l < TL; l++) {
            float v = sc[l] + tr[END_L * TL + l];
            if (v > best) { best = v; li = l; }
        }
        if (score_off >= 0) out[score_off + b] = best;
        if (label_off >= 0) {
            int cur = li;
            for (int t = T_ - 1; t >= 0; t--) {
                out[label_off + (size_t)b * T_ + t] = (float)cur;
                cur = bp[t][cur];
            }
        }
    }
}

// ---------------- launch -----------------------------------------------------
extern "C" void kernel_launch(void* const* d_in, const int* in_sizes, int n_in,
                              void* d_out, int out_size) {
    const int*   x       = (const int*)d_in[0];
    const float* emb     = (const float*)d_in[1];
    const float* W_ih_f  = (const float*)d_in[2];
    const float* W_hh_f  = (const float*)d_in[3];
    const float* b_f     = (const float*)d_in[4];
    const float* W_ih_b  = (const float*)d_in[5];
    const float* W_hh_b  = (const float*)d_in[6];
    const float* b_b     = (const float*)d_in[7];
    const float* fc1_W   = (const float*)d_in[8];
    const float* fc1_b   = (const float*)d_in[9];
    const float* cls_W   = (const float*)d_in[10];
    const float* cls_b   = (const float*)d_in[11];
    const float* trans   = (const float*)d_in[12];
    float* out = (float*)d_out;

    int score_off = 0, label_off = B_;
    if (out_size == B_ * T_)      { score_off = -1; label_off = 0; }
    else if (out_size == B_)      { label_off = -1; }

    cudaFuncSetAttribute(fused_kernel, cudaFuncAttributeMaxDynamicSharedMemorySize, L_SMEM_BYTES);
    cudaFuncSetAttribute(fc1_kernel, cudaFuncAttributeMaxDynamicSharedMemorySize, XP_SMEM_BYTES);

    zero_bar_kernel<<<64, 256>>>();
    prep_whh_kernel<<<1024, 256>>>(W_hh_f, W_hh_b);
    fused_kernel<<<N_LSTM_BLK + N_WORKERS, 256, L_SMEM_BYTES>>>(x, emb, W_ih_f, b_f, W_ih_b, b_b);
    fc1_kernel<<<T_, 256, XP_SMEM_BYTES>>>(fc1_W, fc1_b, cls_W, cls_b);
    viterbi_kernel<<<B_, 32>>>(trans, out, score_off, label_off);
}